// round 2
// baseline (speedup 1.0000x reference)
#include <cuda_runtime.h>
#include <math.h>

// ---------------- problem constants ----------------
#define Bq  32
#define Dn  10
#define QLn 16
#define DLn 128
#define BD  320
#define Ff  300
#define Hh  256
#define G4  1024
#define Cc  50
#define NFc 50
#define MFc 20
#define NTQ (Bq*QLn)      // 512
#define NTD (BD*DLn)      // 40960

// ---------------- device scratch ----------------
__device__ float g_Xq[NTQ*Ff];
__device__ float g_Xd[(size_t)NTD*Ff];
__device__ float g_xgq[(size_t)NTQ*G4];
__device__ float g_xgd[(size_t)NTD*G4];
__device__ float g_encq[NTQ*Hh];
__device__ float g_encd[(size_t)NTD*Hh];
__device__ float g_c[BD*Hh];
__device__ float g_pq[NTQ*Cc];
__device__ float g_pdT[(size_t)BD*Cc*DLn];
__device__ float g_s3[(size_t)Bq*NFc*QLn*3*Cc];
__device__ float g_s5[(size_t)Bq*NFc*QLn*5*Cc];
__device__ float g_s7[(size_t)Bq*NFc*QLn*7*Cc];
__device__ float g_f[(size_t)BD*150*QLn*DLn];
__device__ float g_qb[G4];
__device__ float g_db[G4];
__device__ float g_zero[Hh];   // never written: stays zero

__device__ __forceinline__ float sigf(float x){ return 1.f/(1.f+expf(-x)); }

// ---------------- bias precombine ----------------
__global__ void bias_sum_k(const float* __restrict__ qb1, const float* __restrict__ qb2,
                           const float* __restrict__ db1, const float* __restrict__ db2)
{
    int t = blockIdx.x*blockDim.x + threadIdx.x;
    if (t < G4){ g_qb[t] = qb1[t]+qb2[t]; g_db[t] = db1[t]+db2[t]; }
}

// ---------------- generic 64x64 SGEMM ----------------
// C[M,N] = A(gathered)[M,K] * B + bias.  BT: B is [N,K] (use B^T), else [K,N].
// STORE 0: C[m*ldc+n].  STORE 1: pdT layout: img=m>>7, dl=m&127 -> C[(img*50+n)*128+dl]
template<bool GATHER, bool BT, int STORE>
__global__ __launch_bounds__(256) void sgemm64(
    const float* __restrict__ A, const int* __restrict__ idx, int lda,
    const float* __restrict__ Bm, int ldb, const float* __restrict__ bias,
    float* __restrict__ C, int ldc, int M, int N, int K)
{
    __shared__ float As[16][68];
    __shared__ float Bs[16][68];
    int tid = threadIdx.x;
    int tx = tid & 15, ty = tid >> 4;
    int m0 = blockIdx.y*64, n0 = blockIdx.x*64;
    float acc[4][4] = {};

    int mload = tid >> 2, kl4 = (tid & 3)*4;
    bool avalid = (m0 + mload) < M;
    const float* Aptr = A;
    if (avalid){
        long r = GATHER ? (long)idx[m0+mload] : (long)(m0+mload);
        Aptr = A + r*(long)lda;
    }
    for (int k0 = 0; k0 < K; k0 += 16){
        float4 av = make_float4(0.f,0.f,0.f,0.f);
        if (avalid && (k0+kl4) < K) av = *(const float4*)(Aptr + k0 + kl4);
        As[kl4+0][mload]=av.x; As[kl4+1][mload]=av.y;
        As[kl4+2][mload]=av.z; As[kl4+3][mload]=av.w;
        if (BT){
            int nload = tid >> 2;
            float4 bv = make_float4(0.f,0.f,0.f,0.f);
            if ((n0+nload) < N && (k0+kl4) < K)
                bv = *(const float4*)(Bm + (size_t)(n0+nload)*ldb + k0 + kl4);
            Bs[kl4+0][nload]=bv.x; Bs[kl4+1][nload]=bv.y;
            Bs[kl4+2][nload]=bv.z; Bs[kl4+3][nload]=bv.w;
        } else {
            int kr = tid >> 4, nl = (tid & 15)*4;
            #pragma unroll
            for (int j = 0; j < 4; j++){
                float v = 0.f;
                if ((k0+kr) < K && (n0+nl+j) < N) v = Bm[(size_t)(k0+kr)*ldb + n0 + nl + j];
                Bs[kr][nl+j] = v;
            }
        }
        __syncthreads();
        #pragma unroll
        for (int kk = 0; kk < 16; kk++){
            float4 a = *(float4*)&As[kk][ty*4];
            float4 b = *(float4*)&Bs[kk][tx*4];
            acc[0][0]+=a.x*b.x; acc[0][1]+=a.x*b.y; acc[0][2]+=a.x*b.z; acc[0][3]+=a.x*b.w;
            acc[1][0]+=a.y*b.x; acc[1][1]+=a.y*b.y; acc[1][2]+=a.y*b.z; acc[1][3]+=a.y*b.w;
            acc[2][0]+=a.z*b.x; acc[2][1]+=a.z*b.y; acc[2][2]+=a.z*b.z; acc[2][3]+=a.z*b.w;
            acc[3][0]+=a.w*b.x; acc[3][1]+=a.w*b.y; acc[3][2]+=a.w*b.z; acc[3][3]+=a.w*b.w;
        }
        __syncthreads();
    }
    #pragma unroll
    for (int i = 0; i < 4; i++){
        int m = m0 + ty*4 + i;
        if (m >= M) continue;
        #pragma unroll
        for (int j = 0; j < 4; j++){
            int n = n0 + tx*4 + j;
            if (n >= N) continue;
            float v = acc[i][j];
            if (bias) v += bias[n];
            if (STORE == 0) C[(size_t)m*ldc + n] = v;
            else { int img = m >> 7, dl = m & 127; C[((size_t)img*Cc + n)*DLn + dl] = v; }
        }
    }
}

// ---------------- fused LSTM step ----------------
// g = xg[:,t,:] + h_prev @ Whh^T ; gates -> c,h.  Tile 32 rows x 32 cols(8h x 4gates).
__global__ __launch_bounds__(64) void lstm_step_k(
    const float* __restrict__ xg, const float* __restrict__ Whh,
    const float* __restrict__ hprev, int hstride,
    float* __restrict__ cst, float* __restrict__ enc, int T, int t)
{
    __shared__ float As[32][36];
    __shared__ float Bs[32][33];
    int tid = threadIdx.x;
    int tym = tid >> 3, txc = tid & 7;       // 8x8 thread grid
    int mb = blockIdx.x*32;
    int h0 = blockIdx.y*8;
    float acc[4][4] = {};

    int mload = tid >> 1, klb = (tid & 1)*16;
    int cload = tid >> 1;
    int wrow = ((cload & 3)*Hh) + h0 + (cload >> 2);
    for (int k0 = 0; k0 < Hh; k0 += 32){
        const float* hp = hprev + (size_t)(mb+mload)*hstride + k0 + klb;
        #pragma unroll
        for (int u = 0; u < 4; u++){
            float4 v = *(const float4*)(hp + u*4);
            As[klb+u*4+0][mload]=v.x; As[klb+u*4+1][mload]=v.y;
            As[klb+u*4+2][mload]=v.z; As[klb+u*4+3][mload]=v.w;
        }
        const float* wp = Whh + (size_t)wrow*Hh + k0 + klb;
        #pragma unroll
        for (int u = 0; u < 4; u++){
            float4 v = *(const float4*)(wp + u*4);
            Bs[cload][klb+u*4+0]=v.x; Bs[cload][klb+u*4+1]=v.y;
            Bs[cload][klb+u*4+2]=v.z; Bs[cload][klb+u*4+3]=v.w;
        }
        __syncthreads();
        #pragma unroll
        for (int kk = 0; kk < 32; kk++){
            float4 a = *(float4*)&As[kk][tym*4];
            float b0 = Bs[txc*4+0][kk], b1 = Bs[txc*4+1][kk];
            float b2 = Bs[txc*4+2][kk], b3 = Bs[txc*4+3][kk];
            acc[0][0]+=a.x*b0; acc[0][1]+=a.x*b1; acc[0][2]+=a.x*b2; acc[0][3]+=a.x*b3;
            acc[1][0]+=a.y*b0; acc[1][1]+=a.y*b1; acc[1][2]+=a.y*b2; acc[1][3]+=a.y*b3;
            acc[2][0]+=a.z*b0; acc[2][1]+=a.z*b1; acc[2][2]+=a.z*b2; acc[2][3]+=a.z*b3;
            acc[3][0]+=a.w*b0; acc[3][1]+=a.w*b1; acc[3][2]+=a.w*b2; acc[3][3]+=a.w*b3;
        }
        __syncthreads();
    }
    int h = h0 + txc;
    #pragma unroll
    for (int r = 0; r < 4; r++){
        int m = mb + tym*4 + r;
        size_t tok = (size_t)m*T + t;
        const float* xb = xg + tok*G4;
        float gi = acc[r][0] + xb[h];
        float gf = acc[r][1] + xb[Hh + h];
        float gg = acc[r][2] + xb[2*Hh + h];
        float go = acc[r][3] + xb[3*Hh + h];
        float cp = (t == 0) ? 0.f : cst[(size_t)m*Hh + h];
        float cv = sigf(gf)*cp + sigf(gi)*tanhf(gg);
        float hv = sigf(go)*tanhf(cv);
        cst[(size_t)m*Hh + h] = cv;
        enc[tok*Hh + h] = hv;
    }
}

// ---------------- conv stage 1: s[b][o][q][dd][c] = sum_dq w[o,c,dq,dd]*pq_pad ----
__global__ void s_k(const float* __restrict__ cW, float* __restrict__ s, int KW, long total)
{
    long i = (long)blockIdx.x*blockDim.x + threadIdx.x;
    if (i >= total) return;
    int c  = (int)(i % Cc);
    long r = i / Cc;
    int dd = (int)(r % KW); r /= KW;
    int q  = (int)(r % QLn); r /= QLn;
    int o  = (int)(r % NFc);
    int b  = (int)(r / NFc);
    float v = 0.f;
    #pragma unroll
    for (int dq = 0; dq < 3; dq++){
        int qq = q + dq - 1;
        if (qq >= 0 && qq < QLn)
            v += cW[(((size_t)o*51 + c)*3 + dq)*KW + dd] * g_pq[((size_t)b*QLn + qq)*Cc + c];
    }
    s[i] = v;
}

// ---------------- conv stage 2: per-image GEMM + exact-match epilogue + relu ----
template<int KW>
__global__ __launch_bounds__(256) void convgemm_k(
    const float* __restrict__ sA, const float* __restrict__ cW,
    const float* __restrict__ cb, const int* __restrict__ bqtok,
    const int* __restrict__ bdtok, const float* __restrict__ alpha, int OCB)
{
    const int K = Cc*KW, PW = KW/2;
    __shared__ float As[8][132];
    __shared__ float Bs[8][132];
    __shared__ float ems[18][136];
    __shared__ float wem[8][3*KW];
    __shared__ int qt[16], dt[128];
    int tid = threadIdx.x;
    int img = blockIdx.y, b = img / Dn;
    int m0 = blockIdx.x*128, obase = m0 >> 4;

    if (tid < 16) qt[tid] = bqtok[b*QLn + tid];
    if (tid < 128) dt[tid] = bdtok[(size_t)img*DLn + tid];
    if (tid < 8*3*KW){
        int ol = tid/(3*KW), rr = tid%(3*KW);
        int o = obase + ol;
        wem[ol][rr] = (o < NFc) ? cW[(((size_t)o*51 + 50)*3 + rr/KW)*KW + rr%KW] : 0.f;
    }
    __syncthreads();
    float al = alpha[0];
    for (int e = tid; e < 18*136; e += 256){
        int qi = e/136, dj = e%136;
        int q = qi-1, dl = dj-3;
        float v = 0.f;
        if (q >= 0 && q < QLn && dl >= 0 && dl < DLn) v = (qt[q] == dt[dl]) ? al : 0.f;
        ems[qi][dj] = v;
    }
    const float* Ab = sA + (size_t)b*800*K;
    const float* Pd = &g_pdT[(size_t)img*Cc*DLn];
    int tx = tid & 15, ty = tid >> 4;
    float acc[8][8] = {};
    __syncthreads();

    int mload = tid >> 1, kl = (tid & 1)*4;
    int dl0 = tid & 127, r0 = tid >> 7;
    for (int k0 = 0; k0 < K; k0 += 8){
        #pragma unroll
        for (int j = 0; j < 4; j++){
            int kk = k0 + kl + j; float v = 0.f;
            if ((m0+mload) < 800 && kk < K) v = Ab[(size_t)(m0+mload)*K + kk];
            As[kl+j][mload] = v;
        }
        #pragma unroll
        for (int it = 0; it < 4; it++){
            int r = r0 + 2*it, kk = k0 + r; float v = 0.f;
            if (kk < K){
                int dd = kk/Cc, c = kk - dd*Cc;
                int sdl = dl0 + dd - PW;
                if (sdl >= 0 && sdl < DLn) v = Pd[(size_t)c*DLn + sdl];
            }
            Bs[r][dl0] = v;
        }
        __syncthreads();
        #pragma unroll
        for (int r = 0; r < 8; r++){
            float a[8], bv[8];
            *(float4*)(a)   = *(float4*)&As[r][ty*8];
            *(float4*)(a+4) = *(float4*)&As[r][ty*8+4];
            *(float4*)(bv)   = *(float4*)&Bs[r][tx*8];
            *(float4*)(bv+4) = *(float4*)&Bs[r][tx*8+4];
            #pragma unroll
            for (int i = 0; i < 8; i++)
                #pragma unroll
                for (int j = 0; j < 8; j++) acc[i][j] += a[i]*bv[j];
        }
        __syncthreads();
    }
    #pragma unroll
    for (int i = 0; i < 8; i++){
        int m = m0 + ty*8 + i;
        if (m >= 800) continue;
        int o = m >> 4, q = m & 15, ol = o - obase;
        float bias = cb[o];
        float we[3*KW];
        #pragma unroll
        for (int rr = 0; rr < 3*KW; rr++) we[rr] = wem[ol][rr];
        #pragma unroll
        for (int j = 0; j < 8; j++){
            int dl = tx*8 + j;
            float v = acc[i][j] + bias;
            #pragma unroll
            for (int dq = 0; dq < 3; dq++)
                #pragma unroll
                for (int dd = 0; dd < KW; dd++)
                    v += we[dq*KW+dd] * ems[q+dq][dl+dd+3-PW];
            v = fmaxf(v, 0.f);
            g_f[(((size_t)img*150 + OCB + o)*QLn + q)*DLn + dl] = v;
        }
    }
}

// ---------------- 1x1 conv + global maxpool + linear ----------------
__global__ __launch_bounds__(256) void score_k(
    const float* __restrict__ ccW, const float* __restrict__ ccb,
    const float* __restrict__ outW, const float* __restrict__ outb,
    float* __restrict__ out)
{
    __shared__ float w[MFc][152];
    __shared__ float red[8][MFc];
    int img = blockIdx.x, tid = threadIdx.x;
    for (int e = tid; e < MFc*150; e += 256) w[e/150][e%150] = ccW[e];
    __syncthreads();
    float mx[MFc];
    #pragma unroll
    for (int mf = 0; mf < MFc; mf++) mx[mf] = -1e30f;
    const float* fb = &g_f[(size_t)img*150*QLn*DLn];
    for (int p = tid; p < QLn*DLn; p += 256){
        float acc[MFc];
        #pragma unroll
        for (int mf = 0; mf < MFc; mf++) acc[mf] = ccb[mf];
        for (int nf = 0; nf < 150; nf++){
            float v = fb[(size_t)nf*QLn*DLn + p];
            #pragma unroll
            for (int mf = 0; mf < MFc; mf++) acc[mf] += v*w[mf][nf];
        }
        #pragma unroll
        for (int mf = 0; mf < MFc; mf++) mx[mf] = fmaxf(mx[mf], acc[mf]);
    }
    #pragma unroll
    for (int off = 16; off; off >>= 1)
        #pragma unroll
        for (int mf = 0; mf < MFc; mf++)
            mx[mf] = fmaxf(mx[mf], __shfl_xor_sync(0xFFFFFFFFu, mx[mf], off));
    if ((tid & 31) == 0)
        #pragma unroll
        for (int mf = 0; mf < MFc; mf++) red[tid>>5][mf] = mx[mf];
    __syncthreads();
    if (tid == 0){
        float sc = outb[0];
        #pragma unroll
        for (int mf = 0; mf < MFc; mf++){
            float m = red[0][mf];
            #pragma unroll
            for (int wp = 1; wp < 8; wp++) m = fmaxf(m, red[wp][mf]);
            sc += m*outW[mf];
        }
        out[img] = sc;
    }
}

// ---------------- launch ----------------
extern "C" void kernel_launch(void* const* d_in, const int* in_sizes, int n_in,
                              void* d_out, int out_size)
{
    // resolve first-4 permutation by size
    const int* bqtok = nullptr; const int* bdtok = nullptr;
    for (int i = 0; i < 4; i++){
        if (in_sizes[i] == NTQ)      bqtok = (const int*)d_in[i];
        else if (in_sizes[i] == NTD) bdtok = (const int*)d_in[i];
    }
    const float* emb    = (const float*)d_in[4];
    const float* projW  = (const float*)d_in[5];
    const float* projb  = (const float*)d_in[6];
    const float* qWih   = (const float*)d_in[7];
    const float* qWhh   = (const float*)d_in[8];
    const float* qbih   = (const float*)d_in[9];
    const float* qbhh   = (const float*)d_in[10];
    const float* dWih   = (const float*)d_in[11];
    const float* dWhh   = (const float*)d_in[12];
    const float* dbih   = (const float*)d_in[13];
    const float* dbhh   = (const float*)d_in[14];
    const float* qpW    = (const float*)d_in[15];
    const float* qpb    = (const float*)d_in[16];
    const float* dpW    = (const float*)d_in[17];
    const float* dpb    = (const float*)d_in[18];
    const float* alpha  = (const float*)d_in[19];
    const float* c1W    = (const float*)d_in[20];
    const float* c1b    = (const float*)d_in[21];
    const float* c2W    = (const float*)d_in[22];
    const float* c2b    = (const float*)d_in[23];
    const float* c3W    = (const float*)d_in[24];
    const float* c3b    = (const float*)d_in[25];
    const float* ccW    = (const float*)d_in[26];
    const float* ccb    = (const float*)d_in[27];
    const float* outW   = (const float*)d_in[28];
    const float* outb   = (const float*)d_in[29];
    float* out = (float*)d_out;

    float *pXq,*pXd,*pxgq,*pxgd,*pencq,*pencd,*pc,*ppq,*ppdT,*ps3,*ps5,*ps7,*pqb,*pdb,*pz;
    cudaGetSymbolAddress((void**)&pXq,  g_Xq);
    cudaGetSymbolAddress((void**)&pXd,  g_Xd);
    cudaGetSymbolAddress((void**)&pxgq, g_xgq);
    cudaGetSymbolAddress((void**)&pxgd, g_xgd);
    cudaGetSymbolAddress((void**)&pencq,g_encq);
    cudaGetSymbolAddress((void**)&pencd,g_encd);
    cudaGetSymbolAddress((void**)&pc,   g_c);
    cudaGetSymbolAddress((void**)&ppq,  g_pq);
    cudaGetSymbolAddress((void**)&ppdT, g_pdT);
    cudaGetSymbolAddress((void**)&ps3,  g_s3);
    cudaGetSymbolAddress((void**)&ps5,  g_s5);
    cudaGetSymbolAddress((void**)&ps7,  g_s7);
    cudaGetSymbolAddress((void**)&pqb,  g_qb);
    cudaGetSymbolAddress((void**)&pdb,  g_db);
    cudaGetSymbolAddress((void**)&pz,   g_zero);

    bias_sum_k<<<4,256>>>(qbih,qbhh,dbih,dbhh);

    // embed + proj:  X = emb[tok] @ projW + projb
    sgemm64<true,false,0><<<dim3(5,8),256>>>(emb,bqtok,Ff, projW,Ff, projb, pXq,Ff, NTQ,Ff,Ff);
    sgemm64<true,false,0><<<dim3(5,640),256>>>(emb,bdtok,Ff, projW,Ff, projb, pXd,Ff, NTD,Ff,Ff);

    // input gates: xg = X @ Wih^T + (bih+bhh)
    sgemm64<false,true,0><<<dim3(16,8),256>>>(pXq,nullptr,Ff, qWih,Ff, pqb, pxgq,G4, NTQ,G4,Ff);
    sgemm64<false,true,0><<<dim3(16,640),256>>>(pXd,nullptr,Ff, dWih,Ff, pdb, pxgd,G4, NTD,G4,Ff);

    // query LSTM (32 sequences, 16 steps)
    for (int t = 0; t < QLn; t++){
        const float* hp = (t == 0) ? pz : (pencq + (size_t)(t-1)*Hh);
        int hs = (t == 0) ? 0 : QLn*Hh;
        lstm_step_k<<<dim3(1,32),64>>>(pxgq,qWhh,hp,hs,pc,pencq,QLn,t);
    }
    // doc LSTM (320 sequences, 128 steps)
    for (int t = 0; t < DLn; t++){
        const float* hp = (t == 0) ? pz : (pencd + (size_t)(t-1)*Hh);
        int hs = (t == 0) ? 0 : DLn*Hh;
        lstm_step_k<<<dim3(10,32),64>>>(pxgd,dWhh,hp,hs,pc,pencd,DLn,t);
    }

    // projections: pq [512,50]; pd transposed per image [img][c][dl]
    sgemm64<false,false,0><<<dim3(1,8),256>>>(pencq,nullptr,Hh, qpW,Cc, qpb, ppq,Cc, NTQ,Cc,Hh);
    sgemm64<false,false,1><<<dim3(1,640),256>>>(pencd,nullptr,Hh, dpW,Cc, dpb, ppdT,0, NTD,Cc,Hh);

    // conv stage 1
    {
        long t3 = (long)Bq*NFc*QLn*3*Cc, t5 = (long)Bq*NFc*QLn*5*Cc, t7 = (long)Bq*NFc*QLn*7*Cc;
        s_k<<<(unsigned)((t3+255)/256),256>>>(c1W, ps3, 3, t3);
        s_k<<<(unsigned)((t5+255)/256),256>>>(c2W, ps5, 5, t5);
        s_k<<<(unsigned)((t7+255)/256),256>>>(c3W, ps7, 7, t7);
    }
    // conv stage 2 (GEMM + exact-match + relu)
    convgemm_k<3><<<dim3(7,BD),256>>>(ps3, c1W, c1b, bqtok, bdtok, alpha, 0);
    convgemm_k<5><<<dim3(7,BD),256>>>(ps5, c2W, c2b, bqtok, bdtok, alpha, 50);
    convgemm_k<7><<<dim3(7,BD),256>>>(ps7, c3W, c3b, bqtok, bdtok, alpha, 100);

    // 1x1 conv + maxpool + output linear
    score_k<<<BD,256>>>(ccW, ccb, outW, outb, out);
}

// round 3
// speedup vs baseline: 1.1952x; 1.1952x over previous
#include <cuda_runtime.h>
#include <math.h>

// ---------------- problem constants ----------------
#define Bq  32
#define Dn  10
#define QLn 16
#define DLn 128
#define BD  320
#define Ff  300
#define Hh  256
#define G4  1024
#define Cc  50
#define NFc 50
#define MFc 20
#define NTQ (Bq*QLn)      // 512
#define NTD (BD*DLn)      // 40960

// ---------------- device scratch ----------------
__device__ float g_Xq[NTQ*Ff];
__device__ float g_Xd[(size_t)NTD*Ff];
__device__ float g_xgq[(size_t)NTQ*G4];
__device__ float g_xgd[(size_t)NTD*G4];
__device__ float g_encq[NTQ*Hh];
__device__ float g_encd[(size_t)NTD*Hh];
__device__ float g_c[BD*Hh];
__device__ float g_pq[NTQ*Cc];
__device__ float g_pdT[(size_t)BD*Cc*DLn];
__device__ float g_s3[(size_t)Bq*NFc*QLn*3*Cc];
__device__ float g_s5[(size_t)Bq*NFc*QLn*5*Cc];
__device__ float g_s7[(size_t)Bq*NFc*QLn*7*Cc];
__device__ float g_f[(size_t)BD*150*QLn*DLn];
__device__ float g_qb[G4];
__device__ float g_db[G4];
__device__ float g_zero[Hh];   // never written: stays zero

__device__ __forceinline__ float sigf(float x){ return 1.f/(1.f+expf(-x)); }

__device__ __forceinline__ unsigned f2tf(float x){
    unsigned r; asm("cvt.rna.tf32.f32 %0, %1;" : "=r"(r) : "f"(x)); return r;
}
__device__ __forceinline__ void mma8(float* c, const unsigned* a, const unsigned* b){
    asm volatile("mma.sync.aligned.m16n8k8.row.col.f32.tf32.tf32.f32 "
        "{%0,%1,%2,%3}, {%4,%5,%6,%7}, {%8,%9}, {%0,%1,%2,%3};"
        : "+f"(c[0]),"+f"(c[1]),"+f"(c[2]),"+f"(c[3])
        : "r"(a[0]),"r"(a[1]),"r"(a[2]),"r"(a[3]), "r"(b[0]),"r"(b[1]));
}

// ---------------- bias precombine ----------------
__global__ void bias_sum_k(const float* __restrict__ qb1, const float* __restrict__ qb2,
                           const float* __restrict__ db1, const float* __restrict__ db2)
{
    int t = blockIdx.x*blockDim.x + threadIdx.x;
    if (t < G4){ g_qb[t] = qb1[t]+qb2[t]; g_db[t] = db1[t]+db2[t]; }
}

// ---------------- tf32 tensor-core GEMM: 128x128 tile, 8 warps ----------------
// C[M,N] = A(gathered)[M,K] * B + bias.  BT: B is [N,K].  M must be multiple of 128.
// STORE 0: C[m*ldc+n].  STORE 1: pdT: img=m>>7, dl=m&127 -> C[(img*50+n)*128+dl]
template<bool GATHER, bool BT, int STORE>
__global__ __launch_bounds__(256,1) void gemm_tf32(
    const float* __restrict__ A, const int* __restrict__ idx, int lda,
    const float* __restrict__ Bm, int ldb, const float* __restrict__ bias,
    float* __restrict__ C, int ldc, int M, int N, int K)
{
    __shared__ unsigned As[2][16][132];
    __shared__ unsigned Bs[2][16][132];
    int tid = threadIdx.x;
    int lane = tid & 31, warp = tid >> 5;
    int wm = warp >> 2, wn = warp & 3;
    int m0 = blockIdx.y*128, n0 = blockIdx.x*128;
    int nk = (K + 15) >> 4;

    int ar = tid >> 1;          // A row 0..127
    int ak = (tid & 1) * 8;     // 0 or 8
    const float* Aptr;
    { long r = GATHER ? (long)idx[m0+ar] : (long)(m0+ar);
      Aptr = A + r*(long)lda + ak; }

    float av[8], bv[8];
    // --- global load into regs for tile kt ---
    auto ldg = [&](int kt){
        int k0 = kt*16;
        #pragma unroll
        for (int i=0;i<8;i++){
            int kk = k0 + ak + i;
            av[i] = (kk < K) ? Aptr[k0+i] : 0.f;
        }
        if (BT){
            int nr = tid>>1, bk=(tid&1)*8;
            const float* bp = Bm + (size_t)(n0+nr)*ldb;
            bool nok = (n0+nr) < N;
            #pragma unroll
            for (int i=0;i<8;i++){
                int kk = k0 + bk + i;
                bv[i] = (nok && kk < K) ? bp[kk] : 0.f;
            }
        } else {
            int nc = (tid&31)*4, kr = tid>>5;
            #pragma unroll
            for (int h=0;h<2;h++){
                int kk = k0 + kr + h*8;
                #pragma unroll
                for (int j=0;j<4;j++){
                    int n = n0 + nc + j;
                    bv[h*4+j] = (kk < K && n < N) ? Bm[(size_t)kk*ldb + n] : 0.f;
                }
            }
        }
    };
    auto sts = [&](int buf){
        #pragma unroll
        for (int i=0;i<8;i++) As[buf][ak+i][ar] = f2tf(av[i]);
        if (BT){
            int nr = tid>>1, bk=(tid&1)*8;
            #pragma unroll
            for (int i=0;i<8;i++) Bs[buf][bk+i][nr] = f2tf(bv[i]);
        } else {
            int nc = (tid&31)*4, kr = tid>>5;
            #pragma unroll
            for (int h=0;h<2;h++)
                #pragma unroll
                for (int j=0;j<4;j++) Bs[buf][kr+h*8][nc+j] = f2tf(bv[h*4+j]);
        }
    };

    float acc[4][4][4] = {};
    int r8 = lane>>2, q4 = lane&3;

    ldg(0); sts(0); __syncthreads();
    for (int kt = 0; kt < nk; kt++){
        int p = kt & 1;
        if (kt+1 < nk) ldg(kt+1);
        #pragma unroll
        for (int kb=0; kb<2; kb++){
            int ko = kb*8;
            unsigned af[4][4], bf[4][2];
            #pragma unroll
            for (int mt=0; mt<4; mt++){
                int rb = wm*64 + mt*16;
                af[mt][0] = As[p][ko+q4  ][rb+r8];
                af[mt][1] = As[p][ko+q4  ][rb+r8+8];
                af[mt][2] = As[p][ko+q4+4][rb+r8];
                af[mt][3] = As[p][ko+q4+4][rb+r8+8];
            }
            #pragma unroll
            for (int nt=0; nt<4; nt++){
                int nb = wn*32 + nt*8;
                bf[nt][0] = Bs[p][ko+q4  ][nb+r8];
                bf[nt][1] = Bs[p][ko+q4+4][nb+r8];
            }
            #pragma unroll
            for (int mt=0;mt<4;mt++)
                #pragma unroll
                for (int nt=0;nt<4;nt++)
                    mma8(acc[mt][nt], af[mt], bf[nt]);
        }
        if (kt+1 < nk) sts(p^1);
        __syncthreads();
    }

    #pragma unroll
    for (int mt=0;mt<4;mt++){
        int row = m0 + wm*64 + mt*16 + r8;
        #pragma unroll
        for (int nt=0;nt<4;nt++){
            int col = n0 + wn*32 + nt*8 + q4*2;
            const float* cc = acc[mt][nt];
            #pragma unroll
            for (int j=0;j<2;j++){
                int n = col + j;
                if (n >= N) continue;
                float bb = bias ? bias[n] : 0.f;
                float v0 = cc[j] + bb, v1 = cc[2+j] + bb;
                if (STORE == 0){
                    C[(size_t)row*ldc + n] = v0;
                    C[(size_t)(row+8)*ldc + n] = v1;
                } else {
                    int img = row >> 7;
                    C[((size_t)img*Cc + n)*DLn + (row & 127)] = v0;
                    C[((size_t)img*Cc + n)*DLn + ((row+8) & 127)] = v1;
                }
            }
        }
    }
}

// ---------------- fused LSTM step (128 threads, 32x32 tile) ----------------
__global__ __launch_bounds__(128) void lstm_step_k(
    const float* __restrict__ xg, const float* __restrict__ Whh,
    const float* __restrict__ hprev, int hstride,
    float* __restrict__ cst, float* __restrict__ enc, int T, int t)
{
    __shared__ float As[32][34];   // [k][m]
    __shared__ float Bs[32][33];   // [c][k], c = 4*hh + gate
    int tid = threadIdx.x;
    int mb = blockIdx.x*32, h0 = blockIdx.y*8;
    int tym = tid>>3, txc = tid&7;
    int lr = tid>>2, l4 = (tid&3)*8;
    int wrow = ((lr & 3)*Hh) + h0 + (lr >> 2);
    float acc[2][4] = {};

    for (int k0 = 0; k0 < Hh; k0 += 32){
        const float* hp = hprev + (size_t)(mb+lr)*hstride + k0 + l4;
        #pragma unroll
        for (int u = 0; u < 8; u += 4){
            float4 v = *(const float4*)(hp + u);
            As[l4+u+0][lr]=v.x; As[l4+u+1][lr]=v.y;
            As[l4+u+2][lr]=v.z; As[l4+u+3][lr]=v.w;
        }
        const float* wp = Whh + (size_t)wrow*Hh + k0 + l4;
        #pragma unroll
        for (int u = 0; u < 8; u += 4){
            float4 v = *(const float4*)(wp + u);
            Bs[lr][l4+u+0]=v.x; Bs[lr][l4+u+1]=v.y;
            Bs[lr][l4+u+2]=v.z; Bs[lr][l4+u+3]=v.w;
        }
        __syncthreads();
        #pragma unroll
        for (int kk = 0; kk < 32; kk++){
            float2 a = *(const float2*)&As[kk][tym*2];
            float b0 = Bs[txc*4+0][kk], b1 = Bs[txc*4+1][kk];
            float b2 = Bs[txc*4+2][kk], b3 = Bs[txc*4+3][kk];
            acc[0][0]+=a.x*b0; acc[0][1]+=a.x*b1; acc[0][2]+=a.x*b2; acc[0][3]+=a.x*b3;
            acc[1][0]+=a.y*b0; acc[1][1]+=a.y*b1; acc[1][2]+=a.y*b2; acc[1][3]+=a.y*b3;
        }
        __syncthreads();
    }
    int h = h0 + txc;
    #pragma unroll
    for (int r = 0; r < 2; r++){
        int m = mb + tym*2 + r;
        size_t tok = (size_t)m*T + t;
        const float* xb = xg + tok*G4;
        float gi = acc[r][0] + xb[h];
        float gf = acc[r][1] + xb[Hh + h];
        float gg = acc[r][2] + xb[2*Hh + h];
        float go = acc[r][3] + xb[3*Hh + h];
        float cp = (t == 0) ? 0.f : cst[(size_t)m*Hh + h];
        float cv = sigf(gf)*cp + sigf(gi)*tanhf(gg);
        float hv = sigf(go)*tanhf(cv);
        cst[(size_t)m*Hh + h] = cv;
        enc[tok*Hh + h] = hv;
    }
}

// ---------------- conv stage 1 ----------------
__global__ void s_k(const float* __restrict__ cW, float* __restrict__ s, int KW, long total)
{
    long i = (long)blockIdx.x*blockDim.x + threadIdx.x;
    if (i >= total) return;
    int c  = (int)(i % Cc);
    long r = i / Cc;
    int dd = (int)(r % KW); r /= KW;
    int q  = (int)(r % QLn); r /= QLn;
    int o  = (int)(r % NFc);
    int b  = (int)(r / NFc);
    float v = 0.f;
    #pragma unroll
    for (int dq = 0; dq < 3; dq++){
        int qq = q + dq - 1;
        if (qq >= 0 && qq < QLn)
            v += cW[(((size_t)o*51 + c)*3 + dq)*KW + dd] * g_pq[((size_t)b*QLn + qq)*Cc + c];
    }
    s[i] = v;
}

// ---------------- conv stage 2: tf32 mma GEMM + EM epilogue + relu ----------------
template<int KW>
__global__ __launch_bounds__(256,1) void convgemm_k(
    const float* __restrict__ sA, const float* __restrict__ cW,
    const float* __restrict__ cb, const int* __restrict__ bqtok,
    const int* __restrict__ bdtok, const float* __restrict__ alpha, int OCB)
{
    const int K = Cc*KW, PW = KW/2;
    __shared__ unsigned As[2][16][132];
    __shared__ unsigned Bs[2][16][132];
    __shared__ float ems[18][136];
    __shared__ float wem[8][3*KW];
    __shared__ int qt[16], dt[128], s_any;
    int tid = threadIdx.x;
    int lane = tid & 31, warp = tid >> 5;
    int wm = warp >> 2, wn = warp & 3;
    int img = blockIdx.y, b = img / Dn;
    int m0 = blockIdx.x*128, obase = m0 >> 4;
    int nk = (K + 15) >> 4;

    if (tid == 0) s_any = 0;
    if (tid < 16) qt[tid] = bqtok[b*QLn + tid];
    if (tid < 128) dt[tid] = bdtok[(size_t)img*DLn + tid];
    if (tid < 8*3*KW){
        int ol = tid/(3*KW), rr = tid%(3*KW);
        int o = obase + ol;
        wem[ol][rr] = (o < NFc) ? cW[(((size_t)o*51 + 50)*3 + rr/KW)*KW + rr%KW] : 0.f;
    }
    __syncthreads();
    float al = alpha[0];
    for (int e = tid; e < 18*136; e += 256){
        int qi = e/136, dj = e%136;
        int q = qi-1, dl = dj-3;
        float v = 0.f;
        if (q >= 0 && q < QLn && dl >= 0 && dl < DLn && qt[q] == dt[dl]){ v = al; s_any = 1; }
        ems[qi][dj] = v;
    }

    const float* Ab = sA + (size_t)b*800*K;
    const float* Pd = &g_pdT[(size_t)img*Cc*DLn];
    int ar = tid >> 1, ak = (tid & 1)*8;
    bool mok = (m0 + ar) < 800;
    const float* Aptr = Ab + (size_t)(mok ? (m0+ar) : 0)*K + ak;

    float av[8], bv[8];
    auto ldg = [&](int kt){
        int k0 = kt*16;
        #pragma unroll
        for (int i=0;i<8;i++){
            int kk = k0 + ak + i;
            av[i] = (mok && kk < K) ? Aptr[k0+i] : 0.f;
        }
        int nc = (tid&31)*4, kr = tid>>5;
        #pragma unroll
        for (int h=0;h<2;h++){
            int kk = k0 + kr + h*8;
            int dd = kk/Cc, c = kk - dd*Cc;
            #pragma unroll
            for (int j=0;j<4;j++){
                int sdl = nc + j + dd - PW;
                bv[h*4+j] = (kk < K && sdl >= 0 && sdl < DLn) ? Pd[(size_t)c*DLn + sdl] : 0.f;
            }
        }
    };
    auto sts = [&](int buf){
        #pragma unroll
        for (int i=0;i<8;i++) As[buf][ak+i][ar] = f2tf(av[i]);
        int nc = (tid&31)*4, kr = tid>>5;
        #pragma unroll
        for (int h=0;h<2;h++)
            #pragma unroll
            for (int j=0;j<4;j++) Bs[buf][kr+h*8][nc+j] = f2tf(bv[h*4+j]);
    };

    float acc[4][4][4] = {};
    int r8 = lane>>2, q4 = lane&3;
    __syncthreads();           // ems/qt/dt done before reusing nothing, but keep order
    ldg(0); sts(0); __syncthreads();
    for (int kt = 0; kt < nk; kt++){
        int p = kt & 1;
        if (kt+1 < nk) ldg(kt+1);
        #pragma unroll
        for (int kb=0; kb<2; kb++){
            int ko = kb*8;
            unsigned af[4][4], bf[4][2];
            #pragma unroll
            for (int mt=0; mt<4; mt++){
                int rb = wm*64 + mt*16;
                af[mt][0] = As[p][ko+q4  ][rb+r8];
                af[mt][1] = As[p][ko+q4  ][rb+r8+8];
                af[mt][2] = As[p][ko+q4+4][rb+r8];
                af[mt][3] = As[p][ko+q4+4][rb+r8+8];
            }
            #pragma unroll
            for (int nt=0; nt<4; nt++){
                int nb = wn*32 + nt*8;
                bf[nt][0] = Bs[p][ko+q4  ][nb+r8];
                bf[nt][1] = Bs[p][ko+q4+4][nb+r8];
            }
            #pragma unroll
            for (int mt=0;mt<4;mt++)
                #pragma unroll
                for (int nt=0;nt<4;nt++)
                    mma8(acc[mt][nt], af[mt], bf[nt]);
        }
        if (kt+1 < nk) sts(p^1);
        __syncthreads();
    }

    int any = s_any;
    #pragma unroll
    for (int mt=0;mt<4;mt++){
        int row = m0 + wm*64 + mt*16;          // 16-aligned
        if (row >= 800) continue;
        int o = row >> 4, ol = o - obase;
        float bias = cb[o];
        #pragma unroll
        for (int rr=0; rr<2; rr++){
            int q = r8 + rr*8;
            #pragma unroll
            for (int nt=0;nt<4;nt++){
                int col = wn*32 + nt*8 + q4*2;
                #pragma unroll
                for (int j=0;j<2;j++){
                    int dl = col + j;
                    float v = acc[mt][nt][rr*2 + j] + bias;
                    if (any){
                        #pragma unroll
                        for (int dq = 0; dq < 3; dq++)
                            #pragma unroll
                            for (int dd = 0; dd < KW; dd++)
                                v += wem[ol][dq*KW+dd] * ems[q+dq][dl+dd+3-PW];
                    }
                    v = fmaxf(v, 0.f);
                    g_f[(((size_t)img*150 + OCB + o)*QLn + q)*DLn + dl] = v;
                }
            }
        }
    }
}

// ---------------- 1x1 conv + global maxpool + linear ----------------
__global__ __launch_bounds__(256) void score_k(
    const float* __restrict__ ccW, const float* __restrict__ ccb,
    const float* __restrict__ outW, const float* __restrict__ outb,
    float* __restrict__ out)
{
    __shared__ float w[MFc][152];
    __shared__ float red[8][MFc];
    int img = blockIdx.x, tid = threadIdx.x;
    for (int e = tid; e < MFc*150; e += 256) w[e/150][e%150] = ccW[e];
    __syncthreads();
    float mx[MFc];
    #pragma unroll
    for (int mf = 0; mf < MFc; mf++) mx[mf] = -1e30f;
    const float* fb = &g_f[(size_t)img*150*QLn*DLn];
    for (int p = tid; p < QLn*DLn; p += 256){
        float acc[MFc];
        #pragma unroll
        for (int mf = 0; mf < MFc; mf++) acc[mf] = ccb[mf];
        for (int nf = 0; nf < 150; nf++){
            float v = fb[(size_t)nf*QLn*DLn + p];
            #pragma unroll
            for (int mf = 0; mf < MFc; mf++) acc[mf] += v*w[mf][nf];
        }
        #pragma unroll
        for (int mf = 0; mf < MFc; mf++) mx[mf] = fmaxf(mx[mf], acc[mf]);
    }
    #pragma unroll
    for (int off = 16; off; off >>= 1)
        #pragma unroll
        for (int mf = 0; mf < MFc; mf++)
            mx[mf] = fmaxf(mx[mf], __shfl_xor_sync(0xFFFFFFFFu, mx[mf], off));
    if ((tid & 31) == 0)
        #pragma unroll
        for (int mf = 0; mf < MFc; mf++) red[tid>>5][mf] = mx[mf];
    __syncthreads();
    if (tid == 0){
        float sc = outb[0];
        #pragma unroll
        for (int mf = 0; mf < MFc; mf++){
            float m = red[0][mf];
            #pragma unroll
            for (int wp = 1; wp < 8; wp++) m = fmaxf(m, red[wp][mf]);
            sc += m*outW[mf];
        }
        out[img] = sc;
    }
}

// ---------------- launch ----------------
extern "C" void kernel_launch(void* const* d_in, const int* in_sizes, int n_in,
                              void* d_out, int out_size)
{
    const int* bqtok = nullptr; const int* bdtok = nullptr;
    for (int i = 0; i < 4; i++){
        if (in_sizes[i] == NTQ)      bqtok = (const int*)d_in[i];
        else if (in_sizes[i] == NTD) bdtok = (const int*)d_in[i];
    }
    const float* emb    = (const float*)d_in[4];
    const float* projW  = (const float*)d_in[5];
    const float* projb  = (const float*)d_in[6];
    const float* qWih   = (const float*)d_in[7];
    const float* qWhh   = (const float*)d_in[8];
    const float* qbih   = (const float*)d_in[9];
    const float* qbhh   = (const float*)d_in[10];
    const float* dWih   = (const float*)d_in[11];
    const float* dWhh   = (const float*)d_in[12];
    const float* dbih   = (const float*)d_in[13];
    const float* dbhh   = (const float*)d_in[14];
    const float* qpW    = (const float*)d_in[15];
    const float* qpb    = (const float*)d_in[16];
    const float* dpW    = (const float*)d_in[17];
    const float* dpb    = (const float*)d_in[18];
    const float* alpha  = (const float*)d_in[19];
    const float* c1W    = (const float*)d_in[20];
    const float* c1b    = (const float*)d_in[21];
    const float* c2W    = (const float*)d_in[22];
    const float* c2b    = (const float*)d_in[23];
    const float* c3W    = (const float*)d_in[24];
    const float* c3b    = (const float*)d_in[25];
    const float* ccW    = (const float*)d_in[26];
    const float* ccb    = (const float*)d_in[27];
    const float* outW   = (const float*)d_in[28];
    const float* outb   = (const float*)d_in[29];
    float* out = (float*)d_out;

    float *pXq,*pXd,*pxgq,*pxgd,*pencq,*pencd,*pc,*ppq,*ppdT,*ps3,*ps5,*ps7,*pqb,*pdb,*pz;
    cudaGetSymbolAddress((void**)&pXq,  g_Xq);
    cudaGetSymbolAddress((void**)&pXd,  g_Xd);
    cudaGetSymbolAddress((void**)&pxgq, g_xgq);
    cudaGetSymbolAddress((void**)&pxgd, g_xgd);
    cudaGetSymbolAddress((void**)&pencq,g_encq);
    cudaGetSymbolAddress((void**)&pencd,g_encd);
    cudaGetSymbolAddress((void**)&pc,   g_c);
    cudaGetSymbolAddress((void**)&ppq,  g_pq);
    cudaGetSymbolAddress((void**)&ppdT, g_pdT);
    cudaGetSymbolAddress((void**)&ps3,  g_s3);
    cudaGetSymbolAddress((void**)&ps5,  g_s5);
    cudaGetSymbolAddress((void**)&ps7,  g_s7);
    cudaGetSymbolAddress((void**)&pqb,  g_qb);
    cudaGetSymbolAddress((void**)&pdb,  g_db);
    cudaGetSymbolAddress((void**)&pz,   g_zero);

    bias_sum_k<<<4,256>>>(qbih,qbhh,dbih,dbhh);

    // embed + proj (tf32):  X = emb[tok] @ projW + projb
    gemm_tf32<true,false,0><<<dim3(3,4),256>>>(emb,bqtok,Ff, projW,Ff, projb, pXq,Ff, NTQ,Ff,Ff);
    gemm_tf32<true,false,0><<<dim3(3,320),256>>>(emb,bdtok,Ff, projW,Ff, projb, pXd,Ff, NTD,Ff,Ff);

    // input gates: xg = X @ Wih^T + (bih+bhh)
    gemm_tf32<false,true,0><<<dim3(8,4),256>>>(pXq,nullptr,Ff, qWih,Ff, pqb, pxgq,G4, NTQ,G4,Ff);
    gemm_tf32<false,true,0><<<dim3(8,320),256>>>(pXd,nullptr,Ff, dWih,Ff, pdb, pxgd,G4, NTD,G4,Ff);

    // query LSTM (32 sequences, 16 steps)
    for (int t = 0; t < QLn; t++){
        const float* hp = (t == 0) ? pz : (pencq + (size_t)(t-1)*Hh);
        int hs = (t == 0) ? 0 : QLn*Hh;
        lstm_step_k<<<dim3(1,32),128>>>(pxgq,qWhh,hp,hs,pc,pencq,QLn,t);
    }
    // doc LSTM (320 sequences, 128 steps)
    for (int t = 0; t < DLn; t++){
        const float* hp = (t == 0) ? pz : (pencd + (size_t)(t-1)*Hh);
        int hs = (t == 0) ? 0 : DLn*Hh;
        lstm_step_k<<<dim3(10,32),128>>>(pxgd,dWhh,hp,hs,pc,pencd,DLn,t);
    }

    // projections: pq [512,50]; pd transposed per image [img][c][dl]
    gemm_tf32<false,false,0><<<dim3(1,4),256>>>(pencq,nullptr,Hh, qpW,Cc, qpb, ppq,Cc, NTQ,Cc,Hh);
    gemm_tf32<false,false,1><<<dim3(1,320),256>>>(pencd,nullptr,Hh, dpW,Cc, dpb, ppdT,0, NTD,Cc,Hh);

    // conv stage 1
    {
        long t3 = (long)Bq*NFc*QLn*3*Cc, t5 = (long)Bq*NFc*QLn*5*Cc, t7 = (long)Bq*NFc*QLn*7*Cc;
        s_k<<<(unsigned)((t3+255)/256),256>>>(c1W, ps3, 3, t3);
        s_k<<<(unsigned)((t5+255)/256),256>>>(c2W, ps5, 5, t5);
        s_k<<<(unsigned)((t7+255)/256),256>>>(c3W, ps7, 7, t7);
    }
    // conv stage 2 (tf32 GEMM + exact-match + relu)
    convgemm_k<3><<<dim3(7,BD),256>>>(ps3, c1W, c1b, bqtok, bdtok, alpha, 0);
    convgemm_k<5><<<dim3(7,BD),256>>>(ps5, c2W, c2b, bqtok, bdtok, alpha, 50);
    convgemm_k<7><<<dim3(7,BD),256>>>(ps7, c3W, c3b, bqtok, bdtok, alpha, 100);

    // 1x1 conv + maxpool + output linear
    score_k<<<BD,256>>>(ccW, ccb, outW, outb, out);
}

// round 4
// speedup vs baseline: 1.3586x; 1.1367x over previous
#include <cuda_runtime.h>
#include <math.h>

// ---------------- problem constants ----------------
#define Bq  32
#define Dn  10
#define QLn 16
#define DLn 128
#define BD  320
#define Ff  300
#define Hh  256
#define G4  1024
#define Cc  50
#define NFc 50
#define MFc 20
#define NTQ (Bq*QLn)      // 512
#define NTD (BD*DLn)      // 40960

// ---------------- device scratch ----------------
__device__ float g_Xq[NTQ*Ff];
__device__ float g_Xd[(size_t)NTD*Ff];
__device__ float g_xgq[(size_t)NTQ*G4];
__device__ float g_xgd[(size_t)NTD*G4];
__device__ float g_encq[NTQ*Hh];
__device__ float g_encd[(size_t)NTD*Hh];
__device__ float g_c[BD*Hh];
__device__ float g_pq[NTQ*Cc];
__device__ float g_pdT[(size_t)BD*Cc*DLn];
__device__ float g_s3[(size_t)Bq*NFc*QLn*3*Cc];
__device__ float g_s5[(size_t)Bq*NFc*QLn*5*Cc];
__device__ float g_s7[(size_t)Bq*NFc*QLn*7*Cc];
__device__ float g_f[(size_t)BD*150*QLn*DLn];
__device__ float g_qb[G4];
__device__ float g_db[G4];
__device__ unsigned g_barcnt = 0;
__device__ unsigned g_bargen = 0;

__device__ __forceinline__ float sigf(float x){ return 1.f/(1.f+expf(-x)); }

__device__ __forceinline__ unsigned f2tf(float x){
    unsigned r; asm("cvt.rna.tf32.f32 %0, %1;" : "=r"(r) : "f"(x)); return r;
}
__device__ __forceinline__ void mma8(float* c, const unsigned* a, const unsigned* b){
    asm volatile("mma.sync.aligned.m16n8k8.row.col.f32.tf32.tf32.f32 "
        "{%0,%1,%2,%3}, {%4,%5,%6,%7}, {%8,%9}, {%0,%1,%2,%3};"
        : "+f"(c[0]),"+f"(c[1]),"+f"(c[2]),"+f"(c[3])
        : "r"(a[0]),"r"(a[1]),"r"(a[2]),"r"(a[3]), "r"(b[0]),"r"(b[1]));
}

// software grid barrier (all blocks co-resident: grid <= 148, 1 block/SM)
__device__ __forceinline__ void gridbar(int nblocks){
    __syncthreads();
    if (threadIdx.x == 0){
        __threadfence();
        unsigned gen = *((volatile unsigned*)&g_bargen);
        if (atomicAdd(&g_barcnt, 1u) == (unsigned)nblocks - 1u){
            g_barcnt = 0;
            __threadfence();
            atomicAdd(&g_bargen, 1u);
        } else {
            while (*((volatile unsigned*)&g_bargen) == gen) __nanosleep(40);
        }
        __threadfence();
    }
    __syncthreads();
}

// ---------------- bias precombine ----------------
__global__ void bias_sum_k(const float* __restrict__ qb1, const float* __restrict__ qb2,
                           const float* __restrict__ db1, const float* __restrict__ db2)
{
    int t = blockIdx.x*blockDim.x + threadIdx.x;
    if (t < G4){ g_qb[t] = qb1[t]+qb2[t]; g_db[t] = db1[t]+db2[t]; }
}

// ---------------- tf32 tensor-core GEMM: 128x128 tile, 8 warps ----------------
template<bool GATHER, bool BT, int STORE>
__global__ __launch_bounds__(256,1) void gemm_tf32(
    const float* __restrict__ A, const int* __restrict__ idx, int lda,
    const float* __restrict__ Bm, int ldb, const float* __restrict__ bias,
    float* __restrict__ C, int ldc, int M, int N, int K)
{
    __shared__ unsigned As[2][16][132];
    __shared__ unsigned Bs[2][16][132];
    int tid = threadIdx.x;
    int lane = tid & 31, warp = tid >> 5;
    int wm = warp >> 2, wn = warp & 3;
    int m0 = blockIdx.y*128, n0 = blockIdx.x*128;
    int nk = (K + 15) >> 4;

    int ar = tid >> 1;
    int ak = (tid & 1) * 8;
    const float* Aptr;
    { long r = GATHER ? (long)idx[m0+ar] : (long)(m0+ar);
      Aptr = A + r*(long)lda + ak; }

    float av[8], bv[8];
    auto ldg = [&](int kt){
        int k0 = kt*16;
        #pragma unroll
        for (int i=0;i<8;i++){
            int kk = k0 + ak + i;
            av[i] = (kk < K) ? Aptr[k0+i] : 0.f;
        }
        if (BT){
            int nr = tid>>1, bk=(tid&1)*8;
            const float* bp = Bm + (size_t)(n0+nr)*ldb;
            bool nok = (n0+nr) < N;
            #pragma unroll
            for (int i=0;i<8;i++){
                int kk = k0 + bk + i;
                bv[i] = (nok && kk < K) ? bp[kk] : 0.f;
            }
        } else {
            int nc = (tid&31)*4, kr = tid>>5;
            #pragma unroll
            for (int h=0;h<2;h++){
                int kk = k0 + kr + h*8;
                #pragma unroll
                for (int j=0;j<4;j++){
                    int n = n0 + nc + j;
                    bv[h*4+j] = (kk < K && n < N) ? Bm[(size_t)kk*ldb + n] : 0.f;
                }
            }
        }
    };
    auto sts = [&](int buf){
        #pragma unroll
        for (int i=0;i<8;i++) As[buf][ak+i][ar] = f2tf(av[i]);
        if (BT){
            int nr = tid>>1, bk=(tid&1)*8;
            #pragma unroll
            for (int i=0;i<8;i++) Bs[buf][bk+i][nr] = f2tf(bv[i]);
        } else {
            int nc = (tid&31)*4, kr = tid>>5;
            #pragma unroll
            for (int h=0;h<2;h++)
                #pragma unroll
                for (int j=0;j<4;j++) Bs[buf][kr+h*8][nc+j] = f2tf(bv[h*4+j]);
        }
    };

    float acc[4][4][4] = {};
    int r8 = lane>>2, q4 = lane&3;

    ldg(0); sts(0); __syncthreads();
    for (int kt = 0; kt < nk; kt++){
        int p = kt & 1;
        if (kt+1 < nk) ldg(kt+1);
        #pragma unroll
        for (int kb=0; kb<2; kb++){
            int ko = kb*8;
            unsigned af[4][4], bf[4][2];
            #pragma unroll
            for (int mt=0; mt<4; mt++){
                int rb = wm*64 + mt*16;
                af[mt][0] = As[p][ko+q4  ][rb+r8];
                af[mt][1] = As[p][ko+q4  ][rb+r8+8];
                af[mt][2] = As[p][ko+q4+4][rb+r8];
                af[mt][3] = As[p][ko+q4+4][rb+r8+8];
            }
            #pragma unroll
            for (int nt=0; nt<4; nt++){
                int nb = wn*32 + nt*8;
                bf[nt][0] = Bs[p][ko+q4  ][nb+r8];
                bf[nt][1] = Bs[p][ko+q4+4][nb+r8];
            }
            #pragma unroll
            for (int mt=0;mt<4;mt++)
                #pragma unroll
                for (int nt=0;nt<4;nt++)
                    mma8(acc[mt][nt], af[mt], bf[nt]);
        }
        if (kt+1 < nk) sts(p^1);
        __syncthreads();
    }

    #pragma unroll
    for (int mt=0;mt<4;mt++){
        int row = m0 + wm*64 + mt*16 + r8;
        #pragma unroll
        for (int nt=0;nt<4;nt++){
            int col = n0 + wn*32 + nt*8 + q4*2;
            const float* cc = acc[mt][nt];
            #pragma unroll
            for (int j=0;j<2;j++){
                int n = col + j;
                if (n >= N) continue;
                float bb = bias ? bias[n] : 0.f;
                float v0 = cc[j] + bb, v1 = cc[2+j] + bb;
                if (STORE == 0){
                    C[(size_t)row*ldc + n] = v0;
                    C[(size_t)(row+8)*ldc + n] = v1;
                } else {
                    int img = row >> 7;
                    C[((size_t)img*Cc + n)*DLn + (row & 127)] = v0;
                    C[((size_t)img*Cc + n)*DLn + ((row+8) & 127)] = v1;
                }
            }
        }
    }
}

// ---------------- persistent LSTM ----------------
// grid (nseq/32, 8), 256 threads, all blocks co-resident. Block (nb,hb) owns
// seqs [nb*32,+32) x h-dims [hb*32,+32) x all 4 gates. Whh slice (128 rows,
// remapped col j = hp*4+gate) cached in smem as tf32 for all T steps.
#define LSTM_SMEM ((256*136 + 256*40)*4)
__global__ __launch_bounds__(256,1) void lstm_persist(
    const float* __restrict__ xg, const float* __restrict__ Whh,
    float* __restrict__ cst, float* __restrict__ enc, int T)
{
    extern __shared__ unsigned smbuf[];
    unsigned* Bs = smbuf;                  // [256][136] tf32 Whh slice
    unsigned* As = smbuf + 256*136;        // [256][40]  tf32 h_prev
    float* Gs = (float*)As;                // [32][136]  overlay: gate preacts
    int tid = threadIdx.x;
    int lane = tid & 31, warp = tid >> 5;
    int r8 = lane >> 2, q4 = lane & 3;
    int wm = warp & 1, wn = warp >> 1;
    int n0 = blockIdx.x * 32;
    int h0 = blockIdx.y * 32;
    int nblocks = gridDim.x * gridDim.y;

    for (int idx = tid; idx < 128*256; idx += 256){
        int j = idx >> 8, k = idx & 255;
        int r = ((j & 3) << 8) + h0 + (j >> 2);
        Bs[k*136 + j] = f2tf(Whh[(size_t)r*Hh + k]);
    }
    __syncthreads();

    for (int t = 0; t < T; t++){
        if (t == 0){
            for (int idx = tid; idx < 32*256; idx += 256)
                As[(idx & 255)*40 + (idx >> 8)] = 0u;
        } else {
            for (int idx = tid; idx < 32*256; idx += 256){
                int m = idx >> 8, k = idx & 255;
                As[k*40 + m] = f2tf(enc[((size_t)(n0+m)*T + (t-1))*Hh + k]);
            }
        }
        __syncthreads();

        float acc[4][4] = {};
        int rb = wm*16;
        #pragma unroll 4
        for (int ko = 0; ko < 256; ko += 8){
            unsigned af[4];
            af[0] = As[(ko+q4)*40 + rb + r8];
            af[1] = As[(ko+q4)*40 + rb + r8 + 8];
            af[2] = As[(ko+q4+4)*40 + rb + r8];
            af[3] = As[(ko+q4+4)*40 + rb + r8 + 8];
            #pragma unroll
            for (int nt = 0; nt < 4; nt++){
                int nb = wn*32 + nt*8;
                unsigned bf[2];
                bf[0] = Bs[(ko+q4)*136 + nb + r8];
                bf[1] = Bs[(ko+q4+4)*136 + nb + r8];
                mma8(acc[nt], af, bf);
            }
        }
        __syncthreads();                    // everyone done reading As
        #pragma unroll
        for (int nt = 0; nt < 4; nt++){
            int col = wn*32 + nt*8 + q4*2;
            Gs[(rb+r8)*136 + col]     = acc[nt][0];
            Gs[(rb+r8)*136 + col+1]   = acc[nt][1];
            Gs[(rb+r8+8)*136 + col]   = acc[nt][2];
            Gs[(rb+r8+8)*136 + col+1] = acc[nt][3];
        }
        __syncthreads();

        #pragma unroll
        for (int it = 0; it < 4; it++){
            int id = tid + it*256;
            int m = id >> 5, hp = id & 31;
            int n = n0 + m, h = h0 + hp;
            size_t tok = (size_t)n*T + t;
            const float* xb = xg + tok*(size_t)G4;
            float4 g = *(const float4*)&Gs[m*136 + hp*4];
            float gi = g.x + xb[h];
            float gf = g.y + xb[Hh + h];
            float gg = g.z + xb[2*Hh + h];
            float go = g.w + xb[3*Hh + h];
            float cp = (t == 0) ? 0.f : cst[(size_t)n*Hh + h];
            float cv = sigf(gf)*cp + sigf(gi)*tanhf(gg);
            cst[(size_t)n*Hh + h] = cv;
            enc[tok*Hh + h] = sigf(go)*tanhf(cv);
        }
        gridbar(nblocks);
    }
}

// ---------------- conv stage 1 ----------------
__global__ void s_k(const float* __restrict__ cW, float* __restrict__ s, int KW, long total)
{
    long i = (long)blockIdx.x*blockDim.x + threadIdx.x;
    if (i >= total) return;
    int c  = (int)(i % Cc);
    long r = i / Cc;
    int dd = (int)(r % KW); r /= KW;
    int q  = (int)(r % QLn); r /= QLn;
    int o  = (int)(r % NFc);
    int b  = (int)(r / NFc);
    float v = 0.f;
    #pragma unroll
    for (int dq = 0; dq < 3; dq++){
        int qq = q + dq - 1;
        if (qq >= 0 && qq < QLn)
            v += cW[(((size_t)o*51 + c)*3 + dq)*KW + dd] * g_pq[((size_t)b*QLn + qq)*Cc + c];
    }
    s[i] = v;
}

// ---------------- conv stage 2: tf32 mma GEMM + EM epilogue + relu ----------------
template<int KW>
__global__ __launch_bounds__(256,1) void convgemm_k(
    const float* __restrict__ sA, const float* __restrict__ cW,
    const float* __restrict__ cb, const int* __restrict__ bqtok,
    const int* __restrict__ bdtok, const float* __restrict__ alpha, int OCB)
{
    const int K = Cc*KW, PW = KW/2;
    __shared__ unsigned As[2][16][132];
    __shared__ unsigned Bs[2][16][132];
    __shared__ float ems[18][136];
    __shared__ float wem[8][3*KW];
    __shared__ int qt[16], dt[128], s_any;
    int tid = threadIdx.x;
    int lane = tid & 31, warp = tid >> 5;
    int wm = warp >> 2, wn = warp & 3;
    int img = blockIdx.y, b = img / Dn;
    int m0 = blockIdx.x*128, obase = m0 >> 4;
    int nk = (K + 15) >> 4;

    if (tid == 0) s_any = 0;
    if (tid < 16) qt[tid] = bqtok[b*QLn + tid];
    if (tid < 128) dt[tid] = bdtok[(size_t)img*DLn + tid];
    if (tid < 8*3*KW){
        int ol = tid/(3*KW), rr = tid%(3*KW);
        int o = obase + ol;
        wem[ol][rr] = (o < NFc) ? cW[(((size_t)o*51 + 50)*3 + rr/KW)*KW + rr%KW] : 0.f;
    }
    __syncthreads();
    float al = alpha[0];
    for (int e = tid; e < 18*136; e += 256){
        int qi = e/136, dj = e%136;
        int q = qi-1, dl = dj-3;
        float v = 0.f;
        if (q >= 0 && q < QLn && dl >= 0 && dl < DLn && qt[q] == dt[dl]){ v = al; s_any = 1; }
        ems[qi][dj] = v;
    }

    const float* Ab = sA + (size_t)b*800*K;
    const float* Pd = &g_pdT[(size_t)img*Cc*DLn];
    int ar = tid >> 1, ak = (tid & 1)*8;
    bool mok = (m0 + ar) < 800;
    const float* Aptr = Ab + (size_t)(mok ? (m0+ar) : 0)*K + ak;

    float av[8], bv[8];
    auto ldg = [&](int kt){
        int k0 = kt*16;
        #pragma unroll
        for (int i=0;i<8;i++){
            int kk = k0 + ak + i;
            av[i] = (mok && kk < K) ? Aptr[k0+i] : 0.f;
        }
        int nc = (tid&31)*4, kr = tid>>5;
        #pragma unroll
        for (int h=0;h<2;h++){
            int kk = k0 + kr + h*8;
            int dd = kk/Cc, c = kk - dd*Cc;
            #pragma unroll
            for (int j=0;j<4;j++){
                int sdl = nc + j + dd - PW;
                bv[h*4+j] = (kk < K && sdl >= 0 && sdl < DLn) ? Pd[(size_t)c*DLn + sdl] : 0.f;
            }
        }
    };
    auto sts = [&](int buf){
        #pragma unroll
        for (int i=0;i<8;i++) As[buf][ak+i][ar] = f2tf(av[i]);
        int nc = (tid&31)*4, kr = tid>>5;
        #pragma unroll
        for (int h=0;h<2;h++)
            #pragma unroll
            for (int j=0;j<4;j++) Bs[buf][kr+h*8][nc+j] = f2tf(bv[h*4+j]);
    };

    float acc[4][4][4] = {};
    int r8 = lane>>2, q4 = lane&3;
    __syncthreads();
    ldg(0); sts(0); __syncthreads();
    for (int kt = 0; kt < nk; kt++){
        int p = kt & 1;
        if (kt+1 < nk) ldg(kt+1);
        #pragma unroll
        for (int kb=0; kb<2; kb++){
            int ko = kb*8;
            unsigned af[4][4], bf[4][2];
            #pragma unroll
            for (int mt=0; mt<4; mt++){
                int rb = wm*64 + mt*16;
                af[mt][0] = As[p][ko+q4  ][rb+r8];
                af[mt][1] = As[p][ko+q4  ][rb+r8+8];
                af[mt][2] = As[p][ko+q4+4][rb+r8];
                af[mt][3] = As[p][ko+q4+4][rb+r8+8];
            }
            #pragma unroll
            for (int nt=0; nt<4; nt++){
                int nb = wn*32 + nt*8;
                bf[nt][0] = Bs[p][ko+q4  ][nb+r8];
                bf[nt][1] = Bs[p][ko+q4+4][nb+r8];
            }
            #pragma unroll
            for (int mt=0;mt<4;mt++)
                #pragma unroll
                for (int nt=0;nt<4;nt++)
                    mma8(acc[mt][nt], af[mt], bf[nt]);
        }
        if (kt+1 < nk) sts(p^1);
        __syncthreads();
    }

    int any = s_any;
    #pragma unroll
    for (int mt=0;mt<4;mt++){
        int row = m0 + wm*64 + mt*16;
        if (row >= 800) continue;
        int o = row >> 4, ol = o - obase;
        float bias = cb[o];
        #pragma unroll
        for (int rr=0; rr<2; rr++){
            int q = r8 + rr*8;
            #pragma unroll
            for (int nt=0;nt<4;nt++){
                int col = wn*32 + nt*8 + q4*2;
                #pragma unroll
                for (int j=0;j<2;j++){
                    int dl = col + j;
                    float v = acc[mt][nt][rr*2 + j] + bias;
                    if (any){
                        #pragma unroll
                        for (int dq = 0; dq < 3; dq++)
                            #pragma unroll
                            for (int dd = 0; dd < KW; dd++)
                                v += wem[ol][dq*KW+dd] * ems[q+dq][dl+dd+3-PW];
                    }
                    v = fmaxf(v, 0.f);
                    g_f[(((size_t)img*150 + OCB + o)*QLn + q)*DLn + dl] = v;
                }
            }
        }
    }
}

// ---------------- 1x1 conv + global maxpool + linear ----------------
__global__ __launch_bounds__(256) void score_k(
    const float* __restrict__ ccW, const float* __restrict__ ccb,
    const float* __restrict__ outW, const float* __restrict__ outb,
    float* __restrict__ out)
{
    __shared__ float w[MFc][152];
    __shared__ float red[8][MFc];
    int img = blockIdx.x, tid = threadIdx.x;
    for (int e = tid; e < MFc*150; e += 256) w[e/150][e%150] = ccW[e];
    __syncthreads();
    float mx[MFc];
    #pragma unroll
    for (int mf = 0; mf < MFc; mf++) mx[mf] = -1e30f;
    const float* fb = &g_f[(size_t)img*150*QLn*DLn];
    for (int p = tid; p < QLn*DLn; p += 256){
        float acc[MFc];
        #pragma unroll
        for (int mf = 0; mf < MFc; mf++) acc[mf] = ccb[mf];
        for (int nf = 0; nf < 150; nf++){
            float v = fb[(size_t)nf*QLn*DLn + p];
            #pragma unroll
            for (int mf = 0; mf < MFc; mf++) acc[mf] += v*w[mf][nf];
        }
        #pragma unroll
        for (int mf = 0; mf < MFc; mf++) mx[mf] = fmaxf(mx[mf], acc[mf]);
    }
    #pragma unroll
    for (int off = 16; off; off >>= 1)
        #pragma unroll
        for (int mf = 0; mf < MFc; mf++)
            mx[mf] = fmaxf(mx[mf], __shfl_xor_sync(0xFFFFFFFFu, mx[mf], off));
    if ((tid & 31) == 0)
        #pragma unroll
        for (int mf = 0; mf < MFc; mf++) red[tid>>5][mf] = mx[mf];
    __syncthreads();
    if (tid == 0){
        float sc = outb[0];
        #pragma unroll
        for (int mf = 0; mf < MFc; mf++){
            float m = red[0][mf];
            #pragma unroll
            for (int wp = 1; wp < 8; wp++) m = fmaxf(m, red[wp][mf]);
            sc += m*outW[mf];
        }
        out[img] = sc;
    }
}

// ---------------- launch ----------------
extern "C" void kernel_launch(void* const* d_in, const int* in_sizes, int n_in,
                              void* d_out, int out_size)
{
    const int* bqtok = nullptr; const int* bdtok = nullptr;
    for (int i = 0; i < 4; i++){
        if (in_sizes[i] == NTQ)      bqtok = (const int*)d_in[i];
        else if (in_sizes[i] == NTD) bdtok = (const int*)d_in[i];
    }
    const float* emb    = (const float*)d_in[4];
    const float* projW  = (const float*)d_in[5];
    const float* projb  = (const float*)d_in[6];
    const float* qWih   = (const float*)d_in[7];
    const float* qWhh   = (const float*)d_in[8];
    const float* qbih   = (const float*)d_in[9];
    const float* qbhh   = (const float*)d_in[10];
    const float* dWih   = (const float*)d_in[11];
    const float* dWhh   = (const float*)d_in[12];
    const float* dbih   = (const float*)d_in[13];
    const float* dbhh   = (const float*)d_in[14];
    const float* qpW    = (const float*)d_in[15];
    const float* qpb    = (const float*)d_in[16];
    const float* dpW    = (const float*)d_in[17];
    const float* dpb    = (const float*)d_in[18];
    const float* alpha  = (const float*)d_in[19];
    const float* c1W    = (const float*)d_in[20];
    const float* c1b    = (const float*)d_in[21];
    const float* c2W    = (const float*)d_in[22];
    const float* c2b    = (const float*)d_in[23];
    const float* c3W    = (const float*)d_in[24];
    const float* c3b    = (const float*)d_in[25];
    const float* ccW    = (const float*)d_in[26];
    const float* ccb    = (const float*)d_in[27];
    const float* outW   = (const float*)d_in[28];
    const float* outb   = (const float*)d_in[29];
    float* out = (float*)d_out;

    float *pXq,*pXd,*pxgq,*pxgd,*pencq,*pencd,*pc,*ppq,*ppdT,*ps3,*ps5,*ps7;
    cudaGetSymbolAddress((void**)&pXq,  g_Xq);
    cudaGetSymbolAddress((void**)&pXd,  g_Xd);
    cudaGetSymbolAddress((void**)&pxgq, g_xgq);
    cudaGetSymbolAddress((void**)&pxgd, g_xgd);
    cudaGetSymbolAddress((void**)&pencq,g_encq);
    cudaGetSymbolAddress((void**)&pencd,g_encd);
    cudaGetSymbolAddress((void**)&pc,   g_c);
    cudaGetSymbolAddress((void**)&ppq,  g_pq);
    cudaGetSymbolAddress((void**)&ppdT, g_pdT);
    cudaGetSymbolAddress((void**)&ps3,  g_s3);
    cudaGetSymbolAddress((void**)&ps5,  g_s5);
    cudaGetSymbolAddress((void**)&ps7,  g_s7);
    float *pqb,*pdb;
    cudaGetSymbolAddress((void**)&pqb,  g_qb);
    cudaGetSymbolAddress((void**)&pdb,  g_db);

    cudaFuncSetAttribute(lstm_persist, cudaFuncAttributeMaxDynamicSharedMemorySize, LSTM_SMEM);

    bias_sum_k<<<4,256>>>(qbih,qbhh,dbih,dbhh);

    // embed + proj (tf32):  X = emb[tok] @ projW + projb
    gemm_tf32<true,false,0><<<dim3(3,4),256>>>(emb,bqtok,Ff, projW,Ff, projb, pXq,Ff, NTQ,Ff,Ff);
    gemm_tf32<true,false,0><<<dim3(3,320),256>>>(emb,bdtok,Ff, projW,Ff, projb, pXd,Ff, NTD,Ff,Ff);

    // input gates: xg = X @ Wih^T + (bih+bhh)
    gemm_tf32<false,true,0><<<dim3(8,4),256>>>(pXq,nullptr,Ff, qWih,Ff, pqb, pxgq,G4, NTQ,G4,Ff);
    gemm_tf32<false,true,0><<<dim3(8,320),256>>>(pXd,nullptr,Ff, dWih,Ff, pdb, pxgd,G4, NTD,G4,Ff);

    // persistent LSTMs (query: 8 blocks, doc: 80 blocks; software grid barrier)
    lstm_persist<<<dim3(1,8),256,LSTM_SMEM>>>(pxgq, qWhh, pc, pencq, QLn);
    lstm_persist<<<dim3(10,8),256,LSTM_SMEM>>>(pxgd, dWhh, pc, pencd, DLn);

    // projections: pq [512,50]; pd transposed per image [img][c][dl]
    gemm_tf32<false,false,0><<<dim3(1,4),256>>>(pencq,nullptr,Hh, qpW,Cc, qpb, ppq,Cc, NTQ,Cc,Hh);
    gemm_tf32<false,false,1><<<dim3(1,320),256>>>(pencd,nullptr,Hh, dpW,Cc, dpb, ppdT,0, NTD,Cc,Hh);

    // conv stage 1
    {
        long t3 = (long)Bq*NFc*QLn*3*Cc, t5 = (long)Bq*NFc*QLn*5*Cc, t7 = (long)Bq*NFc*QLn*7*Cc;
        s_k<<<(unsigned)((t3+255)/256),256>>>(c1W, ps3, 3, t3);
        s_k<<<(unsigned)((t5+255)/256),256>>>(c2W, ps5, 5, t5);
        s_k<<<(unsigned)((t7+255)/256),256>>>(c3W, ps7, 7, t7);
    }
    // conv stage 2 (tf32 GEMM + exact-match + relu)
    convgemm_k<3><<<dim3(7,BD),256>>>(ps3, c1W, c1b, bqtok, bdtok, alpha, 0);
    convgemm_k<5><<<dim3(7,BD),256>>>(ps5, c2W, c2b, bqtok, bdtok, alpha, 50);
    convgemm_k<7><<<dim3(7,BD),256>>>(ps7, c3W, c3b, bqtok, bdtok, alpha, 100);

    // 1x1 conv + maxpool + output linear
    score_k<<<BD,256>>>(ccW, ccb, outW, outb, out);
}

// round 5
// speedup vs baseline: 1.5456x; 1.1376x over previous
#include <cuda_runtime.h>
#include <math.h>

// ---------------- problem constants ----------------
#define Bq  32
#define Dn  10
#define QLn 16
#define DLn 128
#define BD  320
#define Ff  300
#define Hh  256
#define G4  1024
#define Cc  50
#define NFc 50
#define MFc 20
#define NTQ (Bq*QLn)      // 512
#define NTD (BD*DLn)      // 40960

// ---------------- device scratch ----------------
__device__ float g_Xq[NTQ*Ff];
__device__ float g_Xd[(size_t)NTD*Ff];
__device__ float g_xgq[(size_t)NTQ*G4];
__device__ float g_xgd[(size_t)NTD*G4];
__device__ float g_encq[NTQ*Hh];
__device__ float g_encd[(size_t)NTD*Hh];
__device__ float g_c[BD*Hh];
__device__ float g_pq[NTQ*Cc];
__device__ float g_pdT[(size_t)BD*Cc*DLn];
__device__ float g_s3[(size_t)Bq*NFc*QLn*3*Cc + 16];
__device__ float g_s5[(size_t)Bq*NFc*QLn*5*Cc + 16];
__device__ float g_s7[(size_t)Bq*NFc*QLn*7*Cc + 16];
__device__ float g_f[(size_t)BD*150*QLn*DLn];
__device__ float g_qb[G4];
__device__ float g_db[G4];
__device__ unsigned g_barcnt = 0;
__device__ unsigned g_bargen = 0;

__device__ __forceinline__ float sigf(float x){ return 1.f/(1.f+expf(-x)); }

__device__ __forceinline__ unsigned f2tf(float x){
    unsigned r; asm("cvt.rna.tf32.f32 %0, %1;" : "=r"(r) : "f"(x)); return r;
}
__device__ __forceinline__ void mma8(float* c, const unsigned* a, const unsigned* b){
    asm volatile("mma.sync.aligned.m16n8k8.row.col.f32.tf32.tf32.f32 "
        "{%0,%1,%2,%3}, {%4,%5,%6,%7}, {%8,%9}, {%0,%1,%2,%3};"
        : "+f"(c[0]),"+f"(c[1]),"+f"(c[2]),"+f"(c[3])
        : "r"(a[0]),"r"(a[1]),"r"(a[2]),"r"(a[3]), "r"(b[0]),"r"(b[1]));
}
__device__ __forceinline__ unsigned sptr(const void* p){
    return (unsigned)__cvta_generic_to_shared(p);
}
__device__ __forceinline__ void cpa16(unsigned dst, const void* src, bool pred){
    int sz = pred ? 16 : 0;
    asm volatile("cp.async.cg.shared.global [%0], [%1], 16, %2;" :: "r"(dst), "l"(src), "r"(sz));
}
#define CP_COMMIT() asm volatile("cp.async.commit_group;")
#define CP_WAIT0()  asm volatile("cp.async.wait_group 0;")

// software grid barrier (all blocks co-resident)
__device__ __forceinline__ void gridbar(int nblocks){
    __syncthreads();
    if (threadIdx.x == 0){
        __threadfence();
        unsigned gen = *((volatile unsigned*)&g_bargen);
        if (atomicAdd(&g_barcnt, 1u) == (unsigned)nblocks - 1u){
            g_barcnt = 0;
            __threadfence();
            atomicAdd(&g_bargen, 1u);
        } else {
            while (*((volatile unsigned*)&g_bargen) == gen) __nanosleep(40);
        }
        __threadfence();
    }
    __syncthreads();
}

// ---------------- bias precombine ----------------
__global__ void bias_sum_k(const float* __restrict__ qb1, const float* __restrict__ qb2,
                           const float* __restrict__ db1, const float* __restrict__ db2)
{
    int t = blockIdx.x*blockDim.x + threadIdx.x;
    if (t < G4){ g_qb[t] = qb1[t]+qb2[t]; g_db[t] = db1[t]+db2[t]; }
}

// ---------------- pipelined tf32 GEMM: 128x128 tile, cp.async, 2 blocks/SM ----
// C[M,N] = A(gathered)[M,K] * B + bias.  BT: B is [N,K].
// BASYNC: B loaded via cp.async (requires 16B-aligned rows); else register-staged.
// STORE 0: C[m*ldc+n].  STORE 1: pdT: img=m>>7 -> C[(img*50+n)*128 + (m&127)]
template<bool GATHER, bool BT, bool BASYNC, int STORE>
__global__ __launch_bounds__(256,2) void gemm_tf32(
    const float* __restrict__ A, const int* __restrict__ idx, int lda,
    const float* __restrict__ Bm, int ldb, const float* __restrict__ bias,
    float* __restrict__ C, int ldc, int M, int N, int K)
{
    __shared__ float As[2][128][20];    // [m][k] rows, 80B stride (16B-aligned)
    __shared__ float Bsr[2][2560];      // BT: [n*20+k]; !BT: [k*132+n]
    int tid = threadIdx.x;
    int lane = tid & 31, warp = tid >> 5;
    int wm = warp >> 2, wn = warp & 3;
    int m0 = blockIdx.y*128, n0 = blockIdx.x*128;
    int nk = (K + 15) >> 4;
    int r8 = lane>>2, q4 = lane&3;

    // A row assignment for cp.async
    int arow = tid >> 1;
    int acp  = (tid & 1) * 8;           // float offset 0 or 8 (two 16B chunks)
    bool mrowok = (m0 + arow) < M;
    const float* Arow;
    { long r = GATHER ? (long)idx[m0 + (mrowok ? arow : 0)] : (long)(m0 + (mrowok ? arow : 0));
      Arow = A + r*(long)lda; }

    auto asyncA = [&](int kt, int buf){
        int k0 = kt*16;
        const float* src = Arow + k0 + acp;
        unsigned d = sptr(&As[buf][arow][acp]);
        cpa16(d,      src,     mrowok && (k0+acp)   < K);
        cpa16(d+16,   src+4,   mrowok && (k0+acp+4) < K);
    };
    // BT async rows
    bool nrowok = (n0 + arow) < N;
    const float* Brow = Bm + (size_t)(n0 + (nrowok ? arow : 0))*(BT ? ldb : 0);
    auto asyncB_T = [&](int kt, int buf){
        int k0 = kt*16;
        const float* src = Brow + k0 + acp;
        unsigned d = sptr(&Bsr[buf][arow*20 + acp]);
        cpa16(d,    src,   nrowok && (k0+acp)   < K);
        cpa16(d+16, src+4, nrowok && (k0+acp+4) < K);
    };
    // !BT async: 16 k-rows x 128 n
    int bkr = tid >> 4, bnf = (tid & 15)*8;
    auto asyncB_N = [&](int kt, int buf){
        int k0 = kt*16;
        const float* src = Bm + (size_t)(k0+bkr)*ldb + n0 + bnf;
        unsigned d = sptr(&Bsr[buf][bkr*132 + bnf]);
        bool kok = (k0+bkr) < K;
        cpa16(d,    src,   kok && (n0+bnf)   < N);
        cpa16(d+16, src+4, kok && (n0+bnf+4) < N);
    };
    // !BASYNC register B (only !BT used): nc/kr mapping
    float bv[8];
    int nc = (tid&31)*4, kr = tid>>5;
    auto ldgB = [&](int kt){
        int k0 = kt*16;
        #pragma unroll
        for (int h=0;h<2;h++){
            int kk = k0 + kr + h*8;
            #pragma unroll
            for (int j=0;j<4;j++){
                int n = n0 + nc + j;
                bv[h*4+j] = (kk < K && n < N) ? Bm[(size_t)kk*ldb + n] : 0.f;
            }
        }
    };
    auto stsB = [&](int buf){
        #pragma unroll
        for (int h=0;h<2;h++)
            #pragma unroll
            for (int j=0;j<4;j++) Bsr[buf][(kr+h*8)*132 + nc+j] = bv[h*4+j];
    };

    float acc[4][4][4] = {};

    asyncA(0,0);
    if (BASYNC){ if (BT) asyncB_T(0,0); else asyncB_N(0,0); }
    CP_COMMIT();
    if (!BASYNC) ldgB(0);
    CP_WAIT0();
    if (!BASYNC) stsB(0);
    __syncthreads();

    for (int kt = 0; kt < nk; kt++){
        int p = kt & 1;
        bool more = (kt+1 < nk);
        if (more){
            asyncA(kt+1, p^1);
            if (BASYNC){ if (BT) asyncB_T(kt+1, p^1); else asyncB_N(kt+1, p^1); }
            CP_COMMIT();
            if (!BASYNC) ldgB(kt+1);
        }
        #pragma unroll
        for (int kb=0; kb<2; kb++){
            int ko = kb*8;
            unsigned af[4][4], bf[4][2];
            #pragma unroll
            for (int mt=0; mt<4; mt++){
                int rb = wm*64 + mt*16;
                af[mt][0] = __float_as_uint(As[p][rb+r8  ][ko+q4  ]);
                af[mt][1] = __float_as_uint(As[p][rb+r8+8][ko+q4  ]);
                af[mt][2] = __float_as_uint(As[p][rb+r8  ][ko+q4+4]);
                af[mt][3] = __float_as_uint(As[p][rb+r8+8][ko+q4+4]);
            }
            #pragma unroll
            for (int nt=0; nt<4; nt++){
                int nb = wn*32 + nt*8;
                if (BT){
                    bf[nt][0] = __float_as_uint(Bsr[p][(nb+r8)*20 + ko+q4  ]);
                    bf[nt][1] = __float_as_uint(Bsr[p][(nb+r8)*20 + ko+q4+4]);
                } else {
                    bf[nt][0] = __float_as_uint(Bsr[p][(ko+q4  )*132 + nb+r8]);
                    bf[nt][1] = __float_as_uint(Bsr[p][(ko+q4+4)*132 + nb+r8]);
                }
            }
            #pragma unroll
            for (int mt=0;mt<4;mt++)
                #pragma unroll
                for (int nt=0;nt<4;nt++)
                    mma8(acc[mt][nt], af[mt], bf[nt]);
        }
        __syncthreads();
        if (more){
            if (!BASYNC) stsB(p^1);
            CP_WAIT0();
            __syncthreads();
        }
    }

    #pragma unroll
    for (int mt=0;mt<4;mt++){
        int row = m0 + wm*64 + mt*16 + r8;
        #pragma unroll
        for (int nt=0;nt<4;nt++){
            int col = n0 + wn*32 + nt*8 + q4*2;
            const float* cc = acc[mt][nt];
            #pragma unroll
            for (int j=0;j<2;j++){
                int n = col + j;
                if (n >= N) continue;
                float bb = bias ? bias[n] : 0.f;
                float v0 = cc[j] + bb, v1 = cc[2+j] + bb;
                if (STORE == 0){
                    if (row < M)   C[(size_t)row*ldc + n] = v0;
                    if (row+8 < M) C[(size_t)(row+8)*ldc + n] = v1;
                } else {
                    int img = row >> 7;
                    C[((size_t)img*Cc + n)*DLn + (row & 127)] = v0;
                    C[((size_t)img*Cc + n)*DLn + ((row+8) & 127)] = v1;
                }
            }
        }
    }
}

// ---------------- persistent LSTM ----------------
#define LSTM_SMEM ((256*136 + 256*40)*4)
__global__ __launch_bounds__(256,1) void lstm_persist(
    const float* __restrict__ xg, const float* __restrict__ Whh,
    float* __restrict__ cst, float* __restrict__ enc, int T)
{
    extern __shared__ unsigned smbuf[];
    unsigned* Bs = smbuf;                  // [256][136] tf32 Whh slice
    unsigned* As = smbuf + 256*136;        // [256][40]  tf32 h_prev
    float* Gs = (float*)As;                // [32][136]  overlay: gate preacts
    int tid = threadIdx.x;
    int lane = tid & 31, warp = tid >> 5;
    int r8 = lane >> 2, q4 = lane & 3;
    int wm = warp & 1, wn = warp >> 1;
    int n0 = blockIdx.x * 32;
    int h0 = blockIdx.y * 32;
    int nblocks = gridDim.x * gridDim.y;

    for (int idx = tid; idx < 128*256; idx += 256){
        int j = idx >> 8, k = idx & 255;
        int r = ((j & 3) << 8) + h0 + (j >> 2);
        Bs[k*136 + j] = __float_as_uint(Whh[(size_t)r*Hh + k]);
    }
    __syncthreads();

    for (int t = 0; t < T; t++){
        if (t == 0){
            for (int idx = tid; idx < 32*256; idx += 256)
                As[(idx & 255)*40 + (idx >> 8)] = 0u;
        } else {
            for (int idx = tid; idx < 32*256; idx += 256){
                int m = idx >> 8, k = idx & 255;
                As[k*40 + m] = __float_as_uint(enc[((size_t)(n0+m)*T + (t-1))*Hh + k]);
            }
        }
        __syncthreads();

        float acc[4][4] = {};
        int rb = wm*16;
        #pragma unroll 4
        for (int ko = 0; ko < 256; ko += 8){
            unsigned af[4];
            af[0] = As[(ko+q4)*40 + rb + r8];
            af[1] = As[(ko+q4)*40 + rb + r8 + 8];
            af[2] = As[(ko+q4+4)*40 + rb + r8];
            af[3] = As[(ko+q4+4)*40 + rb + r8 + 8];
            #pragma unroll
            for (int nt = 0; nt < 4; nt++){
                int nb = wn*32 + nt*8;
                unsigned bf[2];
                bf[0] = Bs[(ko+q4)*136 + nb + r8];
                bf[1] = Bs[(ko+q4+4)*136 + nb + r8];
                mma8(acc[nt], af, bf);
            }
        }
        __syncthreads();
        #pragma unroll
        for (int nt = 0; nt < 4; nt++){
            int col = wn*32 + nt*8 + q4*2;
            Gs[(rb+r8)*136 + col]     = acc[nt][0];
            Gs[(rb+r8)*136 + col+1]   = acc[nt][1];
            Gs[(rb+r8+8)*136 + col]   = acc[nt][2];
            Gs[(rb+r8+8)*136 + col+1] = acc[nt][3];
        }
        __syncthreads();

        #pragma unroll
        for (int it = 0; it < 4; it++){
            int id = tid + it*256;
            int m = id >> 5, hp = id & 31;
            int n = n0 + m, h = h0 + hp;
            size_t tok = (size_t)n*T + t;
            const float* xb = xg + tok*(size_t)G4;
            float4 g = *(const float4*)&Gs[m*136 + hp*4];
            float gi = g.x + xb[h];
            float gf = g.y + xb[Hh + h];
            float gg = g.z + xb[2*Hh + h];
            float go = g.w + xb[3*Hh + h];
            float cp = (t == 0) ? 0.f : cst[(size_t)n*Hh + h];
            float cv = sigf(gf)*cp + sigf(gi)*tanhf(gg);
            cst[(size_t)n*Hh + h] = cv;
            enc[tok*Hh + h] = sigf(go)*tanhf(cv);
        }
        gridbar(nblocks);
    }
}

// ---------------- conv stage 1 ----------------
__global__ void s_k(const float* __restrict__ cW, float* __restrict__ s, int KW, long total)
{
    long i = (long)blockIdx.x*blockDim.x + threadIdx.x;
    if (i >= total) return;
    int c  = (int)(i % Cc);
    long r = i / Cc;
    int dd = (int)(r % KW); r /= KW;
    int q  = (int)(r % QLn); r /= QLn;
    int o  = (int)(r % NFc);
    int b  = (int)(r / NFc);
    float v = 0.f;
    #pragma unroll
    for (int dq = 0; dq < 3; dq++){
        int qq = q + dq - 1;
        if (qq >= 0 && qq < QLn)
            v += cW[(((size_t)o*51 + c)*3 + dq)*KW + dd] * g_pq[((size_t)b*QLn + qq)*Cc + c];
    }
    s[i] = v;
}

// ---------------- conv stage 2: tf32 mma GEMM + EM epilogue + relu ----------------
template<int KW>
__global__ __launch_bounds__(256,1) void convgemm_k(
    const float* __restrict__ sA, const float* __restrict__ cW,
    const float* __restrict__ cb, const int* __restrict__ bqtok,
    const int* __restrict__ bdtok, const float* __restrict__ alpha, int OCB)
{
    const int K = Cc*KW, PW = KW/2;
    __shared__ unsigned As[2][16][132];
    __shared__ unsigned Bs[2][16][132];
    __shared__ float ems[18][136];
    __shared__ float wem[8][3*KW];
    __shared__ int qt[16], dt[128], s_any;
    int tid = threadIdx.x;
    int lane = tid & 31, warp = tid >> 5;
    int wm = warp >> 2, wn = warp & 3;
    int img = blockIdx.y, b = img / Dn;
    int m0 = blockIdx.x*128, obase = m0 >> 4;
    int nk = (K + 15) >> 4;

    if (tid == 0) s_any = 0;
    if (tid < 16) qt[tid] = bqtok[b*QLn + tid];
    if (tid < 128) dt[tid] = bdtok[(size_t)img*DLn + tid];
    if (tid < 8*3*KW){
        int ol = tid/(3*KW), rr = tid%(3*KW);
        int o = obase + ol;
        wem[ol][rr] = (o < NFc) ? cW[(((size_t)o*51 + 50)*3 + rr/KW)*KW + rr%KW] : 0.f;
    }
    __syncthreads();
    float al = alpha[0];
    for (int e = tid; e < 18*136; e += 256){
        int qi = e/136, dj = e%136;
        int q = qi-1, dl = dj-3;
        float v = 0.f;
        if (q >= 0 && q < QLn && dl >= 0 && dl < DLn && qt[q] == dt[dl]){ v = al; s_any = 1; }
        ems[qi][dj] = v;
    }

    const float* Ab = sA + (size_t)b*800*K;
    const float* Pd = &g_pdT[(size_t)img*Cc*DLn];
    int ar = tid >> 1, ak = (tid & 1)*8;
    bool mok = (m0 + ar) < 800;
    const float* Aptr = Ab + (size_t)(mok ? (m0+ar) : 0)*K + ak;

    float av[8], bv[8];
    auto ldg = [&](int kt){
        int k0 = kt*16;
        #pragma unroll
        for (int i=0;i<8;i++){
            int kk = k0 + ak + i;
            av[i] = (mok && kk < K) ? Aptr[k0+i] : 0.f;
        }
        int nc = (tid&31)*4, kr = tid>>5;
        #pragma unroll
        for (int h=0;h<2;h++){
            int kk = k0 + kr + h*8;
            int dd = kk/Cc, c = kk - dd*Cc;
            #pragma unroll
            for (int j=0;j<4;j++){
                int sdl = nc + j + dd - PW;
                bv[h*4+j] = (kk < K && sdl >= 0 && sdl < DLn) ? Pd[(size_t)c*DLn + sdl] : 0.f;
            }
        }
    };
    auto sts = [&](int buf){
        #pragma unroll
        for (int i=0;i<8;i++) As[buf][ak+i][ar] = __float_as_uint(av[i]);
        int nc = (tid&31)*4, kr = tid>>5;
        #pragma unroll
        for (int h=0;h<2;h++)
            #pragma unroll
            for (int j=0;j<4;j++) Bs[buf][kr+h*8][nc+j] = __float_as_uint(bv[h*4+j]);
    };

    float acc[4][4][4] = {};
    int r8 = lane>>2, q4 = lane&3;
    __syncthreads();
    ldg(0); sts(0); __syncthreads();
    for (int kt = 0; kt < nk; kt++){
        int p = kt & 1;
        if (kt+1 < nk) ldg(kt+1);
        #pragma unroll
        for (int kb=0; kb<2; kb++){
            int ko = kb*8;
            unsigned af[4][4], bf[4][2];
            #pragma unroll
            for (int mt=0; mt<4; mt++){
                int rb = wm*64 + mt*16;
                af[mt][0] = As[p][ko+q4  ][rb+r8];
                af[mt][1] = As[p][ko+q4  ][rb+r8+8];
                af[mt][2] = As[p][ko+q4+4][rb+r8];
                af[mt][3] = As[p][ko+q4+4][rb+r8+8];
            }
            #pragma unroll
            for (int nt=0; nt<4; nt++){
                int nb = wn*32 + nt*8;
                bf[nt][0] = Bs[p][ko+q4  ][nb+r8];
                bf[nt][1] = Bs[p][ko+q4+4][nb+r8];
            }
            #pragma unroll
            for (int mt=0;mt<4;mt++)
                #pragma unroll
                for (int nt=0;nt<4;nt++)
                    mma8(acc[mt][nt], af[mt], bf[nt]);
        }
        if (kt+1 < nk) sts(p^1);
        __syncthreads();
    }

    int any = s_any;
    #pragma unroll
    for (int mt=0;mt<4;mt++){
        int row = m0 + wm*64 + mt*16;
        if (row >= 800) continue;
        int o = row >> 4, ol = o - obase;
        float bias = cb[o];
        #pragma unroll
        for (int rr=0; rr<2; rr++){
            int q = r8 + rr*8;
            #pragma unroll
            for (int nt=0;nt<4;nt++){
                int col = wn*32 + nt*8 + q4*2;
                #pragma unroll
                for (int j=0;j<2;j++){
                    int dl = col + j;
                    float v = acc[mt][nt][rr*2 + j] + bias;
                    if (any){
                        #pragma unroll
                        for (int dq = 0; dq < 3; dq++)
                            #pragma unroll
                            for (int dd = 0; dd < KW; dd++)
                                v += wem[ol][dq*KW+dd] * ems[q+dq][dl+dd+3-PW];
                    }
                    v = fmaxf(v, 0.f);
                    g_f[(((size_t)img*150 + OCB + o)*QLn + q)*DLn + dl] = v;
                }
            }
        }
    }
}

// ---------------- 1x1 conv + global maxpool + linear ----------------
__global__ __launch_bounds__(256) void score_k(
    const float* __restrict__ ccW, const float* __restrict__ ccb,
    const float* __restrict__ outW, const float* __restrict__ outb,
    float* __restrict__ out)
{
    __shared__ float w[MFc][152];
    __shared__ float red[8][MFc];
    int img = blockIdx.x, tid = threadIdx.x;
    for (int e = tid; e < MFc*150; e += 256) w[e/150][e%150] = ccW[e];
    __syncthreads();
    float mx[MFc];
    #pragma unroll
    for (int mf = 0; mf < MFc; mf++) mx[mf] = -1e30f;
    const float* fb = &g_f[(size_t)img*150*QLn*DLn];
    for (int p = tid; p < QLn*DLn; p += 256){
        float acc[MFc];
        #pragma unroll
        for (int mf = 0; mf < MFc; mf++) acc[mf] = ccb[mf];
        for (int nf = 0; nf < 150; nf++){
            float v = fb[(size_t)nf*QLn*DLn + p];
            #pragma unroll
            for (int mf = 0; mf < MFc; mf++) acc[mf] += v*w[mf][nf];
        }
        #pragma unroll
        for (int mf = 0; mf < MFc; mf++) mx[mf] = fmaxf(mx[mf], acc[mf]);
    }
    #pragma unroll
    for (int off = 16; off; off >>= 1)
        #pragma unroll
        for (int mf = 0; mf < MFc; mf++)
            mx[mf] = fmaxf(mx[mf], __shfl_xor_sync(0xFFFFFFFFu, mx[mf], off));
    if ((tid & 31) == 0)
        #pragma unroll
        for (int mf = 0; mf < MFc; mf++) red[tid>>5][mf] = mx[mf];
    __syncthreads();
    if (tid == 0){
        float sc = outb[0];
        #pragma unroll
        for (int mf = 0; mf < MFc; mf++){
            float m = red[0][mf];
            #pragma unroll
            for (int wp = 1; wp < 8; wp++) m = fmaxf(m, red[wp][mf]);
            sc += m*outW[mf];
        }
        out[img] = sc;
    }
}

// ---------------- launch ----------------
extern "C" void kernel_launch(void* const* d_in, const int* in_sizes, int n_in,
                              void* d_out, int out_size)
{
    const int* bqtok = nullptr; const int* bdtok = nullptr;
    for (int i = 0; i < 4; i++){
        if (in_sizes[i] == NTQ)      bqtok = (const int*)d_in[i];
        else if (in_sizes[i] == NTD) bdtok = (const int*)d_in[i];
    }
    const float* emb    = (const float*)d_in[4];
    const float* projW  = (const float*)d_in[5];
    const float* projb  = (const float*)d_in[6];
    const float* qWih   = (const float*)d_in[7];
    const float* qWhh   = (const float*)d_in[8];
    const float* qbih   = (const float*)d_in[9];
    const float* qbhh   = (const float*)d_in[10];
    const float* dWih   = (const float*)d_in[11];
    const float* dWhh   = (const float*)d_in[12];
    const float* dbih   = (const float*)d_in[13];
    const float* dbhh   = (const float*)d_in[14];
    const float* qpW    = (const float*)d_in[15];
    const float* qpb    = (const float*)d_in[16];
    const float* dpW    = (const float*)d_in[17];
    const float* dpb    = (const float*)d_in[18];
    const float* alpha  = (const float*)d_in[19];
    const float* c1W    = (const float*)d_in[20];
    const float* c1b    = (const float*)d_in[21];
    const float* c2W    = (const float*)d_in[22];
    const float* c2b    = (const float*)d_in[23];
    const float* c3W    = (const float*)d_in[24];
    const float* c3b    = (const float*)d_in[25];
    const float* ccW    = (const float*)d_in[26];
    const float* ccb    = (const float*)d_in[27];
    const float* outW   = (const float*)d_in[28];
    const float* outb   = (const float*)d_in[29];
    float* out = (float*)d_out;

    float *pXq,*pXd,*pxgq,*pxgd,*pencq,*pencd,*pc,*ppq,*ppdT,*ps3,*ps5,*ps7;
    cudaGetSymbolAddress((void**)&pXq,  g_Xq);
    cudaGetSymbolAddress((void**)&pXd,  g_Xd);
    cudaGetSymbolAddress((void**)&pxgq, g_xgq);
    cudaGetSymbolAddress((void**)&pxgd, g_xgd);
    cudaGetSymbolAddress((void**)&pencq,g_encq);
    cudaGetSymbolAddress((void**)&pencd,g_encd);
    cudaGetSymbolAddress((void**)&pc,   g_c);
    cudaGetSymbolAddress((void**)&ppq,  g_pq);
    cudaGetSymbolAddress((void**)&ppdT, g_pdT);
    cudaGetSymbolAddress((void**)&ps3,  g_s3);
    cudaGetSymbolAddress((void**)&ps5,  g_s5);
    cudaGetSymbolAddress((void**)&ps7,  g_s7);
    float *pqb,*pdb;
    cudaGetSymbolAddress((void**)&pqb,  g_qb);
    cudaGetSymbolAddress((void**)&pdb,  g_db);

    cudaFuncSetAttribute(lstm_persist, cudaFuncAttributeMaxDynamicSharedMemorySize, LSTM_SMEM);

    bias_sum_k<<<4,256>>>(qbih,qbhh,dbih,dbhh);

    // embed + proj (tf32):  X = emb[tok] @ projW + projb
    gemm_tf32<true,false,true,0><<<dim3(3,4),256>>>(emb,bqtok,Ff, projW,Ff, projb, pXq,Ff, NTQ,Ff,Ff);
    gemm_tf32<true,false,true,0><<<dim3(3,320),256>>>(emb,bdtok,Ff, projW,Ff, projb, pXd,Ff, NTD,Ff,Ff);

    // input gates: xg = X @ Wih^T + (bih+bhh)
    gemm_tf32<false,true,true,0><<<dim3(8,4),256>>>(pXq,nullptr,Ff, qWih,Ff, pqb, pxgq,G4, NTQ,G4,Ff);
    gemm_tf32<false,true,true,0><<<dim3(8,320),256>>>(pXd,nullptr,Ff, dWih,Ff, pdb, pxgd,G4, NTD,G4,Ff);

    // persistent LSTMs
    lstm_persist<<<dim3(1,8),256,LSTM_SMEM>>>(pxgq, qWhh, pc, pencq, QLn);
    lstm_persist<<<dim3(10,8),256,LSTM_SMEM>>>(pxgd, dWhh, pc, pencd, DLn);

    // projections: pq [512,50]; pd transposed per image [img][c][dl]
    gemm_tf32<false,false,false,0><<<dim3(1,4),256>>>(pencq,nullptr,Hh, qpW,Cc, qpb, ppq,Cc, NTQ,Cc,Hh);
    gemm_tf32<false,false,false,1><<<dim3(1,320),256>>>(pencd,nullptr,Hh, dpW,Cc, dpb, ppdT,0, NTD,Cc,Hh);

    // conv stage 1
    {
        long t3 = (long)Bq*NFc*QLn*3*Cc, t5 = (long)Bq*NFc*QLn*5*Cc, t7 = (long)Bq*NFc*QLn*7*Cc;
        s_k<<<(unsigned)((t3+255)/256),256>>>(c1W, ps3, 3, t3);
        s_k<<<(unsigned)((t5+255)/256),256>>>(c2W, ps5, 5, t5);
        s_k<<<(unsigned)((t7+255)/256),256>>>(c3W, ps7, 7, t7);
    }
    // conv stage 2 (tf32 GEMM + exact-match + relu)
    convgemm_k<3><<<dim3(7,BD),256>>>(ps3, c1W, c1b, bqtok, bdtok, alpha, 0);
    convgemm_k<5><<<dim3(7,BD),256>>>(ps5, c2W, c2b, bqtok, bdtok, alpha, 50);
    convgemm_k<7><<<dim3(7,BD),256>>>(ps7, c3W, c3b, bqtok, bdtok, alpha, 100);

    // 1x1 conv + maxpool + output linear
    score_k<<<BD,256>>>(ccW, ccb, outW, outb, out);
}

// round 6
// speedup vs baseline: 1.8050x; 1.1678x over previous
#include <cuda_runtime.h>
#include <math.h>

// ---------------- problem constants ----------------
#define Bq  32
#define Dn  10
#define QLn 16
#define DLn 128
#define BD  320
#define Ff  300
#define Hh  256
#define G4  1024
#define Cc  50
#define NFc 50
#define MFc 20
#define NTQ (Bq*QLn)      // 512
#define NTD (BD*DLn)      // 40960

// ---------------- device scratch ----------------
__device__ float g_Xq[NTQ*Ff];
__device__ float g_Xd[(size_t)NTD*Ff];
__device__ float g_xgq[(size_t)NTQ*G4];
__device__ float g_xgd[(size_t)NTD*G4];
__device__ float g_encq[NTQ*Hh];
__device__ float g_encd[(size_t)NTD*Hh];
__device__ float g_c[BD*Hh];
__device__ float g_pq[NTQ*Cc];
__device__ float g_pdT[(size_t)BD*Cc*DLn];
__device__ float g_s3[(size_t)Bq*NFc*QLn*152 + 16];
__device__ float g_s5[(size_t)Bq*NFc*QLn*252 + 16];
__device__ float g_s7[(size_t)Bq*NFc*QLn*352 + 16];
__device__ float g_f[(size_t)BD*150*QLn*DLn];
__device__ float g_qb[G4];
__device__ float g_db[G4];
__device__ unsigned g_barcnt = 0;
__device__ unsigned g_bargen = 0;

__device__ __forceinline__ float sigf(float x){ return 1.f/(1.f+expf(-x)); }

__device__ __forceinline__ void mma8(float* c, const unsigned* a, const unsigned* b){
    asm volatile("mma.sync.aligned.m16n8k8.row.col.f32.tf32.tf32.f32 "
        "{%0,%1,%2,%3}, {%4,%5,%6,%7}, {%8,%9}, {%0,%1,%2,%3};"
        : "+f"(c[0]),"+f"(c[1]),"+f"(c[2]),"+f"(c[3])
        : "r"(a[0]),"r"(a[1]),"r"(a[2]),"r"(a[3]), "r"(b[0]),"r"(b[1]));
}
__device__ __forceinline__ unsigned sptr(const void* p){
    return (unsigned)__cvta_generic_to_shared(p);
}
__device__ __forceinline__ void cpa16(unsigned dst, const void* src, bool pred){
    int sz = pred ? 16 : 0;
    asm volatile("cp.async.cg.shared.global [%0], [%1], 16, %2;" :: "r"(dst), "l"(src), "r"(sz));
}
#define CP_COMMIT() asm volatile("cp.async.commit_group;")
#define CP_WAIT0()  asm volatile("cp.async.wait_group 0;")
#define CP_WAIT1()  asm volatile("cp.async.wait_group 1;")

// software grid barrier (all blocks co-resident)
__device__ __forceinline__ void gridbar(int nblocks){
    __syncthreads();
    if (threadIdx.x == 0){
        __threadfence();
        unsigned gen = *((volatile unsigned*)&g_bargen);
        if (atomicAdd(&g_barcnt, 1u) == (unsigned)nblocks - 1u){
            g_barcnt = 0;
            __threadfence();
            atomicAdd(&g_bargen, 1u);
        } else {
            while (*((volatile unsigned*)&g_bargen) == gen) __nanosleep(40);
        }
        __threadfence();
    }
    __syncthreads();
}

// ---------------- bias precombine ----------------
__global__ void bias_sum_k(const float* __restrict__ qb1, const float* __restrict__ qb2,
                           const float* __restrict__ db1, const float* __restrict__ db2)
{
    int t = blockIdx.x*blockDim.x + threadIdx.x;
    if (t < G4){ g_qb[t] = qb1[t]+qb2[t]; g_db[t] = db1[t]+db2[t]; }
}

// ---------------- 3-stage pipelined tf32 GEMM: 128x128 tile ----------------
// C[M,N] = A(gathered)[M,K] * B + bias.  BT: B is [N,K].
// BASYNC: B via cp.async (16B-aligned rows); else register-staged (prefetched).
// STORE 0: C[m*ldc+n].  STORE 1: pdT: img=m>>7 -> C[(img*50+n)*128 + (m&127)]
#define GEMM_DSM (6*2560*4)
template<bool GATHER, bool BT, bool BASYNC, int STORE>
__global__ __launch_bounds__(256,2) void gemm_tf32(
    const float* __restrict__ A, const int* __restrict__ idx, int lda,
    const float* __restrict__ Bm, int ldb, const float* __restrict__ bias,
    float* __restrict__ C, int ldc, int M, int N, int K)
{
    extern __shared__ float dsm[];
    float* Asm = dsm;            // 3 stages x [128][20]
    float* Bsm = dsm + 3*2560;   // 3 stages x 2560 (BT: [n*20+k]; !BT: [k*132+n])
    int tid = threadIdx.x;
    int lane = tid & 31, warp = tid >> 5;
    int wm = warp >> 2, wn = warp & 3;
    int m0 = blockIdx.y*128, n0 = blockIdx.x*128;
    int nk = (K + 15) >> 4;
    int r8 = lane>>2, q4 = lane&3;

    int arow = tid >> 1;
    int acp  = (tid & 1) * 8;
    bool mrowok = (m0 + arow) < M;
    const float* Arow;
    { long r = GATHER ? (long)idx[m0 + (mrowok ? arow : 0)] : (long)(m0 + (mrowok ? arow : 0));
      Arow = A + r*(long)lda; }

    bool nrowok = (n0 + arow) < N;
    const float* Brow = Bm + (size_t)(n0 + (nrowok ? arow : 0))*(BT ? ldb : 0);
    int bkr = tid >> 4, bnf = (tid & 15)*8;

    auto issue = [&](int kt, int buf){
        int k0 = kt*16;
        unsigned d = sptr(Asm + buf*2560 + arow*20 + acp);
        cpa16(d,    Arow + k0 + acp,     mrowok && (k0+acp)   < K);
        cpa16(d+16, Arow + k0 + acp + 4, mrowok && (k0+acp+4) < K);
        if (BASYNC){
            if (BT){
                unsigned db = sptr(Bsm + buf*2560 + arow*20 + acp);
                cpa16(db,    Brow + k0 + acp,     nrowok && (k0+acp)   < K);
                cpa16(db+16, Brow + k0 + acp + 4, nrowok && (k0+acp+4) < K);
            } else {
                const float* src = Bm + (size_t)(k0+bkr)*ldb + n0 + bnf;
                unsigned db = sptr(Bsm + buf*2560 + bkr*132 + bnf);
                bool kok = (k0+bkr) < K;
                cpa16(db,    src,   kok && (n0+bnf)   < N);
                cpa16(db+16, src+4, kok && (n0+bnf+4) < N);
            }
        }
        CP_COMMIT();
    };

    // !BASYNC register-staged B
    float bv[8];
    int nc = (tid&31)*4, kr = tid>>5;
    auto ldgB = [&](int kt){
        int k0 = kt*16;
        #pragma unroll
        for (int h=0;h<2;h++){
            int kk = k0 + kr + h*8;
            #pragma unroll
            for (int j=0;j<4;j++){
                int n = n0 + nc + j;
                bv[h*4+j] = (kk < K && n < N) ? Bm[(size_t)kk*ldb + n] : 0.f;
            }
        }
    };
    auto stsB = [&](int buf){
        #pragma unroll
        for (int h=0;h<2;h++)
            #pragma unroll
            for (int j=0;j<4;j++) Bsm[buf*2560 + (kr+h*8)*132 + nc+j] = bv[h*4+j];
    };

    float acc[4][4][4] = {};

    issue(0,0);
    if (nk > 1) issue(1,1);
    if (!BASYNC) ldgB(0);

    int buf = 0;
    for (int kt = 0; kt < nk; kt++){
        if (kt >= nk-1) CP_WAIT0(); else CP_WAIT1();
        __syncthreads();
        if (!BASYNC) stsB(buf);
        if (kt+2 < nk) issue(kt+2, buf == 0 ? 2 : buf-1);
        if (!BASYNC){
            if (kt+1 < nk) ldgB(kt+1);
            __syncthreads();
        }
        const float* Ab2 = Asm + buf*2560;
        const float* Bb2 = Bsm + buf*2560;
        #pragma unroll
        for (int kb=0; kb<2; kb++){
            int ko = kb*8;
            unsigned af[4][4], bf[4][2];
            #pragma unroll
            for (int mt=0; mt<4; mt++){
                int rb = wm*64 + mt*16;
                af[mt][0] = __float_as_uint(Ab2[(rb+r8  )*20 + ko+q4  ]);
                af[mt][1] = __float_as_uint(Ab2[(rb+r8+8)*20 + ko+q4  ]);
                af[mt][2] = __float_as_uint(Ab2[(rb+r8  )*20 + ko+q4+4]);
                af[mt][3] = __float_as_uint(Ab2[(rb+r8+8)*20 + ko+q4+4]);
            }
            #pragma unroll
            for (int nt=0; nt<4; nt++){
                int nb = wn*32 + nt*8;
                if (BT){
                    bf[nt][0] = __float_as_uint(Bb2[(nb+r8)*20 + ko+q4  ]);
                    bf[nt][1] = __float_as_uint(Bb2[(nb+r8)*20 + ko+q4+4]);
                } else {
                    bf[nt][0] = __float_as_uint(Bb2[(ko+q4  )*132 + nb+r8]);
                    bf[nt][1] = __float_as_uint(Bb2[(ko+q4+4)*132 + nb+r8]);
                }
            }
            #pragma unroll
            for (int mt=0;mt<4;mt++)
                #pragma unroll
                for (int nt=0;nt<4;nt++)
                    mma8(acc[mt][nt], af[mt], bf[nt]);
        }
        buf = (buf == 2) ? 0 : buf+1;
    }

    #pragma unroll
    for (int mt=0;mt<4;mt++){
        int row = m0 + wm*64 + mt*16 + r8;
        #pragma unroll
        for (int nt=0;nt<4;nt++){
            int col = n0 + wn*32 + nt*8 + q4*2;
            const float* cc = acc[mt][nt];
            #pragma unroll
            for (int j=0;j<2;j++){
                int n = col + j;
                if (n >= N) continue;
                float bb = bias ? bias[n] : 0.f;
                float v0 = cc[j] + bb, v1 = cc[2+j] + bb;
                if (STORE == 0){
                    if (row < M)   C[(size_t)row*ldc + n] = v0;
                    if (row+8 < M) C[(size_t)(row+8)*ldc + n] = v1;
                } else {
                    int img = row >> 7;
                    C[((size_t)img*Cc + n)*DLn + (row & 127)] = v0;
                    C[((size_t)img*Cc + n)*DLn + ((row+8) & 127)] = v1;
                }
            }
        }
    }
}

// ---------------- persistent LSTM ----------------
#define LSTM_SMEM ((256*136 + 256*40)*4)
__global__ __launch_bounds__(256,1) void lstm_persist(
    const float* __restrict__ xg, const float* __restrict__ Whh,
    float* __restrict__ cst, float* __restrict__ enc, int T)
{
    extern __shared__ unsigned smbuf[];
    unsigned* Bs = smbuf;                  // [256][136] tf32 Whh slice
    unsigned* As = smbuf + 256*136;        // [256][40]  h_prev
    float* Gs = (float*)As;                // [32][136]  overlay: gate preacts
    int tid = threadIdx.x;
    int lane = tid & 31, warp = tid >> 5;
    int r8 = lane >> 2, q4 = lane & 3;
    int wm = warp & 1, wn = warp >> 1;
    int n0 = blockIdx.x * 32;
    int h0 = blockIdx.y * 32;
    int nblocks = gridDim.x * gridDim.y;

    for (int idx = tid; idx < 128*256; idx += 256){
        int j = idx >> 8, k = idx & 255;
        int r = ((j & 3) << 8) + h0 + (j >> 2);
        Bs[k*136 + j] = __float_as_uint(Whh[(size_t)r*Hh + k]);
    }
    __syncthreads();

    for (int t = 0; t < T; t++){
        if (t == 0){
            for (int idx = tid; idx < 32*256; idx += 256)
                As[(idx & 255)*40 + (idx >> 8)] = 0u;
        } else {
            for (int idx = tid; idx < 32*256; idx += 256){
                int m = idx >> 8, k = idx & 255;
                As[k*40 + m] = __float_as_uint(enc[((size_t)(n0+m)*T + (t-1))*Hh + k]);
            }
        }
        __syncthreads();

        float acc[4][4] = {};
        int rb = wm*16;
        #pragma unroll 4
        for (int ko = 0; ko < 256; ko += 8){
            unsigned af[4];
            af[0] = As[(ko+q4)*40 + rb + r8];
            af[1] = As[(ko+q4)*40 + rb + r8 + 8];
            af[2] = As[(ko+q4+4)*40 + rb + r8];
            af[3] = As[(ko+q4+4)*40 + rb + r8 + 8];
            #pragma unroll
            for (int nt = 0; nt < 4; nt++){
                int nb = wn*32 + nt*8;
                unsigned bf[2];
                bf[0] = Bs[(ko+q4)*136 + nb + r8];
                bf[1] = Bs[(ko+q4+4)*136 + nb + r8];
                mma8(acc[nt], af, bf);
            }
        }
        __syncthreads();
        #pragma unroll
        for (int nt = 0; nt < 4; nt++){
            int col = wn*32 + nt*8 + q4*2;
            Gs[(rb+r8)*136 + col]     = acc[nt][0];
            Gs[(rb+r8)*136 + col+1]   = acc[nt][1];
            Gs[(rb+r8+8)*136 + col]   = acc[nt][2];
            Gs[(rb+r8+8)*136 + col+1] = acc[nt][3];
        }
        __syncthreads();

        #pragma unroll
        for (int it = 0; it < 4; it++){
            int id = tid + it*256;
            int m = id >> 5, hp = id & 31;
            int n = n0 + m, h = h0 + hp;
            size_t tok = (size_t)n*T + t;
            const float* xb = xg + tok*(size_t)G4;
            float4 g = *(const float4*)&Gs[m*136 + hp*4];
            float gi = g.x + xb[h];
            float gf = g.y + xb[Hh + h];
            float gg = g.z + xb[2*Hh + h];
            float go = g.w + xb[3*Hh + h];
            float cp = (t == 0) ? 0.f : cst[(size_t)n*Hh + h];
            float cv = sigf(gf)*cp + sigf(gi)*tanhf(gg);
            cst[(size_t)n*Hh + h] = cv;
            enc[tok*Hh + h] = sigf(go)*tanhf(cv);
        }
        gridbar(nblocks);
    }
}

// ---------------- conv stage 1 (padded rows, zero-filled pad) ----------------
__global__ void s_k(const float* __restrict__ cW, float* __restrict__ s,
                    int KW, int KP, long total)
{
    long i = (long)blockIdx.x*blockDim.x + threadIdx.x;
    if (i >= total) return;
    int kk = (int)(i % KP);
    long r = i / KP;
    int q  = (int)(r % QLn); r /= QLn;
    int o  = (int)(r % NFc);
    int b  = (int)(r / NFc);
    float v = 0.f;
    if (kk < Cc*KW){
        int dd = kk / Cc, c = kk - dd*Cc;
        #pragma unroll
        for (int dq = 0; dq < 3; dq++){
            int qq = q + dq - 1;
            if (qq >= 0 && qq < QLn)
                v += cW[(((size_t)o*51 + c)*3 + dq)*KW + dd] * g_pq[((size_t)b*QLn + qq)*Cc + c];
        }
    }
    s[i] = v;
}

// ---------------- conv stage 2: resident-B + 3-stage A pipeline ----------------
#define CONV_DSM ((3*2560 + 50*132)*4)
template<int KW>
__global__ __launch_bounds__(256,2) void convgemm_k(
    const float* __restrict__ sA, const float* __restrict__ cW,
    const float* __restrict__ cb, const int* __restrict__ bqtok,
    const int* __restrict__ bdtok, const float* __restrict__ alpha, int OCB)
{
    const int K = Cc*KW, KP = (K+3)&~3, PW = KW/2;
    const int nk = (KP + 15) >> 4;
    extern __shared__ float dsm[];
    float* Asm = dsm;              // 3 stages x [128][20]
    float* pdt = dsm + 3*2560;     // [50][132]
    __shared__ float ems[18][136];
    __shared__ float wem[8][3*KW];
    __shared__ int qt[16], dt[128], s_any;
    int tid = threadIdx.x;
    int lane = tid & 31, warp = tid >> 5;
    int wm = warp >> 2, wn = warp & 3;
    int img = blockIdx.y, b = img / Dn;
    int m0 = blockIdx.x*128, obase = m0 >> 4;
    int r8 = lane>>2, q4 = lane&3;

    const float* Pd = &g_pdT[(size_t)img*Cc*DLn];
    int arow = tid >> 1, acp = (tid & 1)*8;
    bool mok = (m0 + arow) < 800;
    const float* Arow = sA + ((size_t)b*800 + (mok ? m0+arow : 0))*KP;

    auto issueA = [&](int kt, int buf){
        int k0 = kt*16;
        unsigned d = sptr(Asm + buf*2560 + arow*20 + acp);
        cpa16(d,    Arow + k0 + acp,     mok && (k0+acp)   < KP);
        cpa16(d+16, Arow + k0 + acp + 4, mok && (k0+acp+4) < KP);
    };

    // group0: pdt + A(0); group1: A(1)
    for (int ch = tid; ch < 1600; ch += 256){
        int row = ch >> 5, off = (ch & 31) * 4;
        cpa16(sptr(pdt + row*132 + off), Pd + row*128 + off, true);
    }
    issueA(0,0); CP_COMMIT();
    issueA(1,1); CP_COMMIT();

    if (tid == 0) s_any = 0;
    if (tid < 16) qt[tid] = bqtok[b*QLn + tid];
    if (tid < 128) dt[tid] = bdtok[(size_t)img*DLn + tid];
    if (tid < 8*3*KW){
        int ol = tid/(3*KW), rr = tid%(3*KW);
        int o = obase + ol;
        wem[ol][rr] = (o < NFc) ? cW[(((size_t)o*51 + 50)*3 + rr/KW)*KW + rr%KW] : 0.f;
    }
    __syncthreads();
    float al = alpha[0];
    for (int e = tid; e < 18*136; e += 256){
        int qi = e/136, dj = e%136;
        int q = qi-1, dl = dj-3;
        float v = 0.f;
        if (q >= 0 && q < QLn && dl >= 0 && dl < DLn && qt[q] == dt[dl]){ v = al; s_any = 1; }
        ems[qi][dj] = v;
    }

    float acc[4][4][4] = {};
    int buf = 0;
    for (int kt = 0; kt < nk; kt++){
        if (kt >= nk-1) CP_WAIT0(); else CP_WAIT1();
        __syncthreads();
        if (kt+2 < nk){ issueA(kt+2, buf == 0 ? 2 : buf-1); CP_COMMIT(); }
        const float* Ab2 = Asm + buf*2560;
        #pragma unroll
        for (int kb=0; kb<2; kb++){
            int ko = kb*8;
            int ka = kt*16 + ko + q4;
            int k2 = ka + 4;
            int dda = ka/Cc, ca = ka - dda*Cc;
            int ddb = k2/Cc, cbb = k2 - ddb*Cc;
            unsigned af[4][4], bf[4][2];
            #pragma unroll
            for (int mt=0; mt<4; mt++){
                int rb = wm*64 + mt*16;
                af[mt][0] = __float_as_uint(Ab2[(rb+r8  )*20 + ko+q4  ]);
                af[mt][1] = __float_as_uint(Ab2[(rb+r8+8)*20 + ko+q4  ]);
                af[mt][2] = __float_as_uint(Ab2[(rb+r8  )*20 + ko+q4+4]);
                af[mt][3] = __float_as_uint(Ab2[(rb+r8+8)*20 + ko+q4+4]);
            }
            #pragma unroll
            for (int nt=0; nt<4; nt++){
                int col = wn*32 + nt*8 + r8;
                int sa = col + dda - PW;
                int sb = col + ddb - PW;
                bf[nt][0] = ((unsigned)sa < 128u) ? __float_as_uint(pdt[ca*132 + sa]) : 0u;
                bf[nt][1] = ((unsigned)sb < 128u) ? __float_as_uint(pdt[cbb*132 + sb]) : 0u;
            }
            #pragma unroll
            for (int mt=0;mt<4;mt++)
                #pragma unroll
                for (int nt=0;nt<4;nt++)
                    mma8(acc[mt][nt], af[mt], bf[nt]);
        }
        buf = (buf == 2) ? 0 : buf+1;
    }

    int any = s_any;
    #pragma unroll
    for (int mt=0;mt<4;mt++){
        int row = m0 + wm*64 + mt*16;
        if (row >= 800) continue;
        int o = row >> 4, ol = o - obase;
        float bias = cb[o];
        #pragma unroll
        for (int rr=0; rr<2; rr++){
            int q = r8 + rr*8;
            #pragma unroll
            for (int nt=0;nt<4;nt++){
                int col = wn*32 + nt*8 + q4*2;
                #pragma unroll
                for (int j=0;j<2;j++){
                    int dl = col + j;
                    float v = acc[mt][nt][rr*2 + j] + bias;
                    if (any){
                        #pragma unroll
                        for (int dq = 0; dq < 3; dq++)
                            #pragma unroll
                            for (int dd = 0; dd < KW; dd++)
                                v += wem[ol][dq*KW+dd] * ems[q+dq][dl+dd+3-PW];
                    }
                    v = fmaxf(v, 0.f);
                    g_f[(((size_t)img*150 + OCB + o)*QLn + q)*DLn + dl] = v;
                }
            }
        }
    }
}

// ---------------- 1x1 conv + global maxpool + linear ----------------
__global__ __launch_bounds__(256) void score_k(
    const float* __restrict__ ccW, const float* __restrict__ ccb,
    const float* __restrict__ outW, const float* __restrict__ outb,
    float* __restrict__ out)
{
    __shared__ float w[MFc][152];
    __shared__ float red[8][MFc];
    int img = blockIdx.x, tid = threadIdx.x;
    for (int e = tid; e < MFc*150; e += 256) w[e/150][e%150] = ccW[e];
    __syncthreads();
    float mx[MFc];
    #pragma unroll
    for (int mf = 0; mf < MFc; mf++) mx[mf] = -1e30f;
    const float* fb = &g_f[(size_t)img*150*QLn*DLn];
    for (int p = tid; p < QLn*DLn; p += 256){
        float acc[MFc];
        #pragma unroll
        for (int mf = 0; mf < MFc; mf++) acc[mf] = ccb[mf];
        for (int nf = 0; nf < 150; nf++){
            float v = fb[(size_t)nf*QLn*DLn + p];
            #pragma unroll
            for (int mf = 0; mf < MFc; mf++) acc[mf] += v*w[mf][nf];
        }
        #pragma unroll
        for (int mf = 0; mf < MFc; mf++) mx[mf] = fmaxf(mx[mf], acc[mf]);
    }
    #pragma unroll
    for (int off = 16; off; off >>= 1)
        #pragma unroll
        for (int mf = 0; mf < MFc; mf++)
            mx[mf] = fmaxf(mx[mf], __shfl_xor_sync(0xFFFFFFFFu, mx[mf], off));
    if ((tid & 31) == 0)
        #pragma unroll
        for (int mf = 0; mf < MFc; mf++) red[tid>>5][mf] = mx[mf];
    __syncthreads();
    if (tid == 0){
        float sc = outb[0];
        #pragma unroll
        for (int mf = 0; mf < MFc; mf++){
            float m = red[0][mf];
            #pragma unroll
            for (int wp = 1; wp < 8; wp++) m = fmaxf(m, red[wp][mf]);
            sc += m*outW[mf];
        }
        out[img] = sc;
    }
}

// ---------------- launch ----------------
extern "C" void kernel_launch(void* const* d_in, const int* in_sizes, int n_in,
                              void* d_out, int out_size)
{
    const int* bqtok = nullptr; const int* bdtok = nullptr;
    for (int i = 0; i < 4; i++){
        if (in_sizes[i] == NTQ)      bqtok = (const int*)d_in[i];
        else if (in_sizes[i] == NTD) bdtok = (const int*)d_in[i];
    }
    const float* emb    = (const float*)d_in[4];
    const float* projW  = (const float*)d_in[5];
    const float* projb  = (const float*)d_in[6];
    const float* qWih   = (const float*)d_in[7];
    const float* qWhh   = (const float*)d_in[8];
    const float* qbih   = (const float*)d_in[9];
    const float* qbhh   = (const float*)d_in[10];
    const float* dWih   = (const float*)d_in[11];
    const float* dWhh   = (const float*)d_in[12];
    const float* dbih   = (const float*)d_in[13];
    const float* dbhh   = (const float*)d_in[14];
    const float* qpW    = (const float*)d_in[15];
    const float* qpb    = (const float*)d_in[16];
    const float* dpW    = (const float*)d_in[17];
    const float* dpb    = (const float*)d_in[18];
    const float* alpha  = (const float*)d_in[19];
    const float* c1W    = (const float*)d_in[20];
    const float* c1b    = (const float*)d_in[21];
    const float* c2W    = (const float*)d_in[22];
    const float* c2b    = (const float*)d_in[23];
    const float* c3W    = (const float*)d_in[24];
    const float* c3b    = (const float*)d_in[25];
    const float* ccW    = (const float*)d_in[26];
    const float* ccb    = (const float*)d_in[27];
    const float* outW   = (const float*)d_in[28];
    const float* outb   = (const float*)d_in[29];
    float* out = (float*)d_out;

    float *pXq,*pXd,*pxgq,*pxgd,*pencq,*pencd,*pc,*ppq,*ppdT,*ps3,*ps5,*ps7;
    cudaGetSymbolAddress((void**)&pXq,  g_Xq);
    cudaGetSymbolAddress((void**)&pXd,  g_Xd);
    cudaGetSymbolAddress((void**)&pxgq, g_xgq);
    cudaGetSymbolAddress((void**)&pxgd, g_xgd);
    cudaGetSymbolAddress((void**)&pencq,g_encq);
    cudaGetSymbolAddress((void**)&pencd,g_encd);
    cudaGetSymbolAddress((void**)&pc,   g_c);
    cudaGetSymbolAddress((void**)&ppq,  g_pq);
    cudaGetSymbolAddress((void**)&ppdT, g_pdT);
    cudaGetSymbolAddress((void**)&ps3,  g_s3);
    cudaGetSymbolAddress((void**)&ps5,  g_s5);
    cudaGetSymbolAddress((void**)&ps7,  g_s7);
    float *pqb,*pdb;
    cudaGetSymbolAddress((void**)&pqb,  g_qb);
    cudaGetSymbolAddress((void**)&pdb,  g_db);

    cudaFuncSetAttribute(lstm_persist, cudaFuncAttributeMaxDynamicSharedMemorySize, LSTM_SMEM);
    cudaFuncSetAttribute(gemm_tf32<true,false,true,0>,  cudaFuncAttributeMaxDynamicSharedMemorySize, GEMM_DSM);
    cudaFuncSetAttribute(gemm_tf32<false,true,true,0>,  cudaFuncAttributeMaxDynamicSharedMemorySize, GEMM_DSM);
    cudaFuncSetAttribute(gemm_tf32<false,false,false,0>,cudaFuncAttributeMaxDynamicSharedMemorySize, GEMM_DSM);
    cudaFuncSetAttribute(gemm_tf32<false,false,false,1>,cudaFuncAttributeMaxDynamicSharedMemorySize, GEMM_DSM);
    cudaFuncSetAttribute(convgemm_k<3>, cudaFuncAttributeMaxDynamicSharedMemorySize, CONV_DSM);
    cudaFuncSetAttribute(convgemm_k<5>, cudaFuncAttributeMaxDynamicSharedMemorySize, CONV_DSM);
    cudaFuncSetAttribute(convgemm_k<7>, cudaFuncAttributeMaxDynamicSharedMemorySize, CONV_DSM);

    bias_sum_k<<<4,256>>>(qbih,qbhh,dbih,dbhh);

    // embed + proj (tf32):  X = emb[tok] @ projW + projb
    gemm_tf32<true,false,true,0><<<dim3(3,4),256,GEMM_DSM>>>(emb,bqtok,Ff, projW,Ff, projb, pXq,Ff, NTQ,Ff,Ff);
    gemm_tf32<true,false,true,0><<<dim3(3,320),256,GEMM_DSM>>>(emb,bdtok,Ff, projW,Ff, projb, pXd,Ff, NTD,Ff,Ff);

    // input gates: xg = X @ Wih^T + (bih+bhh)
    gemm_tf32<false,true,true,0><<<dim3(8,4),256,GEMM_DSM>>>(pXq,nullptr,Ff, qWih,Ff, pqb, pxgq,G4, NTQ,G4,Ff);
    gemm_tf32<false,true,true,0><<<dim3(8,320),256,GEMM_DSM>>>(pXd,nullptr,Ff, dWih,Ff, pdb, pxgd,G4, NTD,G4,Ff);

    // persistent LSTMs
    lstm_persist<<<dim3(1,8),256,LSTM_SMEM>>>(pxgq, qWhh, pc, pencq, QLn);
    lstm_persist<<<dim3(10,8),256,LSTM_SMEM>>>(pxgd, dWhh, pc, pencd, DLn);

    // projections: pq [512,50]; pd transposed per image [img][c][dl]
    gemm_tf32<false,false,false,0><<<dim3(1,4),256,GEMM_DSM>>>(pencq,nullptr,Hh, qpW,Cc, qpb, ppq,Cc, NTQ,Cc,Hh);
    gemm_tf32<false,false,false,1><<<dim3(1,320),256,GEMM_DSM>>>(pencd,nullptr,Hh, dpW,Cc, dpb, ppdT,0, NTD,Cc,Hh);

    // conv stage 1 (padded)
    {
        long t3 = (long)Bq*NFc*QLn*152, t5 = (long)Bq*NFc*QLn*252, t7 = (long)Bq*NFc*QLn*352;
        s_k<<<(unsigned)((t3+255)/256),256>>>(c1W, ps3, 3, 152, t3);
        s_k<<<(unsigned)((t5+255)/256),256>>>(c2W, ps5, 5, 252, t5);
        s_k<<<(unsigned)((t7+255)/256),256>>>(c3W, ps7, 7, 352, t7);
    }
    // conv stage 2 (resident-B tf32 GEMM + exact-match + relu)
    convgemm_k<3><<<dim3(7,BD),256,CONV_DSM>>>(ps3, c1W, c1b, bqtok, bdtok, alpha, 0);
    convgemm_k<5><<<dim3(7,BD),256,CONV_DSM>>>(ps5, c2W, c2b, bqtok, bdtok, alpha, 50);
    convgemm_k<7><<<dim3(7,BD),256,CONV_DSM>>>(ps7, c3W, c3b, bqtok, bdtok, alpha, 100);

    // 1x1 conv + maxpool + output linear
    score_k<<<BD,256>>>(ccW, ccb, outW, outb, out);
}

// round 7
// speedup vs baseline: 2.2809x; 1.2636x over previous
#include <cuda_runtime.h>
#include <math.h>

// ---------------- problem constants ----------------
#define Bq  32
#define Dn  10
#define QLn 16
#define DLn 128
#define BD  320
#define Ff  300
#define Hh  256
#define G4  1024
#define Cc  50
#define NFc 50
#define MFc 20
#define NTQ (Bq*QLn)      // 512
#define NTD (BD*DLn)      // 40960

// ---------------- device scratch ----------------
__device__ float g_Xq[NTQ*Ff];
__device__ float g_Xd[(size_t)NTD*Ff];
__device__ float g_xgq[(size_t)NTQ*G4];
__device__ float g_xgd[(size_t)NTD*G4];
__device__ float g_encq[NTQ*Hh];
__device__ float g_encd[(size_t)NTD*Hh];
__device__ float g_pq[NTQ*Cc];
__device__ float g_pdT[(size_t)BD*Cc*DLn];
__device__ float g_s3[(size_t)Bq*NFc*QLn*152 + 16];
__device__ float g_s5[(size_t)Bq*NFc*QLn*252 + 16];
__device__ float g_s7[(size_t)Bq*NFc*QLn*352 + 16];
__device__ float g_f[(size_t)BD*150*QLn*DLn];
__device__ float g_qb[G4];
__device__ float g_db[G4];

__device__ __forceinline__ float tha(float x){
    float y; asm("tanh.approx.f32 %0, %1;" : "=f"(y) : "f"(x)); return y;
}
__device__ __forceinline__ float sigf(float x){ return fmaf(tha(0.5f*x), 0.5f, 0.5f); }

__device__ __forceinline__ void mma8(float* c, const unsigned* a, const unsigned* b){
    asm volatile("mma.sync.aligned.m16n8k8.row.col.f32.tf32.tf32.f32 "
        "{%0,%1,%2,%3}, {%4,%5,%6,%7}, {%8,%9}, {%0,%1,%2,%3};"
        : "+f"(c[0]),"+f"(c[1]),"+f"(c[2]),"+f"(c[3])
        : "r"(a[0]),"r"(a[1]),"r"(a[2]),"r"(a[3]), "r"(b[0]),"r"(b[1]));
}
__device__ __forceinline__ unsigned sptr(const void* p){
    return (unsigned)__cvta_generic_to_shared(p);
}
__device__ __forceinline__ void cpa16(unsigned dst, const void* src, bool pred){
    int sz = pred ? 16 : 0;
    asm volatile("cp.async.cg.shared.global [%0], [%1], 16, %2;" :: "r"(dst), "l"(src), "r"(sz));
}
#define CP_COMMIT() asm volatile("cp.async.commit_group;")
#define CP_WAIT0()  asm volatile("cp.async.wait_group 0;")
#define CP_WAIT1()  asm volatile("cp.async.wait_group 1;")
#define CLUSTER_ARRIVE() asm volatile("barrier.cluster.arrive.aligned;" ::: "memory")
#define CLUSTER_WAIT()   asm volatile("barrier.cluster.wait.aligned;" ::: "memory")

// ---------------- bias precombine ----------------
__global__ void bias_sum_k(const float* __restrict__ qb1, const float* __restrict__ qb2,
                           const float* __restrict__ db1, const float* __restrict__ db2)
{
    int t = blockIdx.x*blockDim.x + threadIdx.x;
    if (t < G4){ g_qb[t] = qb1[t]+qb2[t]; g_db[t] = db1[t]+db2[t]; }
}

// ---------------- 3-stage pipelined tf32 GEMM: 128x128 tile ----------------
// C[M,N] = A(gathered)[M,K] * B + bias.  BT: B is [N,K].
// BASYNC: B via cp.async (16B-aligned rows); else register-staged (prefetched).
// STORE 0: C[m*ldc+n].  STORE 1: pdT: img=m>>7 -> C[(img*50+n)*128 + (m&127)]
#define GEMM_DSM (6*2560*4)
template<bool GATHER, bool BT, bool BASYNC, int STORE>
__global__ __launch_bounds__(256,2) void gemm_tf32(
    const float* __restrict__ A, const int* __restrict__ idx, int lda,
    const float* __restrict__ Bm, int ldb, const float* __restrict__ bias,
    float* __restrict__ C, int ldc, int M, int N, int K)
{
    extern __shared__ float dsm[];
    float* Asm = dsm;            // 3 stages x [128][20]
    float* Bsm = dsm + 3*2560;   // 3 stages x 2560 (BT: [n*20+k]; !BT: [k*132+n])
    int tid = threadIdx.x;
    int lane = tid & 31, warp = tid >> 5;
    int wm = warp >> 2, wn = warp & 3;
    int m0 = blockIdx.y*128, n0 = blockIdx.x*128;
    int nk = (K + 15) >> 4;
    int r8 = lane>>2, q4 = lane&3;

    int arow = tid >> 1;
    int acp  = (tid & 1) * 8;
    bool mrowok = (m0 + arow) < M;
    const float* Arow;
    { long r = GATHER ? (long)idx[m0 + (mrowok ? arow : 0)] : (long)(m0 + (mrowok ? arow : 0));
      Arow = A + r*(long)lda; }

    bool nrowok = (n0 + arow) < N;
    const float* Brow = Bm + (size_t)(n0 + (nrowok ? arow : 0))*(BT ? ldb : 0);
    int bkr = tid >> 4, bnf = (tid & 15)*8;

    auto issue = [&](int kt, int buf){
        int k0 = kt*16;
        unsigned d = sptr(Asm + buf*2560 + arow*20 + acp);
        cpa16(d,    Arow + k0 + acp,     mrowok && (k0+acp)   < K);
        cpa16(d+16, Arow + k0 + acp + 4, mrowok && (k0+acp+4) < K);
        if (BASYNC){
            if (BT){
                unsigned db = sptr(Bsm + buf*2560 + arow*20 + acp);
                cpa16(db,    Brow + k0 + acp,     nrowok && (k0+acp)   < K);
                cpa16(db+16, Brow + k0 + acp + 4, nrowok && (k0+acp+4) < K);
            } else {
                const float* src = Bm + (size_t)(k0+bkr)*ldb + n0 + bnf;
                unsigned db = sptr(Bsm + buf*2560 + bkr*132 + bnf);
                bool kok = (k0+bkr) < K;
                cpa16(db,    src,   kok && (n0+bnf)   < N);
                cpa16(db+16, src+4, kok && (n0+bnf+4) < N);
            }
        }
        CP_COMMIT();
    };

    // !BASYNC register-staged B
    float bv[8];
    int nc = (tid&31)*4, kr = tid>>5;
    auto ldgB = [&](int kt){
        int k0 = kt*16;
        #pragma unroll
        for (int h=0;h<2;h++){
            int kk = k0 + kr + h*8;
            #pragma unroll
            for (int j=0;j<4;j++){
                int n = n0 + nc + j;
                bv[h*4+j] = (kk < K && n < N) ? Bm[(size_t)kk*ldb + n] : 0.f;
            }
        }
    };
    auto stsB = [&](int buf){
        #pragma unroll
        for (int h=0;h<2;h++)
            #pragma unroll
            for (int j=0;j<4;j++) Bsm[buf*2560 + (kr+h*8)*132 + nc+j] = bv[h*4+j];
    };

    float acc[4][4][4] = {};

    issue(0,0);
    if (nk > 1) issue(1,1);
    if (!BASYNC) ldgB(0);

    int buf = 0;
    for (int kt = 0; kt < nk; kt++){
        if (kt >= nk-1) CP_WAIT0(); else CP_WAIT1();
        __syncthreads();
        if (!BASYNC) stsB(buf);
        if (kt+2 < nk) issue(kt+2, buf == 0 ? 2 : buf-1);
        if (!BASYNC){
            if (kt+1 < nk) ldgB(kt+1);
            __syncthreads();
        }
        const float* Ab2 = Asm + buf*2560;
        const float* Bb2 = Bsm + buf*2560;
        #pragma unroll
        for (int kb=0; kb<2; kb++){
            int ko = kb*8;
            unsigned af[4][4], bf[4][2];
            #pragma unroll
            for (int mt=0; mt<4; mt++){
                int rb = wm*64 + mt*16;
                af[mt][0] = __float_as_uint(Ab2[(rb+r8  )*20 + ko+q4  ]);
                af[mt][1] = __float_as_uint(Ab2[(rb+r8+8)*20 + ko+q4  ]);
                af[mt][2] = __float_as_uint(Ab2[(rb+r8  )*20 + ko+q4+4]);
                af[mt][3] = __float_as_uint(Ab2[(rb+r8+8)*20 + ko+q4+4]);
            }
            #pragma unroll
            for (int nt=0; nt<4; nt++){
                int nb = wn*32 + nt*8;
                if (BT){
                    bf[nt][0] = __float_as_uint(Bb2[(nb+r8)*20 + ko+q4  ]);
                    bf[nt][1] = __float_as_uint(Bb2[(nb+r8)*20 + ko+q4+4]);
                } else {
                    bf[nt][0] = __float_as_uint(Bb2[(ko+q4  )*132 + nb+r8]);
                    bf[nt][1] = __float_as_uint(Bb2[(ko+q4+4)*132 + nb+r8]);
                }
            }
            #pragma unroll
            for (int mt=0;mt<4;mt++)
                #pragma unroll
                for (int nt=0;nt<4;nt++)
                    mma8(acc[mt][nt], af[mt], bf[nt]);
        }
        buf = (buf == 2) ? 0 : buf+1;
    }

    #pragma unroll
    for (int mt=0;mt<4;mt++){
        int row = m0 + wm*64 + mt*16 + r8;
        #pragma unroll
        for (int nt=0;nt<4;nt++){
            int col = n0 + wn*32 + nt*8 + q4*2;
            const float* cc = acc[mt][nt];
            #pragma unroll
            for (int j=0;j<2;j++){
                int n = col + j;
                if (n >= N) continue;
                float bb = bias ? bias[n] : 0.f;
                float v0 = cc[j] + bb, v1 = cc[2+j] + bb;
                if (STORE == 0){
                    if (row < M)   C[(size_t)row*ldc + n] = v0;
                    if (row+8 < M) C[(size_t)(row+8)*ldc + n] = v1;
                } else {
                    int img = row >> 7;
                    C[((size_t)img*Cc + n)*DLn + (row & 127)] = v0;
                    C[((size_t)img*Cc + n)*DLn + ((row+8) & 127)] = v1;
                }
            }
        }
    }
}

// ---------------- persistent LSTM (cluster of 8 h-blocks per seq group) ----
// blockIdx.x = hb(0..7) + 8*seq_group. Cluster barrier syncs the 8 h-blocks;
// seq groups are independent. Cell state lives in registers.
#define LSTM_SMEM ((256*136 + 256*40)*4)
__global__ __cluster_dims__(8,1,1) __launch_bounds__(256,1) void lstm_persist(
    const float* __restrict__ xg, const float* __restrict__ Whh,
    float* __restrict__ enc, int T)
{
    extern __shared__ unsigned smbuf[];
    unsigned* Bs = smbuf;                  // [256][136] tf32 Whh slice
    unsigned* As = smbuf + 256*136;        // [256][40]  h_prev
    float* Gs = (float*)As;                // [32][136]  overlay: gate preacts
    int tid = threadIdx.x;
    int lane = tid & 31, warp = tid >> 5;
    int r8 = lane >> 2, q4 = lane & 3;
    int wm = warp & 1, wn = warp >> 1;
    int hb = blockIdx.x & 7, sg = blockIdx.x >> 3;
    int n0 = sg * 32;
    int h0 = hb * 32;

    for (int idx = tid; idx < 128*256; idx += 256){
        int j = idx >> 8, k = idx & 255;
        int r = ((j & 3) << 8) + h0 + (j >> 2);
        Bs[k*136 + j] = __float_as_uint(Whh[(size_t)r*Hh + k]);
    }
    __syncthreads();

    float creg[4] = {0.f, 0.f, 0.f, 0.f};

    for (int t = 0; t < T; t++){
        if (t == 0){
            for (int idx = tid; idx < 32*256; idx += 256)
                As[(idx & 255)*40 + (idx >> 8)] = 0u;
        } else {
            for (int idx = tid; idx < 32*256; idx += 256){
                int m = idx >> 8, k = idx & 255;
                As[k*40 + m] = __float_as_uint(enc[((size_t)(n0+m)*T + (t-1))*Hh + k]);
            }
        }
        __syncthreads();

        float acc[4][4] = {};
        int rb = wm*16;
        #pragma unroll 4
        for (int ko = 0; ko < 256; ko += 8){
            unsigned af[4];
            af[0] = As[(ko+q4)*40 + rb + r8];
            af[1] = As[(ko+q4)*40 + rb + r8 + 8];
            af[2] = As[(ko+q4+4)*40 + rb + r8];
            af[3] = As[(ko+q4+4)*40 + rb + r8 + 8];
            #pragma unroll
            for (int nt = 0; nt < 4; nt++){
                int nb = wn*32 + nt*8;
                unsigned bf[2];
                bf[0] = Bs[(ko+q4)*136 + nb + r8];
                bf[1] = Bs[(ko+q4+4)*136 + nb + r8];
                mma8(acc[nt], af, bf);
            }
        }
        __syncthreads();
        #pragma unroll
        for (int nt = 0; nt < 4; nt++){
            int col = wn*32 + nt*8 + q4*2;
            Gs[(rb+r8)*136 + col]     = acc[nt][0];
            Gs[(rb+r8)*136 + col+1]   = acc[nt][1];
            Gs[(rb+r8+8)*136 + col]   = acc[nt][2];
            Gs[(rb+r8+8)*136 + col+1] = acc[nt][3];
        }
        __syncthreads();

        #pragma unroll
        for (int it = 0; it < 4; it++){
            int id = tid + it*256;
            int m = id >> 5, hp = id & 31;
            int n = n0 + m, h = h0 + hp;
            size_t tok = (size_t)n*T + t;
            const float* xb = xg + tok*(size_t)G4;
            float4 g = *(const float4*)&Gs[m*136 + hp*4];
            float gi = g.x + xb[h];
            float gf = g.y + xb[Hh + h];
            float gg = g.z + xb[2*Hh + h];
            float go = g.w + xb[3*Hh + h];
            float cv = sigf(gf)*creg[it] + sigf(gi)*tha(gg);
            creg[it] = cv;
            enc[tok*Hh + h] = sigf(go)*tha(cv);
        }
        __threadfence();
        CLUSTER_ARRIVE();
        CLUSTER_WAIT();
    }
}

// ---------------- conv stage 1 (padded rows, zero-filled pad) ----------------
__global__ void s_k(const float* __restrict__ cW, float* __restrict__ s,
                    int KW, int KP, long total)
{
    long i = (long)blockIdx.x*blockDim.x + threadIdx.x;
    if (i >= total) return;
    int kk = (int)(i % KP);
    long r = i / KP;
    int q  = (int)(r % QLn); r /= QLn;
    int o  = (int)(r % NFc);
    int b  = (int)(r / NFc);
    float v = 0.f;
    if (kk < Cc*KW){
        int dd = kk / Cc, c = kk - dd*Cc;
        #pragma unroll
        for (int dq = 0; dq < 3; dq++){
            int qq = q + dq - 1;
            if (qq >= 0 && qq < QLn)
                v += cW[(((size_t)o*51 + c)*3 + dq)*KW + dd] * g_pq[((size_t)b*QLn + qq)*Cc + c];
        }
    }
    s[i] = v;
}

// ---------------- conv stage 2: resident-B + 3-stage A pipeline ----------------
#define CONV_DSM ((3*2560 + 50*132)*4)
template<int KW>
__global__ __launch_bounds__(256,2) void convgemm_k(
    const float* __restrict__ sA, const float* __restrict__ cW,
    const float* __restrict__ cb, const int* __restrict__ bqtok,
    const int* __restrict__ bdtok, const float* __restrict__ alpha, int OCB)
{
    const int K = Cc*KW, KP = (K+3)&~3, PW = KW/2;
    const int nk = (KP + 15) >> 4;
    extern __shared__ float dsm[];
    float* Asm = dsm;              // 3 stages x [128][20]
    float* pdt = dsm + 3*2560;     // [50][132]
    __shared__ float ems[18][136];
    __shared__ float wem[8][3*KW];
    __shared__ int qt[16], dt[128], s_any;
    int tid = threadIdx.x;
    int lane = tid & 31, warp = tid >> 5;
    int wm = warp >> 2, wn = warp & 3;
    int img = blockIdx.y, b = img / Dn;
    int m0 = blockIdx.x*128, obase = m0 >> 4;
    int r8 = lane>>2, q4 = lane&3;

    const float* Pd = &g_pdT[(size_t)img*Cc*DLn];
    int arow = tid >> 1, acp = (tid & 1)*8;
    bool mok = (m0 + arow) < 800;
    const float* Arow = sA + ((size_t)b*800 + (mok ? m0+arow : 0))*KP;

    auto issueA = [&](int kt, int buf){
        int k0 = kt*16;
        unsigned d = sptr(Asm + buf*2560 + arow*20 + acp);
        cpa16(d,    Arow + k0 + acp,     mok && (k0+acp)   < KP);
        cpa16(d+16, Arow + k0 + acp + 4, mok && (k0+acp+4) < KP);
    };

    for (int ch = tid; ch < 1600; ch += 256){
        int row = ch >> 5, off = (ch & 31) * 4;
        cpa16(sptr(pdt + row*132 + off), Pd + row*128 + off, true);
    }
    issueA(0,0); CP_COMMIT();
    issueA(1,1); CP_COMMIT();

    if (tid == 0) s_any = 0;
    if (tid < 16) qt[tid] = bqtok[b*QLn + tid];
    if (tid < 128) dt[tid] = bdtok[(size_t)img*DLn + tid];
    if (tid < 8*3*KW){
        int ol = tid/(3*KW), rr = tid%(3*KW);
        int o = obase + ol;
        wem[ol][rr] = (o < NFc) ? cW[(((size_t)o*51 + 50)*3 + rr/KW)*KW + rr%KW] : 0.f;
    }
    __syncthreads();
    float al = alpha[0];
    for (int e = tid; e < 18*136; e += 256){
        int qi = e/136, dj = e%136;
        int q = qi-1, dl = dj-3;
        float v = 0.f;
        if (q >= 0 && q < QLn && dl >= 0 && dl < DLn && qt[q] == dt[dl]){ v = al; s_any = 1; }
        ems[qi][dj] = v;
    }

    float acc[4][4][4] = {};
    int buf = 0;
    for (int kt = 0; kt < nk; kt++){
        if (kt >= nk-1) CP_WAIT0(); else CP_WAIT1();
        __syncthreads();
        if (kt+2 < nk){ issueA(kt+2, buf == 0 ? 2 : buf-1); CP_COMMIT(); }
        const float* Ab2 = Asm + buf*2560;
        #pragma unroll
        for (int kb=0; kb<2; kb++){
            int ko = kb*8;
            int ka = kt*16 + ko + q4;
            int k2 = ka + 4;
            int dda = ka/Cc, ca = ka - dda*Cc;
            int ddb = k2/Cc, cbb = k2 - ddb*Cc;
            unsigned af[4][4], bf[4][2];
            #pragma unroll
            for (int mt=0; mt<4; mt++){
                int rb = wm*64 + mt*16;
                af[mt][0] = __float_as_uint(Ab2[(rb+r8  )*20 + ko+q4  ]);
                af[mt][1] = __float_as_uint(Ab2[(rb+r8+8)*20 + ko+q4  ]);
                af[mt][2] = __float_as_uint(Ab2[(rb+r8  )*20 + ko+q4+4]);
                af[mt][3] = __float_as_uint(Ab2[(rb+r8+8)*20 + ko+q4+4]);
            }
            #pragma unroll
            for (int nt=0; nt<4; nt++){
                int col = wn*32 + nt*8 + r8;
                int sa = col + dda - PW;
                int sb = col + ddb - PW;
                bf[nt][0] = ((unsigned)sa < 128u) ? __float_as_uint(pdt[ca*132 + sa]) : 0u;
                bf[nt][1] = ((unsigned)sb < 128u) ? __float_as_uint(pdt[cbb*132 + sb]) : 0u;
            }
            #pragma unroll
            for (int mt=0;mt<4;mt++)
                #pragma unroll
                for (int nt=0;nt<4;nt++)
                    mma8(acc[mt][nt], af[mt], bf[nt]);
        }
        buf = (buf == 2) ? 0 : buf+1;
    }

    int any = s_any;
    #pragma unroll
    for (int mt=0;mt<4;mt++){
        int row = m0 + wm*64 + mt*16;
        if (row >= 800) continue;
        int o = row >> 4, ol = o - obase;
        float bias = cb[o];
        #pragma unroll
        for (int rr=0; rr<2; rr++){
            int q = r8 + rr*8;
            #pragma unroll
            for (int nt=0;nt<4;nt++){
                int col = wn*32 + nt*8 + q4*2;
                #pragma unroll
                for (int j=0;j<2;j++){
                    int dl = col + j;
                    float v = acc[mt][nt][rr*2 + j] + bias;
                    if (any){
                        #pragma unroll
                        for (int dq = 0; dq < 3; dq++)
                            #pragma unroll
                            for (int dd = 0; dd < KW; dd++)
                                v += wem[ol][dq*KW+dd] * ems[q+dq][dl+dd+3-PW];
                    }
                    v = fmaxf(v, 0.f);
                    g_f[(((size_t)img*150 + OCB + o)*QLn + q)*DLn + dl] = v;
                }
            }
        }
    }
}

// ---------------- 1x1 conv + global maxpool + linear ----------------
__global__ __launch_bounds__(256) void score_k(
    const float* __restrict__ ccW, const float* __restrict__ ccb,
    const float* __restrict__ outW, const float* __restrict__ outb,
    float* __restrict__ out)
{
    __shared__ float w[MFc][152];
    __shared__ float red[8][MFc];
    int img = blockIdx.x, tid = threadIdx.x;
    for (int e = tid; e < MFc*150; e += 256) w[e/150][e%150] = ccW[e];
    __syncthreads();
    float mx[MFc];
    #pragma unroll
    for (int mf = 0; mf < MFc; mf++) mx[mf] = -1e30f;
    const float* fb = &g_f[(size_t)img*150*QLn*DLn];
    for (int p = tid; p < QLn*DLn; p += 256){
        float acc[MFc];
        #pragma unroll
        for (int mf = 0; mf < MFc; mf++) acc[mf] = ccb[mf];
        for (int nf = 0; nf < 150; nf++){
            float v = fb[(size_t)nf*QLn*DLn + p];
            #pragma unroll
            for (int mf = 0; mf < MFc; mf++) acc[mf] += v*w[mf][nf];
        }
        #pragma unroll
        for (int mf = 0; mf < MFc; mf++) mx[mf] = fmaxf(mx[mf], acc[mf]);
    }
    #pragma unroll
    for (int off = 16; off; off >>= 1)
        #pragma unroll
        for (int mf = 0; mf < MFc; mf++)
            mx[mf] = fmaxf(mx[mf], __shfl_xor_sync(0xFFFFFFFFu, mx[mf], off));
    if ((tid & 31) == 0)
        #pragma unroll
        for (int mf = 0; mf < MFc; mf++) red[tid>>5][mf] = mx[mf];
    __syncthreads();
    if (tid == 0){
        float sc = outb[0];
        #pragma unroll
        for (int mf = 0; mf < MFc; mf++){
            float m = red[0][mf];
            #pragma unroll
            for (int wp = 1; wp < 8; wp++) m = fmaxf(m, red[wp][mf]);
            sc += m*outW[mf];
        }
        out[img] = sc;
    }
}

// ---------------- launch ----------------
extern "C" void kernel_launch(void* const* d_in, const int* in_sizes, int n_in,
                              void* d_out, int out_size)
{
    const int* bqtok = nullptr; const int* bdtok = nullptr;
    for (int i = 0; i < 4; i++){
        if (in_sizes[i] == NTQ)      bqtok = (const int*)d_in[i];
        else if (in_sizes[i] == NTD) bdtok = (const int*)d_in[i];
    }
    const float* emb    = (const float*)d_in[4];
    const float* projW  = (const float*)d_in[5];
    const float* projb  = (const float*)d_in[6];
    const float* qWih   = (const float*)d_in[7];
    const float* qWhh   = (const float*)d_in[8];
    const float* qbih   = (const float*)d_in[9];
    const float* qbhh   = (const float*)d_in[10];
    const float* dWih   = (const float*)d_in[11];
    const float* dWhh   = (const float*)d_in[12];
    const float* dbih   = (const float*)d_in[13];
    const float* dbhh   = (const float*)d_in[14];
    const float* qpW    = (const float*)d_in[15];
    const float* qpb    = (const float*)d_in[16];
    const float* dpW    = (const float*)d_in[17];
    const float* dpb    = (const float*)d_in[18];
    const float* alpha  = (const float*)d_in[19];
    const float* c1W    = (const float*)d_in[20];
    const float* c1b    = (const float*)d_in[21];
    const float* c2W    = (const float*)d_in[22];
    const float* c2b    = (const float*)d_in[23];
    const float* c3W    = (const float*)d_in[24];
    const float* c3b    = (const float*)d_in[25];
    const float* ccW    = (const float*)d_in[26];
    const float* ccb    = (const float*)d_in[27];
    const float* outW   = (const float*)d_in[28];
    const float* outb   = (const float*)d_in[29];
    float* out = (float*)d_out;

    float *pXq,*pXd,*pxgq,*pxgd,*pencq,*pencd,*ppq,*ppdT,*ps3,*ps5,*ps7;
    cudaGetSymbolAddress((void**)&pXq,  g_Xq);
    cudaGetSymbolAddress((void**)&pXd,  g_Xd);
    cudaGetSymbolAddress((void**)&pxgq, g_xgq);
    cudaGetSymbolAddress((void**)&pxgd, g_xgd);
    cudaGetSymbolAddress((void**)&pencq,g_encq);
    cudaGetSymbolAddress((void**)&pencd,g_encd);
    cudaGetSymbolAddress((void**)&ppq,  g_pq);
    cudaGetSymbolAddress((void**)&ppdT, g_pdT);
    cudaGetSymbolAddress((void**)&ps3,  g_s3);
    cudaGetSymbolAddress((void**)&ps5,  g_s5);
    cudaGetSymbolAddress((void**)&ps7,  g_s7);
    float *pqb,*pdb;
    cudaGetSymbolAddress((void**)&pqb,  g_qb);
    cudaGetSymbolAddress((void**)&pdb,  g_db);

    cudaFuncSetAttribute(lstm_persist, cudaFuncAttributeMaxDynamicSharedMemorySize, LSTM_SMEM);
    cudaFuncSetAttribute(gemm_tf32<true,false,true,0>,  cudaFuncAttributeMaxDynamicSharedMemorySize, GEMM_DSM);
    cudaFuncSetAttribute(gemm_tf32<false,true,true,0>,  cudaFuncAttributeMaxDynamicSharedMemorySize, GEMM_DSM);
    cudaFuncSetAttribute(gemm_tf32<false,false,false,0>,cudaFuncAttributeMaxDynamicSharedMemorySize, GEMM_DSM);
    cudaFuncSetAttribute(gemm_tf32<false,false,false,1>,cudaFuncAttributeMaxDynamicSharedMemorySize, GEMM_DSM);
    cudaFuncSetAttribute(convgemm_k<3>, cudaFuncAttributeMaxDynamicSharedMemorySize, CONV_DSM);
    cudaFuncSetAttribute(convgemm_k<5>, cudaFuncAttributeMaxDynamicSharedMemorySize, CONV_DSM);
    cudaFuncSetAttribute(convgemm_k<7>, cudaFuncAttributeMaxDynamicSharedMemorySize, CONV_DSM);

    bias_sum_k<<<4,256>>>(qbih,qbhh,dbih,dbhh);

    // embed + proj (tf32):  X = emb[tok] @ projW + projb
    gemm_tf32<true,false,true,0><<<dim3(3,4),256,GEMM_DSM>>>(emb,bqtok,Ff, projW,Ff, projb, pXq,Ff, NTQ,Ff,Ff);
    gemm_tf32<true,false,true,0><<<dim3(3,320),256,GEMM_DSM>>>(emb,bdtok,Ff, projW,Ff, projb, pXd,Ff, NTD,Ff,Ff);

    // input gates: xg = X @ Wih^T + (bih+bhh)
    gemm_tf32<false,true,true,0><<<dim3(8,4),256,GEMM_DSM>>>(pXq,nullptr,Ff, qWih,Ff, pqb, pxgq,G4, NTQ,G4,Ff);
    gemm_tf32<false,true,true,0><<<dim3(8,320),256,GEMM_DSM>>>(pXd,nullptr,Ff, dWih,Ff, pdb, pxgd,G4, NTD,G4,Ff);

    // persistent LSTMs (clusters of 8 h-blocks; query: 1 cluster, doc: 10)
    lstm_persist<<<8,256,LSTM_SMEM>>>(pxgq, qWhh, pencq, QLn);
    lstm_persist<<<80,256,LSTM_SMEM>>>(pxgd, dWhh, pencd, DLn);

    // projections: pq [512,50]; pd transposed per image [img][c][dl]
    gemm_tf32<false,false,false,0><<<dim3(1,4),256,GEMM_DSM>>>(pencq,nullptr,Hh, qpW,Cc, qpb, ppq,Cc, NTQ,Cc,Hh);
    gemm_tf32<false,false,false,1><<<dim3(1,320),256,GEMM_DSM>>>(pencd,nullptr,Hh, dpW,Cc, dpb, ppdT,0, NTD,Cc,Hh);

    // conv stage 1 (padded)
    {
        long t3 = (long)Bq*NFc*QLn*152, t5 = (long)Bq*NFc*QLn*252, t7 = (long)Bq*NFc*QLn*352;
        s_k<<<(unsigned)((t3+255)/256),256>>>(c1W, ps3, 3, 152, t3);
        s_k<<<(unsigned)((t5+255)/256),256>>>(c2W, ps5, 5, 252, t5);
        s_k<<<(unsigned)((t7+255)/256),256>>>(c3W, ps7, 7, 352, t7);
    }
    // conv stage 2 (resident-B tf32 GEMM + exact-match + relu)
    convgemm_k<3><<<dim3(7,BD),256,CONV_DSM>>>(ps3, c1W, c1b, bqtok, bdtok, alpha, 0);
    convgemm_k<5><<<dim3(7,BD),256,CONV_DSM>>>(ps5, c2W, c2b, bqtok, bdtok, alpha, 50);
    convgemm_k<7><<<dim3(7,BD),256,CONV_DSM>>>(ps7, c3W, c3b, bqtok, bdtok, alpha, 100);

    // 1x1 conv + maxpool + output linear
    score_k<<<BD,256>>>(ccW, ccb, outW, outb, out);
}

// round 8
// speedup vs baseline: 3.1159x; 1.3661x over previous
#include <cuda_runtime.h>
#include <math.h>

// ---------------- problem constants ----------------
#define Bq  32
#define Dn  10
#define QLn 16
#define DLn 128
#define BD  320
#define Ff  300
#define Hh  256
#define G4  1024
#define Cc  50
#define NFc 50
#define MFc 20
#define NTQ (Bq*QLn)      // 512
#define NTD (BD*DLn)      // 40960

// ---------------- device scratch ----------------
__device__ float g_Xq[NTQ*Ff];
__device__ float g_Xd[(size_t)NTD*Ff];
__device__ float g_xgq[(size_t)NTQ*G4];
__device__ float g_xgd[(size_t)NTD*G4];
__device__ float g_encq[NTQ*Hh];
__device__ float g_encd[(size_t)NTD*Hh];
__device__ float g_pq[NTQ*Cc];
__device__ float g_pdT[(size_t)BD*Cc*DLn];
__device__ float g_s3[(size_t)Bq*NFc*QLn*152 + 16];
__device__ float g_s5[(size_t)Bq*NFc*QLn*252 + 16];
__device__ float g_s7[(size_t)Bq*NFc*QLn*352 + 16];
__device__ float g_f[(size_t)BD*150*QLn*DLn];
__device__ float g_qb[G4];
__device__ float g_db[G4];

__device__ __forceinline__ float tha(float x){
    float y; asm("tanh.approx.f32 %0, %1;" : "=f"(y) : "f"(x)); return y;
}
__device__ __forceinline__ float sigf(float x){ return fmaf(tha(0.5f*x), 0.5f, 0.5f); }

__device__ __forceinline__ void mma8(float* c, const unsigned* a, const unsigned* b){
    asm volatile("mma.sync.aligned.m16n8k8.row.col.f32.tf32.tf32.f32 "
        "{%0,%1,%2,%3}, {%4,%5,%6,%7}, {%8,%9}, {%0,%1,%2,%3};"
        : "+f"(c[0]),"+f"(c[1]),"+f"(c[2]),"+f"(c[3])
        : "r"(a[0]),"r"(a[1]),"r"(a[2]),"r"(a[3]), "r"(b[0]),"r"(b[1]));
}
__device__ __forceinline__ unsigned sptr(const void* p){
    return (unsigned)__cvta_generic_to_shared(p);
}
__device__ __forceinline__ void cpa16(unsigned dst, const void* src, bool pred){
    int sz = pred ? 16 : 0;
    asm volatile("cp.async.cg.shared.global [%0], [%1], 16, %2;" :: "r"(dst), "l"(src), "r"(sz));
}
#define CP_COMMIT() asm volatile("cp.async.commit_group;")
#define CP_WAIT0()  asm volatile("cp.async.wait_group 0;")
#define CP_WAIT1()  asm volatile("cp.async.wait_group 1;")
#define CLUSTER_ARRIVE() asm volatile("barrier.cluster.arrive.aligned;" ::: "memory")
#define CLUSTER_WAIT()   asm volatile("barrier.cluster.wait.aligned;" ::: "memory")

// ---------------- bias precombine ----------------
__global__ void bias_sum_k(const float* __restrict__ qb1, const float* __restrict__ qb2,
                           const float* __restrict__ db1, const float* __restrict__ db2)
{
    int t = blockIdx.x*blockDim.x + threadIdx.x;
    if (t < G4){ g_qb[t] = qb1[t]+qb2[t]; g_db[t] = db1[t]+db2[t]; }
}

// ---------------- dual-side 3-stage pipelined tf32 GEMM ----------------
struct GS {
    const float* A; const int* idx; const float* Bm; const float* bias;
    float* C; int M; int ldc; int store;   // store 0: C[m*ldc+n]; 1: pdT layout
};
#define GEMM_DSM (6*2560*4)
template<bool GATHER, bool BT, bool BASYNC>
__global__ __launch_bounds__(256,2) void gemm_dual(
    GS s1, GS s2, int ysplit, int lda, int ldb, int N, int K)
{
    extern __shared__ float dsm[];
    float* Asm = dsm;            // 3 stages x [128][20]
    float* Bsm = dsm + 3*2560;   // 3 stages x 2560 (BT: [n*20+k]; !BT: [k*132+n])
    int tid = threadIdx.x;
    int lane = tid & 31, warp = tid >> 5;
    int wm = warp >> 2, wn = warp & 3;
    bool side2 = ((int)blockIdx.y >= ysplit);
    const float* A_   = side2 ? s2.A    : s1.A;
    const int*   idx_ = side2 ? s2.idx  : s1.idx;
    const float* Bm_  = side2 ? s2.Bm   : s1.Bm;
    const float* bias = side2 ? s2.bias : s1.bias;
    float*       C    = side2 ? s2.C    : s1.C;
    int M    = side2 ? s2.M    : s1.M;
    int ldc  = side2 ? s2.ldc  : s1.ldc;
    int store= side2 ? s2.store: s1.store;
    int by = (int)blockIdx.y - (side2 ? ysplit : 0);
    int m0 = by*128, n0 = blockIdx.x*128;
    int nk = (K + 15) >> 4;
    int r8 = lane>>2, q4 = lane&3;

    int arow = tid >> 1;
    int acp  = (tid & 1) * 8;
    bool mrowok = (m0 + arow) < M;
    const float* Arow;
    { long r = GATHER ? (long)idx_[m0 + (mrowok ? arow : 0)] : (long)(m0 + (mrowok ? arow : 0));
      Arow = A_ + r*(long)lda; }

    bool nrowok = (n0 + arow) < N;
    const float* Brow = Bm_ + (size_t)(n0 + (nrowok ? arow : 0))*(BT ? ldb : 0);
    int bkr = tid >> 4, bnf = (tid & 15)*8;

    auto issue = [&](int kt, int buf){
        int k0 = kt*16;
        unsigned d = sptr(Asm + buf*2560 + arow*20 + acp);
        cpa16(d,    Arow + k0 + acp,     mrowok && (k0+acp)   < K);
        cpa16(d+16, Arow + k0 + acp + 4, mrowok && (k0+acp+4) < K);
        if (BASYNC){
            if (BT){
                unsigned db = sptr(Bsm + buf*2560 + arow*20 + acp);
                cpa16(db,    Brow + k0 + acp,     nrowok && (k0+acp)   < K);
                cpa16(db+16, Brow + k0 + acp + 4, nrowok && (k0+acp+4) < K);
            } else {
                const float* src = Bm_ + (size_t)(k0+bkr)*ldb + n0 + bnf;
                unsigned db = sptr(Bsm + buf*2560 + bkr*132 + bnf);
                bool kok = (k0+bkr) < K;
                cpa16(db,    src,   kok && (n0+bnf)   < N);
                cpa16(db+16, src+4, kok && (n0+bnf+4) < N);
            }
        }
        CP_COMMIT();
    };

    float bv[8];
    int nc = (tid&31)*4, kr = tid>>5;
    auto ldgB = [&](int kt){
        int k0 = kt*16;
        #pragma unroll
        for (int h=0;h<2;h++){
            int kk = k0 + kr + h*8;
            #pragma unroll
            for (int j=0;j<4;j++){
                int n = n0 + nc + j;
                bv[h*4+j] = (kk < K && n < N) ? Bm_[(size_t)kk*ldb + n] : 0.f;
            }
        }
    };
    auto stsB = [&](int buf){
        #pragma unroll
        for (int h=0;h<2;h++)
            #pragma unroll
            for (int j=0;j<4;j++) Bsm[buf*2560 + (kr+h*8)*132 + nc+j] = bv[h*4+j];
    };

    float acc[4][4][4] = {};

    issue(0,0);
    if (nk > 1) issue(1,1);
    if (!BASYNC) ldgB(0);

    int buf = 0;
    for (int kt = 0; kt < nk; kt++){
        if (kt >= nk-1) CP_WAIT0(); else CP_WAIT1();
        __syncthreads();
        if (!BASYNC) stsB(buf);
        if (kt+2 < nk) issue(kt+2, buf == 0 ? 2 : buf-1);
        if (!BASYNC){
            if (kt+1 < nk) ldgB(kt+1);
            __syncthreads();
        }
        const float* Ab2 = Asm + buf*2560;
        const float* Bb2 = Bsm + buf*2560;
        #pragma unroll
        for (int kb=0; kb<2; kb++){
            int ko = kb*8;
            unsigned af[4][4], bf[4][2];
            #pragma unroll
            for (int mt=0; mt<4; mt++){
                int rb = wm*64 + mt*16;
                af[mt][0] = __float_as_uint(Ab2[(rb+r8  )*20 + ko+q4  ]);
                af[mt][1] = __float_as_uint(Ab2[(rb+r8+8)*20 + ko+q4  ]);
                af[mt][2] = __float_as_uint(Ab2[(rb+r8  )*20 + ko+q4+4]);
                af[mt][3] = __float_as_uint(Ab2[(rb+r8+8)*20 + ko+q4+4]);
            }
            #pragma unroll
            for (int nt=0; nt<4; nt++){
                int nb = wn*32 + nt*8;
                if (BT){
                    bf[nt][0] = __float_as_uint(Bb2[(nb+r8)*20 + ko+q4  ]);
                    bf[nt][1] = __float_as_uint(Bb2[(nb+r8)*20 + ko+q4+4]);
                } else {
                    bf[nt][0] = __float_as_uint(Bb2[(ko+q4  )*132 + nb+r8]);
                    bf[nt][1] = __float_as_uint(Bb2[(ko+q4+4)*132 + nb+r8]);
                }
            }
            #pragma unroll
            for (int mt=0;mt<4;mt++)
                #pragma unroll
                for (int nt=0;nt<4;nt++)
                    mma8(acc[mt][nt], af[mt], bf[nt]);
        }
        buf = (buf == 2) ? 0 : buf+1;
    }

    #pragma unroll
    for (int mt=0;mt<4;mt++){
        int row = m0 + wm*64 + mt*16 + r8;
        #pragma unroll
        for (int nt=0;nt<4;nt++){
            int col = n0 + wn*32 + nt*8 + q4*2;
            const float* cc = acc[mt][nt];
            #pragma unroll
            for (int j=0;j<2;j++){
                int n = col + j;
                if (n >= N) continue;
                float bb = bias ? bias[n] : 0.f;
                float v0 = cc[j] + bb, v1 = cc[2+j] + bb;
                if (store == 0){
                    if (row < M)   C[(size_t)row*ldc + n] = v0;
                    if (row+8 < M) C[(size_t)(row+8)*ldc + n] = v1;
                } else {
                    int img = row >> 7;
                    C[((size_t)img*Cc + n)*DLn + (row & 127)] = v0;
                    C[((size_t)img*Cc + n)*DLn + ((row+8) & 127)] = v1;
                }
            }
        }
    }
}

// ---------------- persistent LSTM (merged: cluster 0 = query, 1..10 = doc) ----
#define LSTM_SMEM ((256*136 + 256*40)*4)
__global__ __cluster_dims__(8,1,1) __launch_bounds__(256,1) void lstm_persist(
    const float* __restrict__ xgq, const float* __restrict__ Whq, float* __restrict__ encq,
    const float* __restrict__ xgd, const float* __restrict__ Whd, float* __restrict__ encd)
{
    extern __shared__ unsigned smbuf[];
    unsigned* Bs = smbuf;                  // [256][136] tf32 Whh slice
    unsigned* As = smbuf + 256*136;        // [256][40]  h_prev
    float* Gs = (float*)As;                // [32][136]  overlay: gate preacts
    int tid = threadIdx.x;
    int lane = tid & 31, warp = tid >> 5;
    int r8 = lane >> 2, q4 = lane & 3;
    int wm = warp & 1, wn = warp >> 1;
    int cid = blockIdx.x >> 3, hb = blockIdx.x & 7;
    const float* xg; const float* Whh; float* enc; int T, n0;
    if (cid == 0){ xg = xgq; Whh = Whq; enc = encq; T = QLn; n0 = 0; }
    else        { xg = xgd; Whh = Whd; enc = encd; T = DLn; n0 = (cid-1)*32; }
    int h0 = hb * 32;

    for (int idx = tid; idx < 128*256; idx += 256){
        int j = idx >> 8, k = idx & 255;
        int r = ((j & 3) << 8) + h0 + (j >> 2);
        Bs[k*136 + j] = __float_as_uint(Whh[(size_t)r*Hh + k]);
    }
    __syncthreads();

    float creg[4] = {0.f, 0.f, 0.f, 0.f};

    for (int t = 0; t < T; t++){
        if (t == 0){
            for (int idx = tid; idx < 32*256; idx += 256)
                As[(idx & 255)*40 + (idx >> 8)] = 0u;
        } else {
            for (int idx = tid; idx < 32*256; idx += 256){
                int m = idx >> 8, k = idx & 255;
                As[k*40 + m] = __float_as_uint(enc[((size_t)(n0+m)*T + (t-1))*Hh + k]);
            }
        }
        __syncthreads();

        float acc[4][4] = {};
        int rb = wm*16;
        #pragma unroll 4
        for (int ko = 0; ko < 256; ko += 8){
            unsigned af[4];
            af[0] = As[(ko+q4)*40 + rb + r8];
            af[1] = As[(ko+q4)*40 + rb + r8 + 8];
            af[2] = As[(ko+q4+4)*40 + rb + r8];
            af[3] = As[(ko+q4+4)*40 + rb + r8 + 8];
            #pragma unroll
            for (int nt = 0; nt < 4; nt++){
                int nb = wn*32 + nt*8;
                unsigned bf[2];
                bf[0] = Bs[(ko+q4)*136 + nb + r8];
                bf[1] = Bs[(ko+q4+4)*136 + nb + r8];
                mma8(acc[nt], af, bf);
            }
        }
        __syncthreads();
        #pragma unroll
        for (int nt = 0; nt < 4; nt++){
            int col = wn*32 + nt*8 + q4*2;
            Gs[(rb+r8)*136 + col]     = acc[nt][0];
            Gs[(rb+r8)*136 + col+1]   = acc[nt][1];
            Gs[(rb+r8+8)*136 + col]   = acc[nt][2];
            Gs[(rb+r8+8)*136 + col+1] = acc[nt][3];
        }
        __syncthreads();

        #pragma unroll
        for (int it = 0; it < 4; it++){
            int id = tid + it*256;
            int m = id >> 5, hp = id & 31;
            int n = n0 + m, h = h0 + hp;
            size_t tok = (size_t)n*T + t;
            const float* xb = xg + tok*(size_t)G4;
            float4 g = *(const float4*)&Gs[m*136 + hp*4];
            float gi = g.x + xb[h];
            float gf = g.y + xb[Hh + h];
            float gg = g.z + xb[2*Hh + h];
            float go = g.w + xb[3*Hh + h];
            float cv = sigf(gf)*creg[it] + sigf(gi)*tha(gg);
            creg[it] = cv;
            enc[tok*Hh + h] = sigf(go)*tha(cv);
        }
        __threadfence();
        CLUSTER_ARRIVE();
        CLUSTER_WAIT();
    }
}

// ---------------- conv stage 1 (merged 3 convs via blockIdx.y) ----------------
__global__ void s_k(const float* __restrict__ c1W, const float* __restrict__ c2W,
                    const float* __restrict__ c3W,
                    float* __restrict__ s3, float* __restrict__ s5, float* __restrict__ s7)
{
    int z = blockIdx.y;
    int KW = 3 + 2*z, KP = 152 + 100*z;
    const float* cW = (z==0) ? c1W : (z==1) ? c2W : c3W;
    float* s = (z==0) ? s3 : (z==1) ? s5 : s7;
    long total = (long)Bq*NFc*QLn*KP;
    long i = (long)blockIdx.x*blockDim.x + threadIdx.x;
    if (i >= total) return;
    int kk = (int)(i % KP);
    long r = i / KP;
    int q  = (int)(r % QLn); r /= QLn;
    int o  = (int)(r % NFc);
    int b  = (int)(r / NFc);
    float v = 0.f;
    if (kk < Cc*KW){
        int dd = kk / Cc, c = kk - dd*Cc;
        #pragma unroll
        for (int dq = 0; dq < 3; dq++){
            int qq = q + dq - 1;
            if (qq >= 0 && qq < QLn)
                v += cW[(((size_t)o*51 + c)*3 + dq)*KW + dd] * g_pq[((size_t)b*QLn + qq)*Cc + c];
        }
    }
    s[i] = v;
}

// ---------------- conv stage 2: merged (blockIdx.z), resident-B, 3-stage A ----
#define CONV_DSM ((3*2560 + 50*132)*4)
__global__ __launch_bounds__(256,2) void convgemm_k(
    const float* __restrict__ sA3, const float* __restrict__ sA5, const float* __restrict__ sA7,
    const float* __restrict__ c1W, const float* __restrict__ c1b,
    const float* __restrict__ c2W, const float* __restrict__ c2b,
    const float* __restrict__ c3W, const float* __restrict__ c3b,
    const int* __restrict__ bqtok, const int* __restrict__ bdtok,
    const float* __restrict__ alpha)
{
    int z = blockIdx.z;
    const int KW = 3 + 2*z, KP = 152 + 100*z, PW = KW >> 1, OCB = z*50;
    const int nk = (KP + 15) >> 4;
    const float* sA = (z==0) ? sA3 : (z==1) ? sA5 : sA7;
    const float* cW = (z==0) ? c1W : (z==1) ? c2W : c3W;
    const float* cb = (z==0) ? c1b : (z==1) ? c2b : c3b;
    extern __shared__ float dsm[];
    float* Asm = dsm;              // 3 stages x [128][20]
    float* pdt = dsm + 3*2560;     // [50][132]
    __shared__ float ems[18][136];
    __shared__ float wem[8][21];
    __shared__ int qt[16], dt[128], s_any;
    int tid = threadIdx.x;
    int lane = tid & 31, warp = tid >> 5;
    int wm = warp >> 2, wn = warp & 3;
    int img = blockIdx.y, b = img / Dn;
    int m0 = blockIdx.x*128, obase = m0 >> 4;
    int r8 = lane>>2, q4 = lane&3;

    const float* Pd = &g_pdT[(size_t)img*Cc*DLn];
    int arow = tid >> 1, acp = (tid & 1)*8;
    bool mok = (m0 + arow) < 800;
    const float* Arow = sA + ((size_t)b*800 + (mok ? m0+arow : 0))*KP;

    auto issueA = [&](int kt, int buf){
        int k0 = kt*16;
        unsigned d = sptr(Asm + buf*2560 + arow*20 + acp);
        cpa16(d,    Arow + k0 + acp,     mok && (k0+acp)   < KP);
        cpa16(d+16, Arow + k0 + acp + 4, mok && (k0+acp+4) < KP);
    };

    for (int ch = tid; ch < 1600; ch += 256){
        int row = ch >> 5, off = (ch & 31) * 4;
        cpa16(sptr(pdt + row*132 + off), Pd + row*128 + off, true);
    }
    issueA(0,0); CP_COMMIT();
    issueA(1,1); CP_COMMIT();

    if (tid == 0) s_any = 0;
    if (tid < 16) qt[tid] = bqtok[b*QLn + tid];
    if (tid < 128) dt[tid] = bdtok[(size_t)img*DLn + tid];
    if (tid < 8*3*KW){
        int ol = tid/(3*KW), rr = tid%(3*KW);
        int o = obase + ol;
        wem[ol][rr] = (o < NFc) ? cW[(((size_t)o*51 + 50)*3 + rr/KW)*KW + rr%KW] : 0.f;
    }
    __syncthreads();
    float al = alpha[0];
    for (int e = tid; e < 18*136; e += 256){
        int qi = e/136, dj = e%136;
        int q = qi-1, dl = dj-3;
        float v = 0.f;
        if (q >= 0 && q < QLn && dl >= 0 && dl < DLn && qt[q] == dt[dl]){ v = al; s_any = 1; }
        ems[qi][dj] = v;
    }

    float acc[4][4][4] = {};
    int buf = 0;
    for (int kt = 0; kt < nk; kt++){
        if (kt >= nk-1) CP_WAIT0(); else CP_WAIT1();
        __syncthreads();
        if (kt+2 < nk){ issueA(kt+2, buf == 0 ? 2 : buf-1); CP_COMMIT(); }
        const float* Ab2 = Asm + buf*2560;
        #pragma unroll
        for (int kb=0; kb<2; kb++){
            int ko = kb*8;
            int ka = kt*16 + ko + q4;
            int k2 = ka + 4;
            int dda = ka/Cc, ca = ka - dda*Cc;
            int ddb = k2/Cc, cbb = k2 - ddb*Cc;
            unsigned af[4][4], bf[4][2];
            #pragma unroll
            for (int mt=0; mt<4; mt++){
                int rb = wm*64 + mt*16;
                af[mt][0] = __float_as_uint(Ab2[(rb+r8  )*20 + ko+q4  ]);
                af[mt][1] = __float_as_uint(Ab2[(rb+r8+8)*20 + ko+q4  ]);
                af[mt][2] = __float_as_uint(Ab2[(rb+r8  )*20 + ko+q4+4]);
                af[mt][3] = __float_as_uint(Ab2[(rb+r8+8)*20 + ko+q4+4]);
            }
            #pragma unroll
            for (int nt=0; nt<4; nt++){
                int col = wn*32 + nt*8 + r8;
                int sa = col + dda - PW;
                int sb = col + ddb - PW;
                bf[nt][0] = ((unsigned)sa < 128u) ? __float_as_uint(pdt[ca*132 + sa]) : 0u;
                bf[nt][1] = ((unsigned)sb < 128u) ? __float_as_uint(pdt[cbb*132 + sb]) : 0u;
            }
            #pragma unroll
            for (int mt=0;mt<4;mt++)
                #pragma unroll
                for (int nt=0;nt<4;nt++)
                    mma8(acc[mt][nt], af[mt], bf[nt]);
        }
        buf = (buf == 2) ? 0 : buf+1;
    }

    int any = s_any;
    #pragma unroll
    for (int mt=0;mt<4;mt++){
        int row = m0 + wm*64 + mt*16;
        if (row >= 800) continue;
        int o = row >> 4, ol = o - obase;
        float bias = cb[o];
        #pragma unroll
        for (int rr=0; rr<2; rr++){
            int q = r8 + rr*8;
            #pragma unroll
            for (int nt=0;nt<4;nt++){
                int col = wn*32 + nt*8 + q4*2;
                #pragma unroll
                for (int j=0;j<2;j++){
                    int dl = col + j;
                    float v = acc[mt][nt][rr*2 + j] + bias;
                    if (any){
                        for (int dq = 0; dq < 3; dq++)
                            for (int dd = 0; dd < KW; dd++)
                                v += wem[ol][dq*KW+dd] * ems[q+dq][dl+dd+3-PW];
                    }
                    v = fmaxf(v, 0.f);
                    g_f[(((size_t)img*150 + OCB + o)*QLn + q)*DLn + dl] = v;
                }
            }
        }
    }
}

// ---------------- 1x1 conv + maxpool + linear (tf32 mma) ----------------
// C[32pad][2048] = W[20][150] @ f[150][2048]; bias+max folded, then dot out_W.
#define SCORE_DSM ((3*8*264 + 152*36)*4)
__global__ __launch_bounds__(256,2) void score_k(
    const float* __restrict__ ccW, const float* __restrict__ ccb,
    const float* __restrict__ outW, const float* __restrict__ outb,
    float* __restrict__ out)
{
    extern __shared__ float dsm[];
    float* fs = dsm;               // 3 stages x [8][264]
    float* Ws = dsm + 3*8*264;     // [152][36]: Ws[k*36+m]
    __shared__ float red[32][8];
    __shared__ float part[32];
    int img = blockIdx.x, tid = threadIdx.x;
    int lane = tid & 31, warp = tid >> 5;
    int r8 = lane >> 2, q4 = lane & 3;

    for (int idx = tid; idx < 152*32; idx += 256){
        int m = idx & 31, k = idx >> 5;
        Ws[k*36 + m] = (m < MFc && k < 150) ? ccW[m*150 + k] : 0.f;
    }

    const float* fimg = &g_f[(size_t)img*150*2048];
    auto issue = [&](int kt, int pch, int buf){
        #pragma unroll
        for (int h = 0; h < 2; h++){
            int ch = tid + 256*h;
            int row = ch >> 6, off = (ch & 63)*4;
            int kr = kt*8 + row;
            cpa16(sptr(fs + buf*2112 + row*264 + off),
                  fimg + (size_t)kr*2048 + pch*256 + off, kr < 150);
        }
        CP_COMMIT();
    };

    float bb0 = (r8      < MFc) ? ccb[r8]      : 0.f;
    float bb0b= (r8+8    < MFc) ? ccb[r8+8]    : 0.f;
    // rows: mt*16 + r8 (+8). mt=1 rows >= 16: 16+r8 (r8<4 -> <20)
    float maxv[2][2] = {{-1e30f,-1e30f},{-1e30f,-1e30f}};
    __syncthreads();   // Ws ready

    for (int pch = 0; pch < 8; pch++){
        float acc[2][4][4] = {};
        issue(0, pch, 0);
        issue(1, pch, 1);
        int buf = 0;
        for (int kt = 0; kt < 19; kt++){
            if (kt >= 17) CP_WAIT0(); else CP_WAIT1();
            __syncthreads();
            if (kt+2 < 19) issue(kt+2, pch, buf == 0 ? 2 : buf-1);
            const float* fb2 = fs + buf*2112;
            unsigned af[2][4];
            #pragma unroll
            for (int mt=0; mt<2; mt++){
                int mb = mt*16;
                af[mt][0] = __float_as_uint(Ws[(kt*8+q4  )*36 + mb+r8]);
                af[mt][1] = __float_as_uint(Ws[(kt*8+q4  )*36 + mb+r8+8]);
                af[mt][2] = __float_as_uint(Ws[(kt*8+q4+4)*36 + mb+r8]);
                af[mt][3] = __float_as_uint(Ws[(kt*8+q4+4)*36 + mb+r8+8]);
            }
            #pragma unroll
            for (int nt=0; nt<4; nt++){
                int nb = warp*32 + nt*8;
                unsigned bf[2];
                bf[0] = __float_as_uint(fb2[(q4  )*264 + nb+r8]);
                bf[1] = __float_as_uint(fb2[(q4+4)*264 + nb+r8]);
                #pragma unroll
                for (int mt=0; mt<2; mt++)
                    mma8(acc[mt][nt], af[mt], bf);
            }
            buf = (buf == 2) ? 0 : buf+1;
            __syncthreads();
        }
        #pragma unroll
        for (int mt=0; mt<2; mt++){
            float b0 = (mt==0) ? bb0  : ((16+r8 < MFc) ? ccb[16+r8] : 0.f);
            float b1 = (mt==0) ? bb0b : 0.f;
            #pragma unroll
            for (int nt=0; nt<4; nt++){
                float* cc = acc[mt][nt];
                maxv[mt][0] = fmaxf(maxv[mt][0], fmaxf(cc[0], cc[1]) + b0);
                maxv[mt][1] = fmaxf(maxv[mt][1], fmaxf(cc[2], cc[3]) + b1);
            }
        }
    }
    // reduce over q4 (lanes 4*r8+q4)
    #pragma unroll
    for (int mt=0; mt<2; mt++)
        #pragma unroll
        for (int h=0; h<2; h++){
            float v = maxv[mt][h];
            v = fmaxf(v, __shfl_xor_sync(0xFFFFFFFFu, v, 1));
            v = fmaxf(v, __shfl_xor_sync(0xFFFFFFFFu, v, 2));
            maxv[mt][h] = v;
        }
    if (q4 == 0){
        #pragma unroll
        for (int mt=0; mt<2; mt++)
            #pragma unroll
            for (int h=0; h<2; h++)
                red[mt*16 + h*8 + r8][warp] = maxv[mt][h];
    }
    __syncthreads();
    if (tid < 32){
        float m = red[tid][0];
        #pragma unroll
        for (int w = 1; w < 8; w++) m = fmaxf(m, red[tid][w]);
        part[tid] = (tid < MFc) ? m * outW[tid] : 0.f;
    }
    __syncthreads();
    if (tid == 0){
        float sc = outb[0];
        #pragma unroll
        for (int mf = 0; mf < MFc; mf++) sc += part[mf];
        out[img] = sc;
    }
}

// ---------------- launch ----------------
extern "C" void kernel_launch(void* const* d_in, const int* in_sizes, int n_in,
                              void* d_out, int out_size)
{
    const int* bqtok = nullptr; const int* bdtok = nullptr;
    for (int i = 0; i < 4; i++){
        if (in_sizes[i] == NTQ)      bqtok = (const int*)d_in[i];
        else if (in_sizes[i] == NTD) bdtok = (const int*)d_in[i];
    }
    const float* emb    = (const float*)d_in[4];
    const float* projW  = (const float*)d_in[5];
    const float* projb  = (const float*)d_in[6];
    const float* qWih   = (const float*)d_in[7];
    const float* qWhh   = (const float*)d_in[8];
    const float* qbih   = (const float*)d_in[9];
    const float* qbhh   = (const float*)d_in[10];
    const float* dWih   = (const float*)d_in[11];
    const float* dWhh   = (const float*)d_in[12];
    const float* dbih   = (const float*)d_in[13];
    const float* dbhh   = (const float*)d_in[14];
    const float* qpW    = (const float*)d_in[15];
    const float* qpb    = (const float*)d_in[16];
    const float* dpW    = (const float*)d_in[17];
    const float* dpb    = (const float*)d_in[18];
    const float* alpha  = (const float*)d_in[19];
    const float* c1W    = (const float*)d_in[20];
    const float* c1b    = (const float*)d_in[21];
    const float* c2W    = (const float*)d_in[22];
    const float* c2b    = (const float*)d_in[23];
    const float* c3W    = (const float*)d_in[24];
    const float* c3b    = (const float*)d_in[25];
    const float* ccW    = (const float*)d_in[26];
    const float* ccb    = (const float*)d_in[27];
    const float* outW   = (const float*)d_in[28];
    const float* outb   = (const float*)d_in[29];
    float* out = (float*)d_out;

    float *pXq,*pXd,*pxgq,*pxgd,*pencq,*pencd,*ppq,*ppdT,*ps3,*ps5,*ps7,*pqb,*pdb;
    cudaGetSymbolAddress((void**)&pXq,  g_Xq);
    cudaGetSymbolAddress((void**)&pXd,  g_Xd);
    cudaGetSymbolAddress((void**)&pxgq, g_xgq);
    cudaGetSymbolAddress((void**)&pxgd, g_xgd);
    cudaGetSymbolAddress((void**)&pencq,g_encq);
    cudaGetSymbolAddress((void**)&pencd,g_encd);
    cudaGetSymbolAddress((void**)&ppq,  g_pq);
    cudaGetSymbolAddress((void**)&ppdT, g_pdT);
    cudaGetSymbolAddress((void**)&ps3,  g_s3);
    cudaGetSymbolAddress((void**)&ps5,  g_s5);
    cudaGetSymbolAddress((void**)&ps7,  g_s7);
    cudaGetSymbolAddress((void**)&pqb,  g_qb);
    cudaGetSymbolAddress((void**)&pdb,  g_db);

    cudaFuncSetAttribute(lstm_persist, cudaFuncAttributeMaxDynamicSharedMemorySize, LSTM_SMEM);
    cudaFuncSetAttribute(gemm_dual<true,false,true>,  cudaFuncAttributeMaxDynamicSharedMemorySize, GEMM_DSM);
    cudaFuncSetAttribute(gemm_dual<false,true,true>,  cudaFuncAttributeMaxDynamicSharedMemorySize, GEMM_DSM);
    cudaFuncSetAttribute(gemm_dual<false,false,false>,cudaFuncAttributeMaxDynamicSharedMemorySize, GEMM_DSM);
    cudaFuncSetAttribute(convgemm_k, cudaFuncAttributeMaxDynamicSharedMemorySize, CONV_DSM);
    cudaFuncSetAttribute(score_k, cudaFuncAttributeMaxDynamicSharedMemorySize, SCORE_DSM);

    bias_sum_k<<<4,256>>>(qbih,qbhh,dbih,dbhh);

    // embed + proj (dual): X = emb[tok] @ projW + projb
    { GS s1{emb, bqtok, projW, projb, pXq, NTQ, Ff, 0};
      GS s2{emb, bdtok, projW, projb, pXd, NTD, Ff, 0};
      gemm_dual<true,false,true><<<dim3(3,324),256,GEMM_DSM>>>(s1,s2,4, Ff,Ff, Ff,Ff); }

    // input gates (dual): xg = X @ Wih^T + (bih+bhh)
    { GS s1{pXq, nullptr, qWih, pqb, pxgq, NTQ, G4, 0};
      GS s2{pXd, nullptr, dWih, pdb, pxgd, NTD, G4, 0};
      gemm_dual<false,true,true><<<dim3(8,324),256,GEMM_DSM>>>(s1,s2,4, Ff,Ff, G4,Ff); }

    // persistent LSTMs (merged: 11 clusters x 8 blocks)
    lstm_persist<<<88,256,LSTM_SMEM>>>(pxgq, qWhh, pencq, pxgd, dWhh, pencd);

    // projections (dual): pq [512,50]; pdT per image
    { GS s1{pencq, nullptr, qpW, qpb, ppq,  NTQ, Cc, 0};
      GS s2{pencd, nullptr, dpW, dpb, ppdT, NTD, 0,  1};
      gemm_dual<false,false,false><<<dim3(1,324),256,GEMM_DSM>>>(s1,s2,4, Hh,Cc, Cc,Hh); }

    // conv stage 1 (merged)
    {
        long t7 = (long)Bq*NFc*QLn*352;
        s_k<<<dim3((unsigned)((t7+255)/256),3),256>>>(c1W,c2W,c3W, ps3,ps5,ps7);
    }
    // conv stage 2 (merged z-dispatch)
    convgemm_k<<<dim3(7,BD,3),256,CONV_DSM>>>(ps3,ps5,ps7, c1W,c1b, c2W,c2b, c3W,c3b,
                                              bqtok, bdtok, alpha);

    // 1x1 conv + maxpool + linear (tf32 mma)
    score_k<<<BD,256,SCORE_DSM>>>(ccW, ccb, outW, outb, out);
}

// round 9
// speedup vs baseline: 3.4346x; 1.1023x over previous
#include <cuda_runtime.h>
#include <math.h>

// ---------------- problem constants ----------------
#define Bq  32
#define Dn  10
#define QLn 16
#define DLn 128
#define BD  320
#define Ff  300
#define Hh  256
#define G4  1024
#define Cc  50
#define NFc 50
#define MFc 20
#define NTQ (Bq*QLn)      // 512
#define NTD (BD*DLn)      // 40960

// ---------------- device scratch ----------------
__device__ float g_Xq[NTQ*Ff];
__device__ float g_Xd[(size_t)NTD*Ff];
__device__ float g_xgq[(size_t)NTQ*G4];
__device__ float g_xgd[(size_t)NTD*G4];
__device__ float g_encq[NTQ*Hh];
__device__ float g_encd[(size_t)NTD*Hh];
__device__ float g_pq[NTQ*Cc];
__device__ float g_pdT[(size_t)BD*Cc*DLn];
__device__ float g_s3[(size_t)Bq*NFc*QLn*152 + 16];
__device__ float g_s5[(size_t)Bq*NFc*QLn*252 + 16];
__device__ float g_s7[(size_t)Bq*NFc*QLn*352 + 16];
__device__ float g_f[(size_t)BD*150*QLn*DLn];
__device__ float g_qb[G4];
__device__ float g_db[G4];

__device__ __forceinline__ float tha(float x){
    float y; asm("tanh.approx.f32 %0, %1;" : "=f"(y) : "f"(x)); return y;
}
__device__ __forceinline__ float sigf(float x){ return fmaf(tha(0.5f*x), 0.5f, 0.5f); }

__device__ __forceinline__ void mma8(float* c, const unsigned* a, const unsigned* b){
    asm volatile("mma.sync.aligned.m16n8k8.row.col.f32.tf32.tf32.f32 "
        "{%0,%1,%2,%3}, {%4,%5,%6,%7}, {%8,%9}, {%0,%1,%2,%3};"
        : "+f"(c[0]),"+f"(c[1]),"+f"(c[2]),"+f"(c[3])
        : "r"(a[0]),"r"(a[1]),"r"(a[2]),"r"(a[3]), "r"(b[0]),"r"(b[1]));
}
__device__ __forceinline__ unsigned sptr(const void* p){
    return (unsigned)__cvta_generic_to_shared(p);
}
__device__ __forceinline__ void cpa16(unsigned dst, const void* src, bool pred){
    int sz = pred ? 16 : 0;
    asm volatile("cp.async.cg.shared.global [%0], [%1], 16, %2;" :: "r"(dst), "l"(src), "r"(sz));
}
#define CP_COMMIT() asm volatile("cp.async.commit_group;")
#define CP_WAIT0()  asm volatile("cp.async.wait_group 0;")
#define CP_WAIT1()  asm volatile("cp.async.wait_group 1;")
#define CLUSTER_ARRIVE() asm volatile("barrier.cluster.arrive.aligned;" ::: "memory")
#define CLUSTER_WAIT()   asm volatile("barrier.cluster.wait.aligned;" ::: "memory")

// ---------------- bias precombine ----------------
__global__ void bias_sum_k(const float* __restrict__ qb1, const float* __restrict__ qb2,
                           const float* __restrict__ db1, const float* __restrict__ db2)
{
    int t = blockIdx.x*blockDim.x + threadIdx.x;
    if (t < G4){ g_qb[t] = qb1[t]+qb2[t]; g_db[t] = db1[t]+db2[t]; }
}

// ---------------- dual-side 3-stage pipelined tf32 GEMM ----------------
struct GS {
    const float* A; const int* idx; const float* Bm; const float* bias;
    float* C; int M; int ldc; int store;   // store 0: C[m*ldc+n]; 1: pdT layout
};
#define GEMM_DSM (6*2560*4)
template<bool GATHER, bool BT, bool BASYNC>
__global__ __launch_bounds__(256,2) void gemm_dual(
    GS s1, GS s2, int ysplit, int lda, int ldb, int N, int K)
{
    extern __shared__ float dsm[];
    float* Asm = dsm;            // 3 stages x [128][20]
    float* Bsm = dsm + 3*2560;   // 3 stages x 2560 (BT: [n*20+k]; !BT: [k*132+n])
    int tid = threadIdx.x;
    int lane = tid & 31, warp = tid >> 5;
    int wm = warp >> 2, wn = warp & 3;
    bool side2 = ((int)blockIdx.y >= ysplit);
    const float* A_   = side2 ? s2.A    : s1.A;
    const int*   idx_ = side2 ? s2.idx  : s1.idx;
    const float* Bm_  = side2 ? s2.Bm   : s1.Bm;
    const float* bias = side2 ? s2.bias : s1.bias;
    float*       C    = side2 ? s2.C    : s1.C;
    int M    = side2 ? s2.M    : s1.M;
    int ldc  = side2 ? s2.ldc  : s1.ldc;
    int store= side2 ? s2.store: s1.store;
    int by = (int)blockIdx.y - (side2 ? ysplit : 0);
    int m0 = by*128, n0 = blockIdx.x*128;
    int nk = (K + 15) >> 4;
    int r8 = lane>>2, q4 = lane&3;

    int arow = tid >> 1;
    int acp  = (tid & 1) * 8;
    bool mrowok = (m0 + arow) < M;
    const float* Arow;
    { long r = GATHER ? (long)idx_[m0 + (mrowok ? arow : 0)] : (long)(m0 + (mrowok ? arow : 0));
      Arow = A_ + r*(long)lda; }

    bool nrowok = (n0 + arow) < N;
    const float* Brow = Bm_ + (size_t)(n0 + (nrowok ? arow : 0))*(BT ? ldb : 0);
    int bkr = tid >> 4, bnf = (tid & 15)*8;

    auto issue = [&](int kt, int buf){
        int k0 = kt*16;
        unsigned d = sptr(Asm + buf*2560 + arow*20 + acp);
        cpa16(d,    Arow + k0 + acp,     mrowok && (k0+acp)   < K);
        cpa16(d+16, Arow + k0 + acp + 4, mrowok && (k0+acp+4) < K);
        if (BASYNC){
            if (BT){
                unsigned db = sptr(Bsm + buf*2560 + arow*20 + acp);
                cpa16(db,    Brow + k0 + acp,     nrowok && (k0+acp)   < K);
                cpa16(db+16, Brow + k0 + acp + 4, nrowok && (k0+acp+4) < K);
            } else {
                const float* src = Bm_ + (size_t)(k0+bkr)*ldb + n0 + bnf;
                unsigned db = sptr(Bsm + buf*2560 + bkr*132 + bnf);
                bool kok = (k0+bkr) < K;
                cpa16(db,    src,   kok && (n0+bnf)   < N);
                cpa16(db+16, src+4, kok && (n0+bnf+4) < N);
            }
        }
        CP_COMMIT();
    };

    float bv[8];
    int nc = (tid&31)*4, kr = tid>>5;
    auto ldgB = [&](int kt){
        int k0 = kt*16;
        #pragma unroll
        for (int h=0;h<2;h++){
            int kk = k0 + kr + h*8;
            #pragma unroll
            for (int j=0;j<4;j++){
                int n = n0 + nc + j;
                bv[h*4+j] = (kk < K && n < N) ? Bm_[(size_t)kk*ldb + n] : 0.f;
            }
        }
    };
    auto stsB = [&](int buf){
        #pragma unroll
        for (int h=0;h<2;h++)
            #pragma unroll
            for (int j=0;j<4;j++) Bsm[buf*2560 + (kr+h*8)*132 + nc+j] = bv[h*4+j];
    };

    float acc[4][4][4] = {};

    issue(0,0);
    if (nk > 1) issue(1,1);
    if (!BASYNC) ldgB(0);

    int buf = 0;
    for (int kt = 0; kt < nk; kt++){
        if (kt >= nk-1) CP_WAIT0(); else CP_WAIT1();
        __syncthreads();
        if (!BASYNC) stsB(buf);
        if (kt+2 < nk) issue(kt+2, buf == 0 ? 2 : buf-1);
        if (!BASYNC){
            if (kt+1 < nk) ldgB(kt+1);
            __syncthreads();
        }
        const float* Ab2 = Asm + buf*2560;
        const float* Bb2 = Bsm + buf*2560;
        #pragma unroll
        for (int kb=0; kb<2; kb++){
            int ko = kb*8;
            unsigned af[4][4], bf[4][2];
            #pragma unroll
            for (int mt=0; mt<4; mt++){
                int rb = wm*64 + mt*16;
                af[mt][0] = __float_as_uint(Ab2[(rb+r8  )*20 + ko+q4  ]);
                af[mt][1] = __float_as_uint(Ab2[(rb+r8+8)*20 + ko+q4  ]);
                af[mt][2] = __float_as_uint(Ab2[(rb+r8  )*20 + ko+q4+4]);
                af[mt][3] = __float_as_uint(Ab2[(rb+r8+8)*20 + ko+q4+4]);
            }
            #pragma unroll
            for (int nt=0; nt<4; nt++){
                int nb = wn*32 + nt*8;
                if (BT){
                    bf[nt][0] = __float_as_uint(Bb2[(nb+r8)*20 + ko+q4  ]);
                    bf[nt][1] = __float_as_uint(Bb2[(nb+r8)*20 + ko+q4+4]);
                } else {
                    bf[nt][0] = __float_as_uint(Bb2[(ko+q4  )*132 + nb+r8]);
                    bf[nt][1] = __float_as_uint(Bb2[(ko+q4+4)*132 + nb+r8]);
                }
            }
            #pragma unroll
            for (int mt=0;mt<4;mt++)
                #pragma unroll
                for (int nt=0;nt<4;nt++)
                    mma8(acc[mt][nt], af[mt], bf[nt]);
        }
        buf = (buf == 2) ? 0 : buf+1;
    }

    #pragma unroll
    for (int mt=0;mt<4;mt++){
        int row = m0 + wm*64 + mt*16 + r8;
        #pragma unroll
        for (int nt=0;nt<4;nt++){
            int col = n0 + wn*32 + nt*8 + q4*2;
            const float* cc = acc[mt][nt];
            #pragma unroll
            for (int j=0;j<2;j++){
                int n = col + j;
                if (n >= N) continue;
                float bb = bias ? bias[n] : 0.f;
                float v0 = cc[j] + bb, v1 = cc[2+j] + bb;
                if (store == 0){
                    if (row < M)   C[(size_t)row*ldc + n] = v0;
                    if (row+8 < M) C[(size_t)(row+8)*ldc + n] = v1;
                } else {
                    int img = row >> 7;
                    C[((size_t)img*Cc + n)*DLn + (row & 127)] = v0;
                    C[((size_t)img*Cc + n)*DLn + ((row+8) & 127)] = v1;
                }
            }
        }
    }
}

// ---------------- persistent LSTM (merged; prefetched, shfl epilogue) ----------
// Bs: [256][136] Whh slice (k-major). As: [32][260] h_prev (m-major, k-contig).
// xs: [32][132] xg slice for current step: xs[m][g*32+hp].
#define LSTM_BS_W  (256*136)
#define LSTM_AS_W  (32*260)
#define LSTM_XS_W  (32*132)
#define LSTM_SMEM  ((LSTM_BS_W + LSTM_AS_W + LSTM_XS_W)*4)
__global__ __cluster_dims__(8,1,1) __launch_bounds__(256,1) void lstm_persist(
    const float* __restrict__ xgq, const float* __restrict__ Whq, float* __restrict__ encq,
    const float* __restrict__ xgd, const float* __restrict__ Whd, float* __restrict__ encd)
{
    extern __shared__ unsigned smbuf[];
    unsigned* Bs = smbuf;
    float* As = (float*)(smbuf + LSTM_BS_W);
    float* xs = As + LSTM_AS_W;
    int tid = threadIdx.x;
    int lane = tid & 31, warp = tid >> 5;
    int r8 = lane >> 2, q4 = lane & 3;
    int wm = warp & 1, wn = warp >> 1;
    int cid = blockIdx.x >> 3, hb = blockIdx.x & 7;
    const float* xg; const float* Whh; float* enc; int T, n0;
    if (cid == 0){ xg = xgq; Whh = Whq; enc = encq; T = QLn; n0 = 0; }
    else        { xg = xgd; Whh = Whd; enc = encd; T = DLn; n0 = (cid-1)*32; }
    int h0 = hb * 32;

    for (int idx = tid; idx < 128*256; idx += 256){
        int j = idx >> 8, k = idx & 255;
        int r = ((j & 3) << 8) + h0 + (j >> 2);
        Bs[k*136 + j] = __float_as_uint(Whh[(size_t)r*Hh + k]);
    }

    auto issueXS = [&](int t){
        #pragma unroll
        for (int u = 0; u < 4; u++){
            int ch = tid + 256*u;           // 1024 chunks of 16B
            int m  = ch >> 5;
            int g  = (ch >> 3) & 3;
            int o4 = (ch & 7) * 4;
            const float* src = xg + ((size_t)(n0+m)*T + t)*G4 + g*256 + h0 + o4;
            cpa16(sptr(xs + m*132 + g*32 + o4), src, true);
        }
        CP_COMMIT();
    };
    auto issueAS = [&](int t){
        #pragma unroll
        for (int u = 0; u < 8; u++){
            int ch = tid + 256*u;           // 2048 chunks of 16B
            int m  = ch >> 6;
            int k4 = (ch & 63) * 4;
            cpa16(sptr(As + m*260 + k4), enc + ((size_t)(n0+m)*T + (t-1))*Hh + k4, true);
        }
        CP_COMMIT();
    };

    issueXS(0);
    float creg[4] = {0.f, 0.f, 0.f, 0.f};
    int rb = wm*16;

    for (int t = 0; t < T; t++){
        if (t == 0){
            for (int idx = tid; idx < 32*256; idx += 256)
                As[(idx >> 8)*260 + (idx & 255)] = 0.f;
        } else {
            issueAS(t);
        }
        CP_WAIT0();
        __syncthreads();

        float acc[4][4] = {};
        #pragma unroll 4
        for (int ko = 0; ko < 256; ko += 8){
            unsigned af[4];
            af[0] = __float_as_uint(As[(rb+r8  )*260 + ko+q4  ]);
            af[1] = __float_as_uint(As[(rb+r8+8)*260 + ko+q4  ]);
            af[2] = __float_as_uint(As[(rb+r8  )*260 + ko+q4+4]);
            af[3] = __float_as_uint(As[(rb+r8+8)*260 + ko+q4+4]);
            #pragma unroll
            for (int nt = 0; nt < 4; nt++){
                int nb = wn*32 + nt*8;
                unsigned bf[2];
                bf[0] = Bs[(ko+q4)*136 + nb + r8];
                bf[1] = Bs[(ko+q4+4)*136 + nb + r8];
                mma8(acc[nt], af, bf);
            }
        }

        // shfl epilogue: lane^1 holds the complementary gate pair
        bool odd = (q4 & 1);
        int m  = rb + r8 + (odd ? 8 : 0);
        #pragma unroll
        for (int nt = 0; nt < 4; nt++){
            float a0 = acc[nt][0], a1 = acc[nt][1], a2 = acc[nt][2], a3 = acc[nt][3];
            float e0 = __shfl_xor_sync(0xFFFFFFFFu, a0, 1);
            float e1 = __shfl_xor_sync(0xFFFFFFFFu, a1, 1);
            float e2 = __shfl_xor_sync(0xFFFFFFFFu, a2, 1);
            float e3 = __shfl_xor_sync(0xFFFFFFFFu, a3, 1);
            float g0 = odd ? e2 : a0;
            float g1 = odd ? e3 : a1;
            float g2 = odd ? a2 : e0;
            float g3 = odd ? a3 : e1;
            int hp = wn*8 + nt*2 + (q4 >> 1);
            const float* xr = xs + m*132 + hp;
            float gi = g0 + xr[0];
            float gf = g1 + xr[32];
            float gg = g2 + xr[64];
            float go = g3 + xr[96];
            float cv = sigf(gf)*creg[nt] + sigf(gi)*tha(gg);
            creg[nt] = cv;
            enc[((size_t)(n0+m)*T + t)*Hh + h0 + hp] = sigf(go)*tha(cv);
        }
        __syncthreads();                 // all lanes done with xs/As
        if (t+1 < T) issueXS(t+1);       // prefetch next xg slice (pre-barrier)
        CLUSTER_ARRIVE();                // release: enc stores visible to cluster
        CLUSTER_WAIT();
    }
}

// ---------------- conv stage 1 (merged 3 convs via blockIdx.y) ----------------
__global__ void s_k(const float* __restrict__ c1W, const float* __restrict__ c2W,
                    const float* __restrict__ c3W,
                    float* __restrict__ s3, float* __restrict__ s5, float* __restrict__ s7)
{
    int z = blockIdx.y;
    int KW = 3 + 2*z, KP = 152 + 100*z;
    const float* cW = (z==0) ? c1W : (z==1) ? c2W : c3W;
    float* s = (z==0) ? s3 : (z==1) ? s5 : s7;
    long total = (long)Bq*NFc*QLn*KP;
    long i = (long)blockIdx.x*blockDim.x + threadIdx.x;
    if (i >= total) return;
    int kk = (int)(i % KP);
    long r = i / KP;
    int q  = (int)(r % QLn); r /= QLn;
    int o  = (int)(r % NFc);
    int b  = (int)(r / NFc);
    float v = 0.f;
    if (kk < Cc*KW){
        int dd = kk / Cc, c = kk - dd*Cc;
        #pragma unroll
        for (int dq = 0; dq < 3; dq++){
            int qq = q + dq - 1;
            if (qq >= 0 && qq < QLn)
                v += cW[(((size_t)o*51 + c)*3 + dq)*KW + dd] * g_pq[((size_t)b*QLn + qq)*Cc + c];
        }
    }
    s[i] = v;
}

// ---------------- conv stage 2: merged (blockIdx.z), resident-B, 3-stage A ----
#define CONV_DSM ((3*2560 + 50*132)*4)
__global__ __launch_bounds__(256,2) void convgemm_k(
    const float* __restrict__ sA3, const float* __restrict__ sA5, const float* __restrict__ sA7,
    const float* __restrict__ c1W, const float* __restrict__ c1b,
    const float* __restrict__ c2W, const float* __restrict__ c2b,
    const float* __restrict__ c3W, const float* __restrict__ c3b,
    const int* __restrict__ bqtok, const int* __restrict__ bdtok,
    const float* __restrict__ alpha)
{
    int z = blockIdx.z;
    const int KW = 3 + 2*z, KP = 152 + 100*z, PW = KW >> 1, OCB = z*50;
    const int nk = (KP + 15) >> 4;
    const float* sA = (z==0) ? sA3 : (z==1) ? sA5 : sA7;
    const float* cW = (z==0) ? c1W : (z==1) ? c2W : c3W;
    const float* cb = (z==0) ? c1b : (z==1) ? c2b : c3b;
    extern __shared__ float dsm[];
    float* Asm = dsm;              // 3 stages x [128][20]
    float* pdt = dsm + 3*2560;     // [50][132]
    __shared__ float ems[18][136];
    __shared__ float wem[8][21];
    __shared__ int qt[16], dt[128], s_any;
    int tid = threadIdx.x;
    int lane = tid & 31, warp = tid >> 5;
    int wm = warp >> 2, wn = warp & 3;
    int img = blockIdx.y, b = img / Dn;
    int m0 = blockIdx.x*128, obase = m0 >> 4;
    int r8 = lane>>2, q4 = lane&3;

    const float* Pd = &g_pdT[(size_t)img*Cc*DLn];
    int arow = tid >> 1, acp = (tid & 1)*8;
    bool mok = (m0 + arow) < 800;
    const float* Arow = sA + ((size_t)b*800 + (mok ? m0+arow : 0))*KP;

    auto issueA = [&](int kt, int buf){
        int k0 = kt*16;
        unsigned d = sptr(Asm + buf*2560 + arow*20 + acp);
        cpa16(d,    Arow + k0 + acp,     mok && (k0+acp)   < KP);
        cpa16(d+16, Arow + k0 + acp + 4, mok && (k0+acp+4) < KP);
    };

    for (int ch = tid; ch < 1600; ch += 256){
        int row = ch >> 5, off = (ch & 31) * 4;
        cpa16(sptr(pdt + row*132 + off), Pd + row*128 + off, true);
    }
    issueA(0,0); CP_COMMIT();
    issueA(1,1); CP_COMMIT();

    if (tid == 0) s_any = 0;
    if (tid < 16) qt[tid] = bqtok[b*QLn + tid];
    if (tid < 128) dt[tid] = bdtok[(size_t)img*DLn + tid];
    if (tid < 8*3*KW){
        int ol = tid/(3*KW), rr = tid%(3*KW);
        int o = obase + ol;
        wem[ol][rr] = (o < NFc) ? cW[(((size_t)o*51 + 50)*3 + rr/KW)*KW + rr%KW] : 0.f;
    }
    __syncthreads();
    float al = alpha[0];
    for (int e = tid; e < 18*136; e += 256){
        int qi = e/136, dj = e%136;
        int q = qi-1, dl = dj-3;
        float v = 0.f;
        if (q >= 0 && q < QLn && dl >= 0 && dl < DLn && qt[q] == dt[dl]){ v = al; s_any = 1; }
        ems[qi][dj] = v;
    }

    float acc[4][4][4] = {};
    int buf = 0;
    for (int kt = 0; kt < nk; kt++){
        if (kt >= nk-1) CP_WAIT0(); else CP_WAIT1();
        __syncthreads();
        if (kt+2 < nk){ issueA(kt+2, buf == 0 ? 2 : buf-1); CP_COMMIT(); }
        const float* Ab2 = Asm + buf*2560;
        #pragma unroll
        for (int kb=0; kb<2; kb++){
            int ko = kb*8;
            int ka = kt*16 + ko + q4;
            int k2 = ka + 4;
            int dda = ka/Cc, ca = ka - dda*Cc;
            int ddb = k2/Cc, cbb = k2 - ddb*Cc;
            unsigned af[4][4], bf[4][2];
            #pragma unroll
            for (int mt=0; mt<4; mt++){
                int rb = wm*64 + mt*16;
                af[mt][0] = __float_as_uint(Ab2[(rb+r8  )*20 + ko+q4  ]);
                af[mt][1] = __float_as_uint(Ab2[(rb+r8+8)*20 + ko+q4  ]);
                af[mt][2] = __float_as_uint(Ab2[(rb+r8  )*20 + ko+q4+4]);
                af[mt][3] = __float_as_uint(Ab2[(rb+r8+8)*20 + ko+q4+4]);
            }
            #pragma unroll
            for (int nt=0; nt<4; nt++){
                int col = wn*32 + nt*8 + r8;
                int sa = col + dda - PW;
                int sb = col + ddb - PW;
                bf[nt][0] = ((unsigned)sa < 128u) ? __float_as_uint(pdt[ca*132 + sa]) : 0u;
                bf[nt][1] = ((unsigned)sb < 128u) ? __float_as_uint(pdt[cbb*132 + sb]) : 0u;
            }
            #pragma unroll
            for (int mt=0;mt<4;mt++)
                #pragma unroll
                for (int nt=0;nt<4;nt++)
                    mma8(acc[mt][nt], af[mt], bf[nt]);
        }
        buf = (buf == 2) ? 0 : buf+1;
    }

    int any = s_any;
    #pragma unroll
    for (int mt=0;mt<4;mt++){
        int row = m0 + wm*64 + mt*16;
        if (row >= 800) continue;
        int o = row >> 4, ol = o - obase;
        float bias = cb[o];
        #pragma unroll
        for (int rr=0; rr<2; rr++){
            int q = r8 + rr*8;
            #pragma unroll
            for (int nt=0;nt<4;nt++){
                int col = wn*32 + nt*8 + q4*2;
                #pragma unroll
                for (int j=0;j<2;j++){
                    int dl = col + j;
                    float v = acc[mt][nt][rr*2 + j] + bias;
                    if (any){
                        for (int dq = 0; dq < 3; dq++)
                            for (int dd = 0; dd < KW; dd++)
                                v += wem[ol][dq*KW+dd] * ems[q+dq][dl+dd+3-PW];
                    }
                    v = fmaxf(v, 0.f);
                    g_f[(((size_t)img*150 + OCB + o)*QLn + q)*DLn + dl] = v;
                }
            }
        }
    }
}

// ---------------- 1x1 conv + maxpool + linear (tf32 mma) ----------------
#define SCORE_DSM ((3*8*264 + 152*36)*4)
__global__ __launch_bounds__(256,2) void score_k(
    const float* __restrict__ ccW, const float* __restrict__ ccb,
    const float* __restrict__ outW, const float* __restrict__ outb,
    float* __restrict__ out)
{
    extern __shared__ float dsm[];
    float* fs = dsm;               // 3 stages x [8][264]
    float* Ws = dsm + 3*8*264;     // [152][36]: Ws[k*36+m]
    __shared__ float red[32][8];
    __shared__ float part[32];
    int img = blockIdx.x, tid = threadIdx.x;
    int lane = tid & 31, warp = tid >> 5;
    int r8 = lane >> 2, q4 = lane & 3;

    for (int idx = tid; idx < 152*32; idx += 256){
        int m = idx & 31, k = idx >> 5;
        Ws[k*36 + m] = (m < MFc && k < 150) ? ccW[m*150 + k] : 0.f;
    }

    const float* fimg = &g_f[(size_t)img*150*2048];
    auto issue = [&](int kt, int pch, int buf){
        #pragma unroll
        for (int h = 0; h < 2; h++){
            int ch = tid + 256*h;
            int row = ch >> 6, off = (ch & 63)*4;
            int kr = kt*8 + row;
            cpa16(sptr(fs + buf*2112 + row*264 + off),
                  fimg + (size_t)kr*2048 + pch*256 + off, kr < 150);
        }
        CP_COMMIT();
    };

    float bb0 = (r8      < MFc) ? ccb[r8]      : 0.f;
    float bb0b= (r8+8    < MFc) ? ccb[r8+8]    : 0.f;
    float maxv[2][2] = {{-1e30f,-1e30f},{-1e30f,-1e30f}};
    __syncthreads();   // Ws ready

    for (int pch = 0; pch < 8; pch++){
        float acc[2][4][4] = {};
        issue(0, pch, 0);
        issue(1, pch, 1);
        int buf = 0;
        for (int kt = 0; kt < 19; kt++){
            if (kt >= 17) CP_WAIT0(); else CP_WAIT1();
            __syncthreads();
            if (kt+2 < 19) issue(kt+2, pch, buf == 0 ? 2 : buf-1);
            const float* fb2 = fs + buf*2112;
            unsigned af[2][4];
            #pragma unroll
            for (int mt=0; mt<2; mt++){
                int mb = mt*16;
                af[mt][0] = __float_as_uint(Ws[(kt*8+q4  )*36 + mb+r8]);
                af[mt][1] = __float_as_uint(Ws[(kt*8+q4  )*36 + mb+r8+8]);
                af[mt][2] = __float_as_uint(Ws[(kt*8+q4+4)*36 + mb+r8]);
                af[mt][3] = __float_as_uint(Ws[(kt*8+q4+4)*36 + mb+r8+8]);
            }
            #pragma unroll
            for (int nt=0; nt<4; nt++){
                int nb = warp*32 + nt*8;
                unsigned bf[2];
                bf[0] = __float_as_uint(fb2[(q4  )*264 + nb+r8]);
                bf[1] = __float_as_uint(fb2[(q4+4)*264 + nb+r8]);
                #pragma unroll
                for (int mt=0; mt<2; mt++)
                    mma8(acc[mt][nt], af[mt], bf);
            }
            buf = (buf == 2) ? 0 : buf+1;
            __syncthreads();
        }
        #pragma unroll
        for (int mt=0; mt<2; mt++){
            float b0 = (mt==0) ? bb0  : ((16+r8 < MFc) ? ccb[16+r8] : 0.f);
            float b1 = (mt==0) ? bb0b : 0.f;
            #pragma unroll
            for (int nt=0; nt<4; nt++){
                float* cc = acc[mt][nt];
                maxv[mt][0] = fmaxf(maxv[mt][0], fmaxf(cc[0], cc[1]) + b0);
                maxv[mt][1] = fmaxf(maxv[mt][1], fmaxf(cc[2], cc[3]) + b1);
            }
        }
    }
    #pragma unroll
    for (int mt=0; mt<2; mt++)
        #pragma unroll
        for (int h=0; h<2; h++){
            float v = maxv[mt][h];
            v = fmaxf(v, __shfl_xor_sync(0xFFFFFFFFu, v, 1));
            v = fmaxf(v, __shfl_xor_sync(0xFFFFFFFFu, v, 2));
            maxv[mt][h] = v;
        }
    if (q4 == 0){
        #pragma unroll
        for (int mt=0; mt<2; mt++)
            #pragma unroll
            for (int h=0; h<2; h++)
                red[mt*16 + h*8 + r8][warp] = maxv[mt][h];
    }
    __syncthreads();
    if (tid < 32){
        float m = red[tid][0];
        #pragma unroll
        for (int w = 1; w < 8; w++) m = fmaxf(m, red[tid][w]);
        part[tid] = (tid < MFc) ? m * outW[tid] : 0.f;
    }
    __syncthreads();
    if (tid == 0){
        float sc = outb[0];
        #pragma unroll
        for (int mf = 0; mf < MFc; mf++) sc += part[mf];
        out[img] = sc;
    }
}

// ---------------- launch ----------------
extern "C" void kernel_launch(void* const* d_in, const int* in_sizes, int n_in,
                              void* d_out, int out_size)
{
    const int* bqtok = nullptr; const int* bdtok = nullptr;
    for (int i = 0; i < 4; i++){
        if (in_sizes[i] == NTQ)      bqtok = (const int*)d_in[i];
        else if (in_sizes[i] == NTD) bdtok = (const int*)d_in[i];
    }
    const float* emb    = (const float*)d_in[4];
    const float* projW  = (const float*)d_in[5];
    const float* projb  = (const float*)d_in[6];
    const float* qWih   = (const float*)d_in[7];
    const float* qWhh   = (const float*)d_in[8];
    const float* qbih   = (const float*)d_in[9];
    const float* qbhh   = (const float*)d_in[10];
    const float* dWih   = (const float*)d_in[11];
    const float* dWhh   = (const float*)d_in[12];
    const float* dbih   = (const float*)d_in[13];
    const float* dbhh   = (const float*)d_in[14];
    const float* qpW    = (const float*)d_in[15];
    const float* qpb    = (const float*)d_in[16];
    const float* dpW    = (const float*)d_in[17];
    const float* dpb    = (const float*)d_in[18];
    const float* alpha  = (const float*)d_in[19];
    const float* c1W    = (const float*)d_in[20];
    const float* c1b    = (const float*)d_in[21];
    const float* c2W    = (const float*)d_in[22];
    const float* c2b    = (const float*)d_in[23];
    const float* c3W    = (const float*)d_in[24];
    const float* c3b    = (const float*)d_in[25];
    const float* ccW    = (const float*)d_in[26];
    const float* ccb    = (const float*)d_in[27];
    const float* outW   = (const float*)d_in[28];
    const float* outb   = (const float*)d_in[29];
    float* out = (float*)d_out;

    float *pXq,*pXd,*pxgq,*pxgd,*pencq,*pencd,*ppq,*ppdT,*ps3,*ps5,*ps7,*pqb,*pdb;
    cudaGetSymbolAddress((void**)&pXq,  g_Xq);
    cudaGetSymbolAddress((void**)&pXd,  g_Xd);
    cudaGetSymbolAddress((void**)&pxgq, g_xgq);
    cudaGetSymbolAddress((void**)&pxgd, g_xgd);
    cudaGetSymbolAddress((void**)&pencq,g_encq);
    cudaGetSymbolAddress((void**)&pencd,g_encd);
    cudaGetSymbolAddress((void**)&ppq,  g_pq);
    cudaGetSymbolAddress((void**)&ppdT, g_pdT);
    cudaGetSymbolAddress((void**)&ps3,  g_s3);
    cudaGetSymbolAddress((void**)&ps5,  g_s5);
    cudaGetSymbolAddress((void**)&ps7,  g_s7);
    cudaGetSymbolAddress((void**)&pqb,  g_qb);
    cudaGetSymbolAddress((void**)&pdb,  g_db);

    cudaFuncSetAttribute(lstm_persist, cudaFuncAttributeMaxDynamicSharedMemorySize, LSTM_SMEM);
    cudaFuncSetAttribute(gemm_dual<true,false,true>,  cudaFuncAttributeMaxDynamicSharedMemorySize, GEMM_DSM);
    cudaFuncSetAttribute(gemm_dual<false,true,true>,  cudaFuncAttributeMaxDynamicSharedMemorySize, GEMM_DSM);
    cudaFuncSetAttribute(gemm_dual<false,false,false>,cudaFuncAttributeMaxDynamicSharedMemorySize, GEMM_DSM);
    cudaFuncSetAttribute(convgemm_k, cudaFuncAttributeMaxDynamicSharedMemorySize, CONV_DSM);
    cudaFuncSetAttribute(score_k, cudaFuncAttributeMaxDynamicSharedMemorySize, SCORE_DSM);

    bias_sum_k<<<4,256>>>(qbih,qbhh,dbih,dbhh);

    // embed + proj (dual): X = emb[tok] @ projW + projb
    { GS s1{emb, bqtok, projW, projb, pXq, NTQ, Ff, 0};
      GS s2{emb, bdtok, projW, projb, pXd, NTD, Ff, 0};
      gemm_dual<true,false,true><<<dim3(3,324),256,GEMM_DSM>>>(s1,s2,4, Ff,Ff, Ff,Ff); }

    // input gates (dual): xg = X @ Wih^T + (bih+bhh)
    { GS s1{pXq, nullptr, qWih, pqb, pxgq, NTQ, G4, 0};
      GS s2{pXd, nullptr, dWih, pdb, pxgd, NTD, G4, 0};
      gemm_dual<false,true,true><<<dim3(8,324),256,GEMM_DSM>>>(s1,s2,4, Ff,Ff, G4,Ff); }

    // persistent LSTMs (merged: 11 clusters x 8 blocks)
    lstm_persist<<<88,256,LSTM_SMEM>>>(pxgq, qWhh, pencq, pxgd, dWhh, pencd);

    // projections (dual): pq [512,50]; pdT per image
    { GS s1{pencq, nullptr, qpW, qpb, ppq,  NTQ, Cc, 0};
      GS s2{pencd, nullptr, dpW, dpb, ppdT, NTD, 0,  1};
      gemm_dual<false,false,false><<<dim3(1,324),256,GEMM_DSM>>>(s1,s2,4, Hh,Cc, Cc,Hh); }

    // conv stage 1 (merged)
    {
        long t7 = (long)Bq*NFc*QLn*352;
        s_k<<<dim3((unsigned)((t7+255)/256),3),256>>>(c1W,c2W,c3W, ps3,ps5,ps7);
    }
    // conv stage 2 (merged z-dispatch)
    convgemm_k<<<dim3(7,BD,3),256,CONV_DSM>>>(ps3,ps5,ps7, c1W,c1b, c2W,c2b, c3W,c3b,
                                              bqtok, bdtok, alpha);

    // 1x1 conv + maxpool + linear (tf32 mma)
    score_k<<<BD,256,SCORE_DSM>>>(ccW, ccb, outW, outb, out);
}